// round 2
// baseline (speedup 1.0000x reference)
#include <cuda_runtime.h>

#define DIM   2048
#define BSZ   2
#define SEQ   2048
#define NH    16
#define HD    128
#define MROWS (BSZ*SEQ)   /* 4096 */

typedef unsigned long long ull;

// ---- packed fp32x2 helpers (Blackwell FFMA2 path; bit-identical to 2x fmaf) ----
#define PACK2(out, lo, hi) \
    asm("mov.b64 %0, {%1, %2};" : "=l"(out) : "r"(__float_as_uint(lo)), "r"(__float_as_uint(hi)))
#define UNPACK2(lo, hi, in) do { unsigned _ulo, _uhi; \
    asm("mov.b64 {%0, %1}, %2;" : "=r"(_ulo), "=r"(_uhi) : "l"(in)); \
    lo = __uint_as_float(_ulo); hi = __uint_as_float(_uhi); } while (0)
#define FMA2(d, a, b, c) \
    asm("fma.rn.f32x2 %0, %1, %2, %3;" : "=l"(d) : "l"(a), "l"(b), "l"(c))
#define MUL2(d, a, b) \
    asm("mul.rn.f32x2 %0, %1, %2;" : "=l"(d) : "l"(a), "l"(b))

// ---- scratch (device globals: allocation-free rule) ----
__device__ float g_q[MROWS*DIM];
__device__ float g_k[MROWS*DIM];
__device__ float g_v[MROWS*DIM];
__device__ float g_attn[MROWS*DIM];

// ============================================================================
// GEMM: C[M,N] = A[M,K] @ W[N,K]^T + bias, M=4096, N=K=2048
// 128x128 block tile, BK=8, 256 threads, 8x8 per thread, f32x2 accumulation.
// ============================================================================
__device__ __forceinline__ void gemm_core(const float* __restrict__ A,
                                          const float* __restrict__ W,
                                          const float* __restrict__ bias,
                                          float* __restrict__ C)
{
    __shared__ float As[8][128];
    __shared__ float Bs[8][128];
    const int tid = threadIdx.x;
    const int cx = tid & 15;        // col group
    const int cy = tid >> 4;        // row group
    const int rowBase = blockIdx.y * 128;
    const int colBase = blockIdx.x * 128;
    const int lr = tid >> 1;        // 0..127
    const int lk = (tid & 1) * 4;   // 0 or 4
    const float* Ap = A + (size_t)(rowBase + lr) * DIM + lk;
    const float* Wp = W + (size_t)(colBase + lr) * DIM + lk;

    ull c2[8][4];
#pragma unroll
    for (int i = 0; i < 8; ++i)
#pragma unroll
        for (int j = 0; j < 4; ++j) c2[i][j] = 0ull;

    for (int kt = 0; kt < DIM; kt += 8) {
        const float4 av = *(const float4*)(Ap + kt);
        const float4 wv = *(const float4*)(Wp + kt);
        As[lk+0][lr] = av.x; As[lk+1][lr] = av.y; As[lk+2][lr] = av.z; As[lk+3][lr] = av.w;
        Bs[lk+0][lr] = wv.x; Bs[lk+1][lr] = wv.y; Bs[lk+2][lr] = wv.z; Bs[lk+3][lr] = wv.w;
        __syncthreads();
#pragma unroll
        for (int kk = 0; kk < 8; ++kk) {
            const float4 a0 = *(const float4*)&As[kk][cy*8];
            const float4 a1 = *(const float4*)&As[kk][cy*8+4];
            const ulonglong2 bl = *(const ulonglong2*)&Bs[kk][cx*8];
            const ulonglong2 bh = *(const ulonglong2*)&Bs[kk][cx*8+4];
            const ull bb0 = bl.x, bb1 = bl.y, bb2 = bh.x, bb3 = bh.y;
            const float aa[8] = {a0.x,a0.y,a0.z,a0.w,a1.x,a1.y,a1.z,a1.w};
#pragma unroll
            for (int i = 0; i < 8; ++i) {
                ull ad; PACK2(ad, aa[i], aa[i]);
                FMA2(c2[i][0], ad, bb0, c2[i][0]);
                FMA2(c2[i][1], ad, bb1, c2[i][1]);
                FMA2(c2[i][2], ad, bb2, c2[i][2]);
                FMA2(c2[i][3], ad, bb3, c2[i][3]);
            }
        }
        __syncthreads();
    }

    float2 bv[4];
#pragma unroll
    for (int j = 0; j < 4; ++j) bv[j] = *(const float2*)&bias[colBase + cx*8 + 2*j];
#pragma unroll
    for (int i = 0; i < 8; ++i) {
        float* Crow = C + (size_t)(rowBase + cy*8 + i) * DIM + colBase + cx*8;
#pragma unroll
        for (int j = 0; j < 4; ++j) {
            float lo, hi; UNPACK2(lo, hi, c2[i][j]);
            float2 o; o.x = lo + bv[j].x; o.y = hi + bv[j].y;
            *(float2*)(Crow + 2*j) = o;
        }
    }
}

__global__ void __launch_bounds__(256, 2) gemm_qkv_kernel(
    const float* __restrict__ x,
    const float* __restrict__ wq, const float* __restrict__ wk, const float* __restrict__ wv,
    const float* __restrict__ bq, const float* __restrict__ bk, const float* __restrict__ bv)
{
    const float *W, *bias; float* C;
    if (blockIdx.z == 0)      { W = wq; bias = bq; C = g_q; }
    else if (blockIdx.z == 1) { W = wk; bias = bk; C = g_k; }
    else                      { W = wv; bias = bv; C = g_v; }
    gemm_core(x, W, bias, C);
}

__global__ void __launch_bounds__(256, 2) gemm_out_kernel(
    const float* __restrict__ wo, const float* __restrict__ bo, float* __restrict__ out)
{
    gemm_core(g_attn, wo, bo, out);
}

// ============================================================================
// Fused RMSNorm(+gain) + RoPE, in place on g_q / g_k. One block per row.
// ============================================================================
__global__ void __launch_bounds__(256) rmsnorm_rope_kernel(
    const float* __restrict__ freqs, const float* __restrict__ gq, const float* __restrict__ gk)
{
    const int row = blockIdx.x;
    const int s = row & (SEQ - 1);
    float* xb = (blockIdx.y == 0 ? g_q : g_k) + (size_t)row * DIM;
    const float* g = (blockIdx.y == 0) ? gq : gk;
    const int tid = threadIdx.x;
    const int base = tid * 8;

    const float4 u = *(const float4*)(xb + base);
    const float4 w = *(const float4*)(xb + base + 4);
    float ss = u.x*u.x + u.y*u.y + u.z*u.z + u.w*u.w
             + w.x*w.x + w.y*w.y + w.z*w.z + w.w*w.w;
#pragma unroll
    for (int m = 16; m > 0; m >>= 1) ss += __shfl_xor_sync(0xffffffffu, ss, m);
    __shared__ float red[8];
    if ((tid & 31) == 0) red[tid >> 5] = ss;
    __syncthreads();
    const float tot = red[0]+red[1]+red[2]+red[3]+red[4]+red[5]+red[6]+red[7];
    const float rinv = rsqrtf(tot * (1.0f/DIM) + 1e-6f);

    const float4 g0 = *(const float4*)(g + base);
    const float4 g1 = *(const float4*)(g + base + 4);
    float y[8] = {u.x*rinv*g0.x, u.y*rinv*g0.y, u.z*rinv*g0.z, u.w*rinv*g0.w,
                  w.x*rinv*g1.x, w.y*rinv*g1.y, w.z*rinv*g1.z, w.w*rinv*g1.w};

    const float* fr = freqs + (size_t)s * HD;   // LC*2 = 128 floats per position
    float o[8];
#pragma unroll
    for (int p = 0; p < 4; ++p) {
        const int col = base + 2*p;
        const int jj = (col & (HD - 1)) >> 1;
        const float cr = fr[2*jj], ci = fr[2*jj + 1];
        const float xr = y[2*p], xi = y[2*p + 1];
        o[2*p]     = xr*cr - xi*ci;
        o[2*p + 1] = xr*ci + xi*cr;
    }
    float4 r0; r0.x = o[0]; r0.y = o[1]; r0.z = o[2]; r0.w = o[3];
    float4 r1; r1.x = o[4]; r1.y = o[5]; r1.z = o[6]; r1.w = o[7];
    *(float4*)(xb + base)     = r0;
    *(float4*)(xb + base + 4) = r1;
}

// ============================================================================
// Flash attention (fp32, full softmax). 64 q-rows per CTA, 64-key tiles.
// 256 threads: thread (tr,tc) owns score rows 4tr..4tr+3, score cols tc+16j,
// and output dims 8tc..8tc+7 of its 4 rows.
// ============================================================================
#define LDT 65
#define ATTN_SMEM ((2*128*LDT + 64*128 + 64*LDT) * sizeof(float))  /* 115968 B */

__global__ void __launch_bounds__(256) attn_kernel()
{
    extern __shared__ float sm[];
    float* q_sT = sm;                 // [128][LDT] kk-major
    float* k_sT = sm + 128*LDT;       // [128][LDT] kk-major
    float* v_s  = sm + 2*128*LDT;     // [64][128]  row-major
    float* p_s  = v_s + 64*128;       // [64][LDT]

    const int tid = threadIdx.x;
    const int tr = tid >> 4;          // 0..15
    const int tc = tid & 15;          // 0..15
    const int b  = blockIdx.z;
    const int h  = blockIdx.y;
    const int q0 = blockIdx.x * 64;

    const float* qg = g_q + (size_t)(b*SEQ + q0) * DIM + h*HD;
    const float* kg = g_k + (size_t)(b*SEQ) * DIM + h*HD;
    const float* vg = g_v + (size_t)(b*SEQ) * DIM + h*HD;

    // load q tile transposed (once)
#pragma unroll
    for (int it = 0; it < 8; ++it) {
        const int f = tid + it*256;
        const int r = f >> 5;
        const int dq = (f & 31) * 4;
        const float4 qv = *(const float4*)(qg + (size_t)r*DIM + dq);
        q_sT[(dq+0)*LDT + r] = qv.x;
        q_sT[(dq+1)*LDT + r] = qv.y;
        q_sT[(dq+2)*LDT + r] = qv.z;
        q_sT[(dq+3)*LDT + r] = qv.w;
    }

    float m_i[4], l_i[4];
    ull o2[4][4];
#pragma unroll
    for (int i = 0; i < 4; ++i) {
        m_i[i] = -1e30f; l_i[i] = 0.0f;
#pragma unroll
        for (int j = 0; j < 4; ++j) o2[i][j] = 0ull;
    }

    const float scale = 0.088388347648318447f;  // 1/sqrt(128)

    for (int kt = 0; kt < SEQ/64; ++kt) {
        const int k0 = kt * 64;
        // load k (transposed) + v tiles
#pragma unroll
        for (int it = 0; it < 8; ++it) {
            const int f = tid + it*256;
            const int r = f >> 5;
            const int dq = (f & 31) * 4;
            const float4 kv = *(const float4*)(kg + (size_t)(k0 + r)*DIM + dq);
            k_sT[(dq+0)*LDT + r] = kv.x;
            k_sT[(dq+1)*LDT + r] = kv.y;
            k_sT[(dq+2)*LDT + r] = kv.z;
            k_sT[(dq+3)*LDT + r] = kv.w;
            const float4 vv = *(const float4*)(vg + (size_t)(k0 + r)*DIM + dq);
            *(float4*)(v_s + r*HD + dq) = vv;
        }
        __syncthreads();

        // scores: s[i][j], rows 4tr+i, cols tc+16j
        ull s2[4][2];
#pragma unroll
        for (int i = 0; i < 4; ++i) { s2[i][0] = 0ull; s2[i][1] = 0ull; }

#pragma unroll 8
        for (int kk = 0; kk < HD; ++kk) {
            const float* qrow = q_sT + kk*LDT;
            const float* krow = k_sT + kk*LDT;
            const float b0 = krow[tc];
            const float b1 = krow[tc + 16];
            const float bx = krow[tc + 32];
            const float b3 = krow[tc + 48];
            ull bb0, bb1;
            PACK2(bb0, b0, b1);
            PACK2(bb1, bx, b3);
#pragma unroll
            for (int i = 0; i < 4; ++i) {
                const float a = qrow[4*tr + i];
                ull ad; PACK2(ad, a, a);
                FMA2(s2[i][0], ad, bb0, s2[i][0]);
                FMA2(s2[i][1], ad, bb1, s2[i][1]);
            }
        }

        // online softmax update (16 lanes with same tr share rows)
#pragma unroll
        for (int i = 0; i < 4; ++i) {
            float t0, t1, t2, t3;
            UNPACK2(t0, t1, s2[i][0]);
            UNPACK2(t2, t3, s2[i][1]);
            t0 *= scale; t1 *= scale; t2 *= scale; t3 *= scale;
            float mx = fmaxf(fmaxf(t0, t1), fmaxf(t2, t3));
            mx = fmaxf(mx, __shfl_xor_sync(0xffffffffu, mx, 1));
            mx = fmaxf(mx, __shfl_xor_sync(0xffffffffu, mx, 2));
            mx = fmaxf(mx, __shfl_xor_sync(0xffffffffu, mx, 4));
            mx = fmaxf(mx, __shfl_xor_sync(0xffffffffu, mx, 8));
            const float mnew = fmaxf(m_i[i], mx);
            const float corr = __expf(m_i[i] - mnew);
            const float p0 = __expf(t0 - mnew);
            const float p1 = __expf(t1 - mnew);
            const float p2 = __expf(t2 - mnew);
            const float p3 = __expf(t3 - mnew);
            float rs = (p0 + p1) + (p2 + p3);
            rs += __shfl_xor_sync(0xffffffffu, rs, 1);
            rs += __shfl_xor_sync(0xffffffffu, rs, 2);
            rs += __shfl_xor_sync(0xffffffffu, rs, 4);
            rs += __shfl_xor_sync(0xffffffffu, rs, 8);
            l_i[i] = l_i[i]*corr + rs;
            m_i[i] = mnew;
            ull cc; PACK2(cc, corr, corr);
            MUL2(o2[i][0], o2[i][0], cc);
            MUL2(o2[i][1], o2[i][1], cc);
            MUL2(o2[i][2], o2[i][2], cc);
            MUL2(o2[i][3], o2[i][3], cc);
            float* pr = p_s + (4*tr + i)*LDT;
            pr[tc]      = p0;
            pr[tc + 16] = p1;
            pr[tc + 32] = p2;
            pr[tc + 48] = p3;
        }
        __syncthreads();

        // O += P @ V  (thread owns dims 8tc..8tc+7 of rows 4tr..4tr+3)
#pragma unroll 4
        for (int c = 0; c < 64; ++c) {
            const ull* vr = (const ull*)(v_s + c*HD + 8*tc);
            const ull v0 = vr[0], v1 = vr[1], v2 = vr[2], v3 = vr[3];
#pragma unroll
            for (int i = 0; i < 4; ++i) {
                const float p = p_s[(4*tr + i)*LDT + c];
                ull pd; PACK2(pd, p, p);
                FMA2(o2[i][0], pd, v0, o2[i][0]);
                FMA2(o2[i][1], pd, v1, o2[i][1]);
                FMA2(o2[i][2], pd, v2, o2[i][2]);
                FMA2(o2[i][3], pd, v3, o2[i][3]);
            }
        }
        __syncthreads();
    }

    // finalize
#pragma unroll
    for (int i = 0; i < 4; ++i) {
        const float linv = 1.0f / l_i[i];
        float* orow = g_attn + (size_t)(b*SEQ + q0 + 4*tr + i) * DIM + h*HD + 8*tc;
#pragma unroll
        for (int j = 0; j < 4; ++j) {
            float lo, hi; UNPACK2(lo, hi, o2[i][j]);
            float2 o; o.x = lo*linv; o.y = hi*linv;
            *(float2*)(orow + 2*j) = o;
        }
    }
}

// ============================================================================
// Launcher
// ============================================================================
extern "C" void kernel_launch(void* const* d_in, const int* in_sizes, int n_in,
                              void* d_out, int out_size)
{
    const float* x  = (const float*)d_in[0];
    const float* fr = (const float*)d_in[1];
    const float* wq = (const float*)d_in[2];
    const float* bq = (const float*)d_in[3];
    const float* wk = (const float*)d_in[4];
    const float* bk = (const float*)d_in[5];
    const float* wv = (const float*)d_in[6];
    const float* bv = (const float*)d_in[7];
    const float* wo = (const float*)d_in[8];
    const float* bo = (const float*)d_in[9];
    const float* gq = (const float*)d_in[10];
    const float* gk = (const float*)d_in[11];
    float* out = (float*)d_out;

    (void)in_sizes; (void)n_in; (void)out_size;

    gemm_qkv_kernel<<<dim3(DIM/128, MROWS/128, 3), 256>>>(x, wq, wk, wv, bq, bk, bv);
    rmsnorm_rope_kernel<<<dim3(MROWS, 2), 256>>>(fr, gq, gk);
    cudaFuncSetAttribute(attn_kernel, cudaFuncAttributeMaxDynamicSharedMemorySize, (int)ATTN_SMEM);
    attn_kernel<<<dim3(SEQ/64, NH, BSZ), 256, ATTN_SMEM>>>();
    gemm_out_kernel<<<dim3(DIM/128, MROWS/128, 1), 256>>>(wo, bo, out);
}

// round 5
// speedup vs baseline: 2.3694x; 2.3694x over previous
#include <cuda_runtime.h>
#include <cuda_bf16.h>
#include <cstdint>

#define DIM   2048
#define BSZ   2
#define SEQ   2048
#define NH    16
#define HD    128
#define MROWS (BSZ*SEQ)   /* 4096 */

typedef unsigned long long ull;

// ---- packed fp32x2 helpers (for the fp32 attention kernel) ----
#define PACK2(out, lo, hi) \
    asm("mov.b64 %0, {%1, %2};" : "=l"(out) : "r"(__float_as_uint(lo)), "r"(__float_as_uint(hi)))
#define UNPACK2(lo, hi, in) do { unsigned _ulo, _uhi; \
    asm("mov.b64 {%0, %1}, %2;" : "=r"(_ulo), "=r"(_uhi) : "l"(in)); \
    lo = __uint_as_float(_ulo); hi = __uint_as_float(_uhi); } while (0)
#define FMA2(d, a, b, c) \
    asm("fma.rn.f32x2 %0, %1, %2, %3;" : "=l"(d) : "l"(a), "l"(b), "l"(c))
#define MUL2(d, a, b) \
    asm("mul.rn.f32x2 %0, %1, %2;" : "=l"(d) : "l"(a), "l"(b))

// ---- mma.sync / ldmatrix helpers (baseline PTX, no sm_103a features) ----
__device__ __forceinline__ uint32_t smem_to_u32(const void* p) {
    uint32_t a;
    asm("{ .reg .u64 t; cvta.to.shared.u64 t, %1; cvt.u32.u64 %0, t; }" : "=r"(a) : "l"(p));
    return a;
}
__device__ __forceinline__ void ldsm4(uint32_t (&r)[4], uint32_t addr) {
    asm volatile("ldmatrix.sync.aligned.m8n8.x4.shared.b16 {%0,%1,%2,%3}, [%4];"
                 : "=r"(r[0]), "=r"(r[1]), "=r"(r[2]), "=r"(r[3]) : "r"(addr));
}
__device__ __forceinline__ void mma_bf16(float (&d)[4], const uint32_t (&a)[4],
                                         uint32_t b0, uint32_t b1) {
    asm volatile("mma.sync.aligned.m16n8k16.row.col.f32.bf16.bf16.f32 "
                 "{%0,%1,%2,%3}, {%4,%5,%6,%7}, {%8,%9}, {%0,%1,%2,%3};"
                 : "+f"(d[0]), "+f"(d[1]), "+f"(d[2]), "+f"(d[3])
                 : "r"(a[0]), "r"(a[1]), "r"(a[2]), "r"(a[3]), "r"(b0), "r"(b1));
}

// ---- scratch (device globals: allocation-free rule) ----
__device__ float g_q[MROWS*DIM];
__device__ float g_k[MROWS*DIM];
__device__ float g_v[MROWS*DIM];
__device__ float g_attn[MROWS*DIM];

// ============================================================================
// HMMA GEMM: C[M,N] = A[M,K] @ W[N,K]^T + bias   (M=4096, N=K=2048)
// 128x128 CTA tile, 8 warps (2x4), bf16 hi/lo split (3 MMAs), fp32 accum.
// K staged by 32; double-buffered smem.
// ============================================================================
#define BK        32
#define NSTAGES   (DIM / BK)            /* 64 */
#define LDS_B     40                    /* bf16 elems per smem row (pad 8) */
#define TILE_BYT  (128 * LDS_B * 2)     /* 10240 */
#define OFF_AHI   0
#define OFF_ALO   (1 * TILE_BYT)
#define OFF_BHI   (2 * TILE_BYT)
#define OFF_BLO   (3 * TILE_BYT)
#define BUF_BYT   (4 * TILE_BYT)        /* 40960 */
#define GEMM_SMEM (2 * BUF_BYT)         /* 81920 */

__device__ __forceinline__ void split4(float4 v, uint2& hi, uint2& lo) {
    __nv_bfloat16 h0 = __float2bfloat16(v.x);
    __nv_bfloat16 h1 = __float2bfloat16(v.y);
    __nv_bfloat16 h2 = __float2bfloat16(v.z);
    __nv_bfloat16 h3 = __float2bfloat16(v.w);
    __nv_bfloat16 l0 = __float2bfloat16(v.x - __bfloat162float(h0));
    __nv_bfloat16 l1 = __float2bfloat16(v.y - __bfloat162float(h1));
    __nv_bfloat16 l2 = __float2bfloat16(v.z - __bfloat162float(h2));
    __nv_bfloat16 l3 = __float2bfloat16(v.w - __bfloat162float(h3));
    hi.x = ((uint32_t)__bfloat16_as_ushort(h1) << 16) | __bfloat16_as_ushort(h0);
    hi.y = ((uint32_t)__bfloat16_as_ushort(h3) << 16) | __bfloat16_as_ushort(h2);
    lo.x = ((uint32_t)__bfloat16_as_ushort(l1) << 16) | __bfloat16_as_ushort(l0);
    lo.y = ((uint32_t)__bfloat16_as_ushort(l3) << 16) | __bfloat16_as_ushort(l2);
}

__device__ __forceinline__ void gemm_tc_core(const float* __restrict__ A,
                                             const float* __restrict__ W,
                                             const float* __restrict__ bias,
                                             float* __restrict__ C)
{
    extern __shared__ char smem[];
    const uint32_t smem_u = smem_to_u32(smem);
    const int tid  = threadIdx.x;
    const int lane = tid & 31;
    const int wid  = tid >> 5;
    const int wm   = wid & 1;       // 0..1 : 64-row band
    const int wn   = wid >> 1;      // 0..3 : 32-col band

    const int rowBase = blockIdx.y * 128;
    const int colBase = blockIdx.x * 128;

    // global load mapping: thread -> (row, 16-float slab)
    const int lrow = tid >> 1;           // 0..127
    const int lcol = (tid & 1) * 16;     // 0 or 16
    const float* Ap = A + (size_t)(rowBase + lrow) * DIM + lcol;
    const float* Wp = W + (size_t)(colBase + lrow) * DIM + lcol;
    const uint32_t st_off = (uint32_t)lrow * (LDS_B * 2) + (uint32_t)lcol * 2;

    // ldmatrix per-lane offsets
    // A (row-major m16k16): lanes 0-15 -> rows 0-15 @k0 ; lanes 16-31 -> rows 0-15 @k8
    const uint32_t a_off = (uint32_t)(wm * 64 + (lane & 15)) * (LDS_B * 2)
                         + (uint32_t)((lane >> 4) * 8) * 2;
    // B (col-major k16n8, W stored [N][K]): lanes 0-7 n0-7@k0, 8-15 n0-7@k8,
    //                                       16-23 n8-15@k0, 24-31 n8-15@k8
    const uint32_t b_off = (uint32_t)(wn * 32 + ((lane >> 4) & 1) * 8 + (lane & 7)) * (LDS_B * 2)
                         + (uint32_t)(((lane >> 3) & 1) * 8) * 2;

    float acc[4][4][4];
#pragma unroll
    for (int t = 0; t < 4; ++t)
#pragma unroll
        for (int n = 0; n < 4; ++n)
#pragma unroll
            for (int e = 0; e < 4; ++e) acc[t][n][e] = 0.0f;

    float4 ra[4], rb[4];

    // ---- prologue: load + store stage 0 into buffer 0 ----
#pragma unroll
    for (int i = 0; i < 4; ++i) {
        ra[i] = *(const float4*)(Ap + 4 * i);
        rb[i] = *(const float4*)(Wp + 4 * i);
    }
    {
        char* buf = smem;   // buffer 0
#pragma unroll
        for (int i = 0; i < 4; ++i) {
            uint2 h, l;
            split4(ra[i], h, l);
            *(uint2*)(buf + OFF_AHI + st_off + 8 * i) = h;
            *(uint2*)(buf + OFF_ALO + st_off + 8 * i) = l;
            split4(rb[i], h, l);
            *(uint2*)(buf + OFF_BHI + st_off + 8 * i) = h;
            *(uint2*)(buf + OFF_BLO + st_off + 8 * i) = l;
        }
    }
    __syncthreads();

    // ---- main loop ----
    for (int s = 0; s < NSTAGES; ++s) {
        if (s + 1 < NSTAGES) {
            const size_t kofs = (size_t)(s + 1) * BK;
#pragma unroll
            for (int i = 0; i < 4; ++i) {
                ra[i] = *(const float4*)(Ap + kofs + 4 * i);
                rb[i] = *(const float4*)(Wp + kofs + 4 * i);
            }
        }

        const uint32_t cb = smem_u + (uint32_t)(s & 1) * BUF_BYT;
#pragma unroll
        for (int ks = 0; ks < 2; ++ks) {
            uint32_t ah[4][4], al[4][4], bh[2][4], bl[2][4];
#pragma unroll
            for (int t = 0; t < 4; ++t) {
                ldsm4(ah[t], cb + OFF_AHI + a_off + (uint32_t)t * (16 * LDS_B * 2) + ks * 32);
                ldsm4(al[t], cb + OFF_ALO + a_off + (uint32_t)t * (16 * LDS_B * 2) + ks * 32);
            }
#pragma unroll
            for (int p = 0; p < 2; ++p) {
                ldsm4(bh[p], cb + OFF_BHI + b_off + (uint32_t)p * (16 * LDS_B * 2) + ks * 32);
                ldsm4(bl[p], cb + OFF_BLO + b_off + (uint32_t)p * (16 * LDS_B * 2) + ks * 32);
            }
#pragma unroll
            for (int t = 0; t < 4; ++t) {
#pragma unroll
                for (int n = 0; n < 4; ++n) {
                    const int p = n >> 1, sub = n & 1;
                    mma_bf16(acc[t][n], ah[t], bh[p][sub * 2], bh[p][sub * 2 + 1]);
                    mma_bf16(acc[t][n], ah[t], bl[p][sub * 2], bl[p][sub * 2 + 1]);
                    mma_bf16(acc[t][n], al[t], bh[p][sub * 2], bh[p][sub * 2 + 1]);
                }
            }
        }

        if (s + 1 < NSTAGES) {
            char* buf = smem + ((s + 1) & 1) * BUF_BYT;
#pragma unroll
            for (int i = 0; i < 4; ++i) {
                uint2 h, l;
                split4(ra[i], h, l);
                *(uint2*)(buf + OFF_AHI + st_off + 8 * i) = h;
                *(uint2*)(buf + OFF_ALO + st_off + 8 * i) = l;
                split4(rb[i], h, l);
                *(uint2*)(buf + OFF_BHI + st_off + 8 * i) = h;
                *(uint2*)(buf + OFF_BLO + st_off + 8 * i) = l;
            }
            __syncthreads();
        }
    }

    // ---- epilogue: fragment layout m16n8: c0,c1 -> row lane>>2; c2,c3 -> +8 ----
#pragma unroll
    for (int t = 0; t < 4; ++t) {
        const int r1 = rowBase + wm * 64 + t * 16 + (lane >> 2);
#pragma unroll
        for (int n = 0; n < 4; ++n) {
            const int col = colBase + wn * 32 + n * 8 + (lane & 3) * 2;
            const float2 b2 = *(const float2*)&bias[col];
            float2 o1, o2;
            o1.x = acc[t][n][0] + b2.x; o1.y = acc[t][n][1] + b2.y;
            o2.x = acc[t][n][2] + b2.x; o2.y = acc[t][n][3] + b2.y;
            *(float2*)&C[(size_t)r1 * DIM + col]       = o1;
            *(float2*)&C[(size_t)(r1 + 8) * DIM + col] = o2;
        }
    }
}

__global__ void __launch_bounds__(256) gemm_qkv_kernel(
    const float* __restrict__ x,
    const float* __restrict__ wq, const float* __restrict__ wk, const float* __restrict__ wv,
    const float* __restrict__ bq, const float* __restrict__ bk, const float* __restrict__ bv)
{
    const float *W, *bias; float* C;
    if (blockIdx.z == 0)      { W = wq; bias = bq; C = g_q; }
    else if (blockIdx.z == 1) { W = wk; bias = bk; C = g_k; }
    else                      { W = wv; bias = bv; C = g_v; }
    gemm_tc_core(x, W, bias, C);
}

__global__ void __launch_bounds__(256) gemm_out_kernel(
    const float* __restrict__ wo, const float* __restrict__ bo, float* __restrict__ out)
{
    gemm_tc_core(g_attn, wo, bo, out);
}

// ============================================================================
// Fused RMSNorm(+gain) + RoPE, in place on g_q / g_k. One block per row.
// ============================================================================
__global__ void __launch_bounds__(256) rmsnorm_rope_kernel(
    const float* __restrict__ freqs, const float* __restrict__ gq, const float* __restrict__ gk)
{
    const int row = blockIdx.x;
    const int s = row & (SEQ - 1);
    float* xb = (blockIdx.y == 0 ? g_q : g_k) + (size_t)row * DIM;
    const float* g = (blockIdx.y == 0) ? gq : gk;
    const int tid = threadIdx.x;
    const int base = tid * 8;

    const float4 u = *(const float4*)(xb + base);
    const float4 w = *(const float4*)(xb + base + 4);
    float ss = u.x*u.x + u.y*u.y + u.z*u.z + u.w*u.w
             + w.x*w.x + w.y*w.y + w.z*w.z + w.w*w.w;
#pragma unroll
    for (int m = 16; m > 0; m >>= 1) ss += __shfl_xor_sync(0xffffffffu, ss, m);
    __shared__ float red[8];
    if ((tid & 31) == 0) red[tid >> 5] = ss;
    __syncthreads();
    const float tot = red[0]+red[1]+red[2]+red[3]+red[4]+red[5]+red[6]+red[7];
    const float rinv = rsqrtf(tot * (1.0f/DIM) + 1e-6f);

    const float4 g0 = *(const float4*)(g + base);
    const float4 g1 = *(const float4*)(g + base + 4);
    float y[8] = {u.x*rinv*g0.x, u.y*rinv*g0.y, u.z*rinv*g0.z, u.w*rinv*g0.w,
                  w.x*rinv*g1.x, w.y*rinv*g1.y, w.z*rinv*g1.z, w.w*rinv*g1.w};

    const float* fr = freqs + (size_t)s * HD;
    float o[8];
#pragma unroll
    for (int p = 0; p < 4; ++p) {
        const int col = base + 2*p;
        const int jj = (col & (HD - 1)) >> 1;
        const float cr = fr[2*jj], ci = fr[2*jj + 1];
        const float xr = y[2*p], xi = y[2*p + 1];
        o[2*p]     = xr*cr - xi*ci;
        o[2*p + 1] = xr*ci + xi*cr;
    }
    float4 r0; r0.x = o[0]; r0.y = o[1]; r0.z = o[2]; r0.w = o[3];
    float4 r1; r1.x = o[4]; r1.y = o[5]; r1.z = o[6]; r1.w = o[7];
    *(float4*)(xb + base)     = r0;
    *(float4*)(xb + base + 4) = r1;
}

// ============================================================================
// Flash attention (fp32, full softmax). 64 q-rows per CTA, 64-key tiles.
// ============================================================================
#define LDT 65
#define ATTN_SMEM ((2*128*LDT + 64*128 + 64*LDT) * sizeof(float))  /* 115968 B */

__global__ void __launch_bounds__(256) attn_kernel()
{
    extern __shared__ float smf[];
    float* q_sT = smf;
    float* k_sT = smf + 128*LDT;
    float* v_s  = smf + 2*128*LDT;
    float* p_s  = v_s + 64*128;

    const int tid = threadIdx.x;
    const int tr = tid >> 4;
    const int tc = tid & 15;
    const int b  = blockIdx.z;
    const int h  = blockIdx.y;
    const int q0 = blockIdx.x * 64;

    const float* qg = g_q + (size_t)(b*SEQ + q0) * DIM + h*HD;
    const float* kg = g_k + (size_t)(b*SEQ) * DIM + h*HD;
    const float* vg = g_v + (size_t)(b*SEQ) * DIM + h*HD;

#pragma unroll
    for (int it = 0; it < 8; ++it) {
        const int f = tid + it*256;
        const int r = f >> 5;
        const int dq = (f & 31) * 4;
        const float4 qv = *(const float4*)(qg + (size_t)r*DIM + dq);
        q_sT[(dq+0)*LDT + r] = qv.x;
        q_sT[(dq+1)*LDT + r] = qv.y;
        q_sT[(dq+2)*LDT + r] = qv.z;
        q_sT[(dq+3)*LDT + r] = qv.w;
    }

    float m_i[4], l_i[4];
    ull o2[4][4];
#pragma unroll
    for (int i = 0; i < 4; ++i) {
        m_i[i] = -1e30f; l_i[i] = 0.0f;
#pragma unroll
        for (int j = 0; j < 4; ++j) o2[i][j] = 0ull;
    }

    const float scale = 0.088388347648318447f;

    for (int kt = 0; kt < SEQ/64; ++kt) {
        const int k0 = kt * 64;
#pragma unroll
        for (int it = 0; it < 8; ++it) {
            const int f = tid + it*256;
            const int r = f >> 5;
            const int dq = (f & 31) * 4;
            const float4 kv = *(const float4*)(kg + (size_t)(k0 + r)*DIM + dq);
            k_sT[(dq+0)*LDT + r] = kv.x;
            k_sT[(dq+1)*LDT + r] = kv.y;
            k_sT[(dq+2)*LDT + r] = kv.z;
            k_sT[(dq+3)*LDT + r] = kv.w;
            const float4 vv = *(const float4*)(vg + (size_t)(k0 + r)*DIM + dq);
            *(float4*)(v_s + r*HD + dq) = vv;
        }
        __syncthreads();

        ull s2[4][2];
#pragma unroll
        for (int i = 0; i < 4; ++i) { s2[i][0] = 0ull; s2[i][1] = 0ull; }

#pragma unroll 8
        for (int kk = 0; kk < HD; ++kk) {
            const float* qrow = q_sT + kk*LDT;
            const float* krow = k_sT + kk*LDT;
            const float b0 = krow[tc];
            const float b1 = krow[tc + 16];
            const float bx = krow[tc + 32];
            const float b3 = krow[tc + 48];
            ull bb0, bb1;
            PACK2(bb0, b0, b1);
            PACK2(bb1, bx, b3);
#pragma unroll
            for (int i = 0; i < 4; ++i) {
                const float a = qrow[4*tr + i];
                ull ad; PACK2(ad, a, a);
                FMA2(s2[i][0], ad, bb0, s2[i][0]);
                FMA2(s2[i][1], ad, bb1, s2[i][1]);
            }
        }

#pragma unroll
        for (int i = 0; i < 4; ++i) {
            float t0, t1, t2, t3;
            UNPACK2(t0, t1, s2[i][0]);
            UNPACK2(t2, t3, s2[i][1]);
            t0 *= scale; t1 *= scale; t2 *= scale; t3 *= scale;
            float mx = fmaxf(fmaxf(t0, t1), fmaxf(t2, t3));
            mx = fmaxf(mx, __shfl_xor_sync(0xffffffffu, mx, 1));
            mx = fmaxf(mx, __shfl_xor_sync(0xffffffffu, mx, 2));
            mx = fmaxf(mx, __shfl_xor_sync(0xffffffffu, mx, 4));
            mx = fmaxf(mx, __shfl_xor_sync(0xffffffffu, mx, 8));
            const float mnew = fmaxf(m_i[i], mx);
            const float corr = __expf(m_i[i] - mnew);
            const float p0 = __expf(t0 - mnew);
            const float p1 = __expf(t1 - mnew);
            const float p2 = __expf(t2 - mnew);
            const float p3 = __expf(t3 - mnew);
            float rs = (p0 + p1) + (p2 + p3);
            rs += __shfl_xor_sync(0xffffffffu, rs, 1);
            rs += __shfl_xor_sync(0xffffffffu, rs, 2);
            rs += __shfl_xor_sync(0xffffffffu, rs, 4);
            rs += __shfl_xor_sync(0xffffffffu, rs, 8);
            l_i[i] = l_i[i]*corr + rs;
            m_i[i] = mnew;
            ull cc; PACK2(cc, corr, corr);
            MUL2(o2[i][0], o2[i][0], cc);
            MUL2(o2[i][1], o2[i][1], cc);
            MUL2(o2[i][2], o2[i][2], cc);
            MUL2(o2[i][3], o2[i][3], cc);
            float* pr = p_s + (4*tr + i)*LDT;
            pr[tc]      = p0;
            pr[tc + 16] = p1;
            pr[tc + 32] = p2;
            pr[tc + 48] = p3;
        }
        __syncthreads();

#pragma unroll 4
        for (int c = 0; c < 64; ++c) {
            const ull* vr = (const ull*)(v_s + c*HD + 8*tc);
            const ull v0 = vr[0], v1 = vr[1], v2 = vr[2], v3 = vr[3];
#pragma unroll
            for (int i = 0; i < 4; ++i) {
                const float p = p_s[(4*tr + i)*LDT + c];
                ull pd; PACK2(pd, p, p);
                FMA2(o2[i][0], pd, v0, o2[i][0]);
                FMA2(o2[i][1], pd, v1, o2[i][1]);
                FMA2(o2[i][2], pd, v2, o2[i][2]);
                FMA2(o2[i][3], pd, v3, o2[i][3]);
            }
        }
        __syncthreads();
    }

#pragma unroll
    for (int i = 0; i < 4; ++i) {
        const float linv = 1.0f / l_i[i];
        float* orow = g_attn + (size_t)(b*SEQ + q0 + 4*tr + i) * DIM + h*HD + 8*tc;
#pragma unroll
        for (int j = 0; j < 4; ++j) {
            float lo, hi; UNPACK2(lo, hi, o2[i][j]);
            float2 o; o.x = lo*linv; o.y = hi*linv;
            *(float2*)(orow + 2*j) = o;
        }
    }
}

// ============================================================================
// Launcher
// ============================================================================
extern "C" void kernel_launch(void* const* d_in, const int* in_sizes, int n_in,
                              void* d_out, int out_size)
{
    const float* x  = (const float*)d_in[0];
    const float* fr = (const float*)d_in[1];
    const float* wq = (const float*)d_in[2];
    const float* bq = (const float*)d_in[3];
    const float* wk = (const float*)d_in[4];
    const float* bk = (const float*)d_in[5];
    const float* wv = (const float*)d_in[6];
    const float* bv = (const float*)d_in[7];
    const float* wo = (const float*)d_in[8];
    const float* bo = (const float*)d_in[9];
    const float* gq = (const float*)d_in[10];
    const float* gk = (const float*)d_in[11];
    float* out = (float*)d_out;

    (void)in_sizes; (void)n_in; (void)out_size;

    cudaFuncSetAttribute(gemm_qkv_kernel, cudaFuncAttributeMaxDynamicSharedMemorySize, GEMM_SMEM);
    cudaFuncSetAttribute(gemm_out_kernel, cudaFuncAttributeMaxDynamicSharedMemorySize, GEMM_SMEM);
    cudaFuncSetAttribute(attn_kernel, cudaFuncAttributeMaxDynamicSharedMemorySize, (int)ATTN_SMEM);

    gemm_qkv_kernel<<<dim3(DIM/128, MROWS/128, 3), 256, GEMM_SMEM>>>(x, wq, wk, wv, bq, bk, bv);
    rmsnorm_rope_kernel<<<dim3(MROWS, 2), 256>>>(fr, gq, gk);
    attn_kernel<<<dim3(SEQ/64, NH, BSZ), 256, ATTN_SMEM>>>();
    gemm_out_kernel<<<dim3(DIM/128, MROWS/128, 1), 256, GEMM_SMEM>>>(wo, bo, out);
}

// round 6
// speedup vs baseline: 3.4861x; 1.4713x over previous
#include <cuda_runtime.h>
#include <cuda_bf16.h>
#include <cstdint>

#define DIM   2048
#define BSZ   2
#define SEQ   2048
#define NH    16
#define HD    128
#define MROWS (BSZ*SEQ)   /* 4096 */

typedef unsigned long long ull;

// ---- mma.sync / ldmatrix helpers (baseline PTX, no sm_103a features) ----
__device__ __forceinline__ uint32_t smem_to_u32(const void* p) {
    uint32_t a;
    asm("{ .reg .u64 t; cvta.to.shared.u64 t, %1; cvt.u32.u64 %0, t; }" : "=r"(a) : "l"(p));
    return a;
}
__device__ __forceinline__ void ldsm4(uint32_t (&r)[4], uint32_t addr) {
    asm volatile("ldmatrix.sync.aligned.m8n8.x4.shared.b16 {%0,%1,%2,%3}, [%4];"
                 : "=r"(r[0]), "=r"(r[1]), "=r"(r[2]), "=r"(r[3]) : "r"(addr));
}
__device__ __forceinline__ void ldsm4t(uint32_t (&r)[4], uint32_t addr) {
    asm volatile("ldmatrix.sync.aligned.m8n8.x4.trans.shared.b16 {%0,%1,%2,%3}, [%4];"
                 : "=r"(r[0]), "=r"(r[1]), "=r"(r[2]), "=r"(r[3]) : "r"(addr));
}
__device__ __forceinline__ void mma_bf16(float (&d)[4], const uint32_t (&a)[4],
                                         uint32_t b0, uint32_t b1) {
    asm volatile("mma.sync.aligned.m16n8k16.row.col.f32.bf16.bf16.f32 "
                 "{%0,%1,%2,%3}, {%4,%5,%6,%7}, {%8,%9}, {%0,%1,%2,%3};"
                 : "+f"(d[0]), "+f"(d[1]), "+f"(d[2]), "+f"(d[3])
                 : "r"(a[0]), "r"(a[1]), "r"(a[2]), "r"(a[3]), "r"(b0), "r"(b1));
}
__device__ __forceinline__ uint32_t cvt2bf(float hi, float lo) {
    uint32_t r; asm("cvt.rn.bf16x2.f32 %0, %1, %2;" : "=r"(r) : "f"(hi), "f"(lo)); return r;
}
__device__ __forceinline__ float bflo(uint32_t p) { return __uint_as_float(p << 16); }
__device__ __forceinline__ float bfhi(uint32_t p) { return __uint_as_float(p & 0xffff0000u); }

// ---- scratch (device globals: allocation-free rule) ----
__device__ float g_q[MROWS*DIM];
__device__ float g_k[MROWS*DIM];
__device__ float g_v[MROWS*DIM];
__device__ float g_attn[MROWS*DIM];

__device__ __forceinline__ void split4(float4 v, uint2& hi, uint2& lo) {
    __nv_bfloat16 h0 = __float2bfloat16(v.x);
    __nv_bfloat16 h1 = __float2bfloat16(v.y);
    __nv_bfloat16 h2 = __float2bfloat16(v.z);
    __nv_bfloat16 h3 = __float2bfloat16(v.w);
    __nv_bfloat16 l0 = __float2bfloat16(v.x - __bfloat162float(h0));
    __nv_bfloat16 l1 = __float2bfloat16(v.y - __bfloat162float(h1));
    __nv_bfloat16 l2 = __float2bfloat16(v.z - __bfloat162float(h2));
    __nv_bfloat16 l3 = __float2bfloat16(v.w - __bfloat162float(h3));
    hi.x = ((uint32_t)__bfloat16_as_ushort(h1) << 16) | __bfloat16_as_ushort(h0);
    hi.y = ((uint32_t)__bfloat16_as_ushort(h3) << 16) | __bfloat16_as_ushort(h2);
    lo.x = ((uint32_t)__bfloat16_as_ushort(l1) << 16) | __bfloat16_as_ushort(l0);
    lo.y = ((uint32_t)__bfloat16_as_ushort(l3) << 16) | __bfloat16_as_ushort(l2);
}

// ============================================================================
// HMMA GEMM: C[M,N] = A[M,K] @ W[N,K]^T + bias   (unchanged from Round 5)
// ============================================================================
#define BK        32
#define NSTAGES   (DIM / BK)
#define LDS_B     40
#define TILE_BYT  (128 * LDS_B * 2)
#define OFF_AHI   0
#define OFF_ALO   (1 * TILE_BYT)
#define OFF_BHI   (2 * TILE_BYT)
#define OFF_BLO   (3 * TILE_BYT)
#define BUF_BYT   (4 * TILE_BYT)
#define GEMM_SMEM (2 * BUF_BYT)

__device__ __forceinline__ void gemm_tc_core(const float* __restrict__ A,
                                             const float* __restrict__ W,
                                             const float* __restrict__ bias,
                                             float* __restrict__ C)
{
    extern __shared__ char smem[];
    const uint32_t smem_u = smem_to_u32(smem);
    const int tid  = threadIdx.x;
    const int lane = tid & 31;
    const int wid  = tid >> 5;
    const int wm   = wid & 1;
    const int wn   = wid >> 1;

    const int rowBase = blockIdx.y * 128;
    const int colBase = blockIdx.x * 128;

    const int lrow = tid >> 1;
    const int lcol = (tid & 1) * 16;
    const float* Ap = A + (size_t)(rowBase + lrow) * DIM + lcol;
    const float* Wp = W + (size_t)(colBase + lrow) * DIM + lcol;
    const uint32_t st_off = (uint32_t)lrow * (LDS_B * 2) + (uint32_t)lcol * 2;

    const uint32_t a_off = (uint32_t)(wm * 64 + (lane & 15)) * (LDS_B * 2)
                         + (uint32_t)((lane >> 4) * 8) * 2;
    const uint32_t b_off = (uint32_t)(wn * 32 + ((lane >> 4) & 1) * 8 + (lane & 7)) * (LDS_B * 2)
                         + (uint32_t)(((lane >> 3) & 1) * 8) * 2;

    float acc[4][4][4];
#pragma unroll
    for (int t = 0; t < 4; ++t)
#pragma unroll
        for (int n = 0; n < 4; ++n)
#pragma unroll
            for (int e = 0; e < 4; ++e) acc[t][n][e] = 0.0f;

    float4 ra[4], rb[4];

#pragma unroll
    for (int i = 0; i < 4; ++i) {
        ra[i] = *(const float4*)(Ap + 4 * i);
        rb[i] = *(const float4*)(Wp + 4 * i);
    }
    {
        char* buf = smem;
#pragma unroll
        for (int i = 0; i < 4; ++i) {
            uint2 h, l;
            split4(ra[i], h, l);
            *(uint2*)(buf + OFF_AHI + st_off + 8 * i) = h;
            *(uint2*)(buf + OFF_ALO + st_off + 8 * i) = l;
            split4(rb[i], h, l);
            *(uint2*)(buf + OFF_BHI + st_off + 8 * i) = h;
            *(uint2*)(buf + OFF_BLO + st_off + 8 * i) = l;
        }
    }
    __syncthreads();

    for (int s = 0; s < NSTAGES; ++s) {
        if (s + 1 < NSTAGES) {
            const size_t kofs = (size_t)(s + 1) * BK;
#pragma unroll
            for (int i = 0; i < 4; ++i) {
                ra[i] = *(const float4*)(Ap + kofs + 4 * i);
                rb[i] = *(const float4*)(Wp + kofs + 4 * i);
            }
        }

        const uint32_t cb = smem_u + (uint32_t)(s & 1) * BUF_BYT;
#pragma unroll
        for (int ks = 0; ks < 2; ++ks) {
            uint32_t ah[4][4], al[4][4], bh[2][4], bl[2][4];
#pragma unroll
            for (int t = 0; t < 4; ++t) {
                ldsm4(ah[t], cb + OFF_AHI + a_off + (uint32_t)t * (16 * LDS_B * 2) + ks * 32);
                ldsm4(al[t], cb + OFF_ALO + a_off + (uint32_t)t * (16 * LDS_B * 2) + ks * 32);
            }
#pragma unroll
            for (int p = 0; p < 2; ++p) {
                ldsm4(bh[p], cb + OFF_BHI + b_off + (uint32_t)p * (16 * LDS_B * 2) + ks * 32);
                ldsm4(bl[p], cb + OFF_BLO + b_off + (uint32_t)p * (16 * LDS_B * 2) + ks * 32);
            }
#pragma unroll
            for (int t = 0; t < 4; ++t) {
#pragma unroll
                for (int n = 0; n < 4; ++n) {
                    const int p = n >> 1, sub = n & 1;
                    mma_bf16(acc[t][n], ah[t], bh[p][sub * 2], bh[p][sub * 2 + 1]);
                    mma_bf16(acc[t][n], ah[t], bl[p][sub * 2], bl[p][sub * 2 + 1]);
                    mma_bf16(acc[t][n], al[t], bh[p][sub * 2], bh[p][sub * 2 + 1]);
                }
            }
        }

        if (s + 1 < NSTAGES) {
            char* buf = smem + ((s + 1) & 1) * BUF_BYT;
#pragma unroll
            for (int i = 0; i < 4; ++i) {
                uint2 h, l;
                split4(ra[i], h, l);
                *(uint2*)(buf + OFF_AHI + st_off + 8 * i) = h;
                *(uint2*)(buf + OFF_ALO + st_off + 8 * i) = l;
                split4(rb[i], h, l);
                *(uint2*)(buf + OFF_BHI + st_off + 8 * i) = h;
                *(uint2*)(buf + OFF_BLO + st_off + 8 * i) = l;
            }
            __syncthreads();
        }
    }

#pragma unroll
    for (int t = 0; t < 4; ++t) {
        const int r1 = rowBase + wm * 64 + t * 16 + (lane >> 2);
#pragma unroll
        for (int n = 0; n < 4; ++n) {
            const int col = colBase + wn * 32 + n * 8 + (lane & 3) * 2;
            const float2 b2 = *(const float2*)&bias[col];
            float2 o1, o2;
            o1.x = acc[t][n][0] + b2.x; o1.y = acc[t][n][1] + b2.y;
            o2.x = acc[t][n][2] + b2.x; o2.y = acc[t][n][3] + b2.y;
            *(float2*)&C[(size_t)r1 * DIM + col]       = o1;
            *(float2*)&C[(size_t)(r1 + 8) * DIM + col] = o2;
        }
    }
}

__global__ void __launch_bounds__(256) gemm_qkv_kernel(
    const float* __restrict__ x,
    const float* __restrict__ wq, const float* __restrict__ wk, const float* __restrict__ wv,
    const float* __restrict__ bq, const float* __restrict__ bk, const float* __restrict__ bv)
{
    const float *W, *bias; float* C;
    if (blockIdx.z == 0)      { W = wq; bias = bq; C = g_q; }
    else if (blockIdx.z == 1) { W = wk; bias = bk; C = g_k; }
    else                      { W = wv; bias = bv; C = g_v; }
    gemm_tc_core(x, W, bias, C);
}

__global__ void __launch_bounds__(256) gemm_out_kernel(
    const float* __restrict__ wo, const float* __restrict__ bo, float* __restrict__ out)
{
    gemm_tc_core(g_attn, wo, bo, out);
}

// ============================================================================
// Fused RMSNorm(+gain) + RoPE, in place on g_q / g_k. One block per row.
// ============================================================================
__global__ void __launch_bounds__(256) rmsnorm_rope_kernel(
    const float* __restrict__ freqs, const float* __restrict__ gq, const float* __restrict__ gk)
{
    const int row = blockIdx.x;
    const int s = row & (SEQ - 1);
    float* xb = (blockIdx.y == 0 ? g_q : g_k) + (size_t)row * DIM;
    const float* g = (blockIdx.y == 0) ? gq : gk;
    const int tid = threadIdx.x;
    const int base = tid * 8;

    const float4 u = *(const float4*)(xb + base);
    const float4 w = *(const float4*)(xb + base + 4);
    float ss = u.x*u.x + u.y*u.y + u.z*u.z + u.w*u.w
             + w.x*w.x + w.y*w.y + w.z*w.z + w.w*w.w;
#pragma unroll
    for (int m = 16; m > 0; m >>= 1) ss += __shfl_xor_sync(0xffffffffu, ss, m);
    __shared__ float red[8];
    if ((tid & 31) == 0) red[tid >> 5] = ss;
    __syncthreads();
    const float tot = red[0]+red[1]+red[2]+red[3]+red[4]+red[5]+red[6]+red[7];
    const float rinv = rsqrtf(tot * (1.0f/DIM) + 1e-6f);

    const float4 g0 = *(const float4*)(g + base);
    const float4 g1 = *(const float4*)(g + base + 4);
    float y[8] = {u.x*rinv*g0.x, u.y*rinv*g0.y, u.z*rinv*g0.z, u.w*rinv*g0.w,
                  w.x*rinv*g1.x, w.y*rinv*g1.y, w.z*rinv*g1.z, w.w*rinv*g1.w};

    const float* fr = freqs + (size_t)s * HD;
    float o[8];
#pragma unroll
    for (int p = 0; p < 4; ++p) {
        const int col = base + 2*p;
        const int jj = (col & (HD - 1)) >> 1;
        const float cr = fr[2*jj], ci = fr[2*jj + 1];
        const float xr = y[2*p], xi = y[2*p + 1];
        o[2*p]     = xr*cr - xi*ci;
        o[2*p + 1] = xr*ci + xi*cr;
    }
    float4 r0; r0.x = o[0]; r0.y = o[1]; r0.z = o[2]; r0.w = o[3];
    float4 r1; r1.x = o[4]; r1.y = o[5]; r1.z = o[6]; r1.w = o[7];
    *(float4*)(xb + base)     = r0;
    *(float4*)(xb + base + 4) = r1;
}

// ============================================================================
// HMMA flash attention. 128 q-rows per CTA, 128-kv tiles.
// 8 warps; warp w owns q rows 16w..16w+15 (full softmax rows -> warp-local).
// QK: Qh*Kh + Qh*Kl + Ql*Kh ; PV: Ph*Vh + Ph*Vl + Pl*Vh (fp32 accum).
// P stays in registers (score C-frag == PV A-frag layout).
// ============================================================================
#define AST   136                        /* halves per smem row (17x16B, conflict-free) */
#define ATILE_BYT (128 * AST * 2)        /* 34816 */
#define AQH  0
#define AQL  (1 * ATILE_BYT)
#define AKH  (2 * ATILE_BYT)
#define AKL  (3 * ATILE_BYT)
#define AVH  (4 * ATILE_BYT)
#define AVL  (5 * ATILE_BYT)
#define ATTN_SMEM (6 * ATILE_BYT)        /* 208896 */

__global__ void __launch_bounds__(256) attn_kernel()
{
    extern __shared__ char smh[];
    const uint32_t smem_u = smem_to_u32(smh);
    const int tid  = threadIdx.x;
    const int lane = tid & 31;
    const int w    = tid >> 5;
    const int b    = blockIdx.z;
    const int h    = blockIdx.y;
    const int q0   = blockIdx.x * 128;

    const float* qg = g_q + (size_t)(b*SEQ + q0) * DIM + h*HD;
    const float* kg = g_k + (size_t)(b*SEQ) * DIM + h*HD;
    const float* vg = g_v + (size_t)(b*SEQ) * DIM + h*HD;

    // global->smem split mapping: thread -> (row tid>>1, 64-col half)
    const int lrow = tid >> 1;
    const int lcol = (tid & 1) * 64;
    const uint32_t stoff = (uint32_t)lrow * (AST * 2) + (uint32_t)lcol * 2;

    // load Q tile once (rows q0..q0+127), split hi/lo
#pragma unroll
    for (int i = 0; i < 16; ++i) {
        const float4 v = *(const float4*)(qg + (size_t)lrow * DIM + lcol + 4 * i);
        uint2 hi, lo; split4(v, hi, lo);
        *(uint2*)(smh + AQH + stoff + 8 * i) = hi;
        *(uint2*)(smh + AQL + stoff + 8 * i) = lo;
    }

    // ldmatrix lane offsets
    const uint32_t a_off  = ((uint32_t)(w * 16 + (lane & 15)) * AST
                           + (uint32_t)((lane >> 4) * 8)) * 2;
    const uint32_t kb_off = ((uint32_t)(((lane >> 4) & 1) * 8 + (lane & 7)) * AST
                           + (uint32_t)(((lane >> 3) & 1) * 8)) * 2;
    const uint32_t vb_off = ((uint32_t)(((lane >> 3) & 1) * 8 + (lane & 7)) * AST
                           + (uint32_t)(((lane >> 4) & 1) * 8)) * 2;

    float O[16][4];
#pragma unroll
    for (int n = 0; n < 16; ++n)
#pragma unroll
        for (int e = 0; e < 4; ++e) O[n][e] = 0.0f;
    float mq0 = -1e30f, mq1 = -1e30f, l0 = 0.0f, l1 = 0.0f;

    const float Cs = 0.12754276931699657f;   // (1/sqrt(128)) * log2(e)

    for (int kt = 0; kt < SEQ / 128; ++kt) {
        __syncthreads();   // previous tile fully consumed (also orders Q stores at kt=0)
        // load K,V tile -> split hi/lo
        const float* kp = kg + (size_t)(kt * 128 + lrow) * DIM + lcol;
        const float* vp = vg + (size_t)(kt * 128 + lrow) * DIM + lcol;
#pragma unroll
        for (int i = 0; i < 16; ++i) {
            const float4 kv4 = *(const float4*)(kp + 4 * i);
            uint2 hi, lo; split4(kv4, hi, lo);
            *(uint2*)(smh + AKH + stoff + 8 * i) = hi;
            *(uint2*)(smh + AKL + stoff + 8 * i) = lo;
            const float4 vv4 = *(const float4*)(vp + 4 * i);
            split4(vv4, hi, lo);
            *(uint2*)(smh + AVH + stoff + 8 * i) = hi;
            *(uint2*)(smh + AVL + stoff + 8 * i) = lo;
        }
        __syncthreads();

        // ---- scores: acc[16 n-tiles][4] over 128 kv cols ----
        float acc[16][4];
#pragma unroll
        for (int n = 0; n < 16; ++n)
#pragma unroll
            for (int e = 0; e < 4; ++e) acc[n][e] = 0.0f;

#pragma unroll
        for (int kc = 0; kc < 8; ++kc) {
            uint32_t qa_h[4], qa_l[4];
            ldsm4(qa_h, smem_u + AQH + a_off + kc * 32);
            ldsm4(qa_l, smem_u + AQL + a_off + kc * 32);
#pragma unroll
            for (int np = 0; np < 8; ++np) {
                uint32_t kbh[4], kbl[4];
                ldsm4(kbh, smem_u + AKH + kb_off + (uint32_t)np * (16 * AST * 2) + kc * 32);
                ldsm4(kbl, smem_u + AKL + kb_off + (uint32_t)np * (16 * AST * 2) + kc * 32);
                mma_bf16(acc[2*np],   qa_h, kbh[0], kbh[1]);
                mma_bf16(acc[2*np],   qa_h, kbl[0], kbl[1]);
                mma_bf16(acc[2*np],   qa_l, kbh[0], kbh[1]);
                mma_bf16(acc[2*np+1], qa_h, kbh[2], kbh[3]);
                mma_bf16(acc[2*np+1], qa_h, kbl[2], kbl[3]);
                mma_bf16(acc[2*np+1], qa_l, kbh[2], kbh[3]);
            }
        }

        // ---- online softmax (row = lane>>2 for c0/c1, +8 for c2/c3) ----
        float pm0 = -1e30f, pm1 = -1e30f;
#pragma unroll
        for (int n = 0; n < 16; ++n) {
            pm0 = fmaxf(pm0, fmaxf(acc[n][0], acc[n][1]));
            pm1 = fmaxf(pm1, fmaxf(acc[n][2], acc[n][3]));
        }
        pm0 = fmaxf(pm0, __shfl_xor_sync(0xffffffffu, pm0, 1));
        pm0 = fmaxf(pm0, __shfl_xor_sync(0xffffffffu, pm0, 2));
        pm1 = fmaxf(pm1, __shfl_xor_sync(0xffffffffu, pm1, 1));
        pm1 = fmaxf(pm1, __shfl_xor_sync(0xffffffffu, pm1, 2));

        const float M0 = fmaxf(mq0, pm0 * Cs);
        const float M1 = fmaxf(mq1, pm1 * Cs);
        const float corr0 = exp2f(mq0 - M0);
        const float corr1 = exp2f(mq1 - M1);
        mq0 = M0; mq1 = M1;

        float rs0 = 0.0f, rs1 = 0.0f;
#pragma unroll
        for (int n = 0; n < 16; ++n) {
            acc[n][0] = exp2f(fmaf(acc[n][0], Cs, -M0));
            acc[n][1] = exp2f(fmaf(acc[n][1], Cs, -M0));
            acc[n][2] = exp2f(fmaf(acc[n][2], Cs, -M1));
            acc[n][3] = exp2f(fmaf(acc[n][3], Cs, -M1));
            rs0 += acc[n][0] + acc[n][1];
            rs1 += acc[n][2] + acc[n][3];
        }
        rs0 += __shfl_xor_sync(0xffffffffu, rs0, 1);
        rs0 += __shfl_xor_sync(0xffffffffu, rs0, 2);
        rs1 += __shfl_xor_sync(0xffffffffu, rs1, 1);
        rs1 += __shfl_xor_sync(0xffffffffu, rs1, 2);
        l0 = l0 * corr0 + rs0;
        l1 = l1 * corr1 + rs1;

#pragma unroll
        for (int n = 0; n < 16; ++n) {
            O[n][0] *= corr0; O[n][1] *= corr0;
            O[n][2] *= corr1; O[n][3] *= corr1;
        }

        // ---- O += P @ V ----
#pragma unroll
        for (int kc = 0; kc < 8; ++kc) {
            uint32_t ph[4], pl[4];
            ph[0] = cvt2bf(acc[2*kc][1],   acc[2*kc][0]);
            ph[1] = cvt2bf(acc[2*kc][3],   acc[2*kc][2]);
            ph[2] = cvt2bf(acc[2*kc+1][1], acc[2*kc+1][0]);
            ph[3] = cvt2bf(acc[2*kc+1][3], acc[2*kc+1][2]);
            {
                float e0 = acc[2*kc][0]   - bflo(ph[0]);
                float e1 = acc[2*kc][1]   - bfhi(ph[0]);
                pl[0] = cvt2bf(e1, e0);
                e0 = acc[2*kc][2]   - bflo(ph[1]);
                e1 = acc[2*kc][3]   - bfhi(ph[1]);
                pl[1] = cvt2bf(e1, e0);
                e0 = acc[2*kc+1][0] - bflo(ph[2]);
                e1 = acc[2*kc+1][1] - bfhi(ph[2]);
                pl[2] = cvt2bf(e1, e0);
                e0 = acc[2*kc+1][2] - bflo(ph[3]);
                e1 = acc[2*kc+1][3] - bfhi(ph[3]);
                pl[3] = cvt2bf(e1, e0);
            }
#pragma unroll
            for (int np = 0; np < 8; ++np) {
                uint32_t vbh[4], vbl[4];
                ldsm4t(vbh, smem_u + AVH + vb_off + (uint32_t)kc * (16 * AST * 2) + np * 32);
                ldsm4t(vbl, smem_u + AVL + vb_off + (uint32_t)kc * (16 * AST * 2) + np * 32);
                mma_bf16(O[2*np],   ph, vbh[0], vbh[1]);
                mma_bf16(O[2*np],   ph, vbl[0], vbl[1]);
                mma_bf16(O[2*np],   pl, vbh[0], vbh[1]);
                mma_bf16(O[2*np+1], ph, vbh[2], vbh[3]);
                mma_bf16(O[2*np+1], ph, vbl[2], vbl[3]);
                mma_bf16(O[2*np+1], pl, vbh[2], vbh[3]);
            }
        }
    }

    // ---- finalize ----
    const float inv0 = 1.0f / l0;
    const float inv1 = 1.0f / l1;
    const int r0g = b*SEQ + q0 + w*16 + (lane >> 2);
#pragma unroll
    for (int n = 0; n < 16; ++n) {
        const int col = h*HD + 8*n + 2*(lane & 3);
        float2 o1, o2;
        o1.x = O[n][0] * inv0; o1.y = O[n][1] * inv0;
        o2.x = O[n][2] * inv1; o2.y = O[n][3] * inv1;
        *(float2*)&g_attn[(size_t)r0g * DIM + col]       = o1;
        *(float2*)&g_attn[(size_t)(r0g + 8) * DIM + col] = o2;
    }
}

// ============================================================================
// Launcher
// ============================================================================
extern "C" void kernel_launch(void* const* d_in, const int* in_sizes, int n_in,
                              void* d_out, int out_size)
{
    const float* x  = (const float*)d_in[0];
    const float* fr = (const float*)d_in[1];
    const float* wq = (const float*)d_in[2];
    const float* bq = (const float*)d_in[3];
    const float* wk = (const float*)d_in[4];
    const float* bk = (const float*)d_in[5];
    const float* wv = (const float*)d_in[6];
    const float* bv = (const float*)d_in[7];
    const float* wo = (const float*)d_in[8];
    const float* bo = (const float*)d_in[9];
    const float* gq = (const float*)d_in[10];
    const float* gk = (const float*)d_in[11];
    float* out = (float*)d_out;

    (void)in_sizes; (void)n_in; (void)out_size;

    cudaFuncSetAttribute(gemm_qkv_kernel, cudaFuncAttributeMaxDynamicSharedMemorySize, GEMM_SMEM);
    cudaFuncSetAttribute(gemm_out_kernel, cudaFuncAttributeMaxDynamicSharedMemorySize, GEMM_SMEM);
    cudaFuncSetAttribute(attn_kernel, cudaFuncAttributeMaxDynamicSharedMemorySize, ATTN_SMEM);

    gemm_qkv_kernel<<<dim3(DIM/128, MROWS/128, 3), 256, GEMM_SMEM>>>(x, wq, wk, wv, bq, bk, bv);
    rmsnorm_rope_kernel<<<dim3(MROWS, 2), 256>>>(fr, gq, gk);
    attn_kernel<<<dim3(SEQ/128, NH, BSZ), 256, ATTN_SMEM>>>();
    gemm_out_kernel<<<dim3(DIM/128, MROWS/128, 1), 256, GEMM_SMEM>>>(wo, bo, out);
}

// round 7
// speedup vs baseline: 4.6689x; 1.3393x over previous
#include <cuda_runtime.h>
#include <cuda_bf16.h>
#include <cstdint>

#define DIM   2048
#define BSZ   2
#define SEQ   2048
#define NH    16
#define HD    128
#define MROWS (BSZ*SEQ)   /* 4096 */

typedef unsigned long long ull;

// ---- PTX helpers (baseline PTX only; no sm_103a-gated features) ----
__device__ __forceinline__ uint32_t smem_to_u32(const void* p) {
    uint32_t a;
    asm("{ .reg .u64 t; cvta.to.shared.u64 t, %1; cvt.u32.u64 %0, t; }" : "=r"(a) : "l"(p));
    return a;
}
__device__ __forceinline__ void ldsm4(uint32_t (&r)[4], uint32_t addr) {
    asm volatile("ldmatrix.sync.aligned.m8n8.x4.shared.b16 {%0,%1,%2,%3}, [%4];"
                 : "=r"(r[0]), "=r"(r[1]), "=r"(r[2]), "=r"(r[3]) : "r"(addr));
}
__device__ __forceinline__ void ldsm4t(uint32_t (&r)[4], uint32_t addr) {
    asm volatile("ldmatrix.sync.aligned.m8n8.x4.trans.shared.b16 {%0,%1,%2,%3}, [%4];"
                 : "=r"(r[0]), "=r"(r[1]), "=r"(r[2]), "=r"(r[3]) : "r"(addr));
}
__device__ __forceinline__ void mma_bf16(float (&d)[4], const uint32_t (&a)[4],
                                         uint32_t b0, uint32_t b1) {
    asm volatile("mma.sync.aligned.m16n8k16.row.col.f32.bf16.bf16.f32 "
                 "{%0,%1,%2,%3}, {%4,%5,%6,%7}, {%8,%9}, {%0,%1,%2,%3};"
                 : "+f"(d[0]), "+f"(d[1]), "+f"(d[2]), "+f"(d[3])
                 : "r"(a[0]), "r"(a[1]), "r"(a[2]), "r"(a[3]), "r"(b0), "r"(b1));
}
__device__ __forceinline__ uint32_t cvt2bf(float hi, float lo) {
    uint32_t r; asm("cvt.rn.bf16x2.f32 %0, %1, %2;" : "=r"(r) : "f"(hi), "f"(lo)); return r;
}
__device__ __forceinline__ float bflo(uint32_t p) { return __uint_as_float(p << 16); }
__device__ __forceinline__ float bfhi(uint32_t p) { return __uint_as_float(p & 0xffff0000u); }

__device__ __forceinline__ void cp_async16(uint32_t saddr, const void* gptr) {
    asm volatile("cp.async.cg.shared.global [%0], [%1], 16;" :: "r"(saddr), "l"(gptr));
}
#define CP_COMMIT()  asm volatile("cp.async.commit_group;" ::: "memory")
#define CP_WAIT(n)   asm volatile("cp.async.wait_group %0;" :: "n"(n) : "memory")

// ---- scratch (device globals: allocation-free rule) ----
__device__ float g_q[MROWS*DIM];
__device__ float g_k[MROWS*DIM];
__device__ float g_v[MROWS*DIM];
__device__ __nv_bfloat16 x_h[MROWS*DIM],  x_l[MROWS*DIM];
__device__ __nv_bfloat16 wq_h[DIM*DIM], wq_l[DIM*DIM];
__device__ __nv_bfloat16 wk_h[DIM*DIM], wk_l[DIM*DIM];
__device__ __nv_bfloat16 wv_h[DIM*DIM], wv_l[DIM*DIM];
__device__ __nv_bfloat16 wo_h[DIM*DIM], wo_l[DIM*DIM];
__device__ __nv_bfloat16 q_h[MROWS*DIM], q_l[MROWS*DIM];
__device__ __nv_bfloat16 k_h[MROWS*DIM], k_l[MROWS*DIM];
__device__ __nv_bfloat16 v_h[MROWS*DIM], v_l[MROWS*DIM];
__device__ __nv_bfloat16 a_h[MROWS*DIM], a_l[MROWS*DIM];

__device__ __forceinline__ void split4(float4 v, uint2& hi, uint2& lo) {
    __nv_bfloat16 h0 = __float2bfloat16(v.x);
    __nv_bfloat16 h1 = __float2bfloat16(v.y);
    __nv_bfloat16 h2 = __float2bfloat16(v.z);
    __nv_bfloat16 h3 = __float2bfloat16(v.w);
    __nv_bfloat16 l0 = __float2bfloat16(v.x - __bfloat162float(h0));
    __nv_bfloat16 l1 = __float2bfloat16(v.y - __bfloat162float(h1));
    __nv_bfloat16 l2 = __float2bfloat16(v.z - __bfloat162float(h2));
    __nv_bfloat16 l3 = __float2bfloat16(v.w - __bfloat162float(h3));
    hi.x = ((uint32_t)__bfloat16_as_ushort(h1) << 16) | __bfloat16_as_ushort(h0);
    hi.y = ((uint32_t)__bfloat16_as_ushort(h3) << 16) | __bfloat16_as_ushort(h2);
    lo.x = ((uint32_t)__bfloat16_as_ushort(l1) << 16) | __bfloat16_as_ushort(l0);
    lo.y = ((uint32_t)__bfloat16_as_ushort(l3) << 16) | __bfloat16_as_ushort(l2);
}

// ============================================================================
// fp32 -> bf16 hi/lo split kernels (sel picks the destination globals)
// ============================================================================
__global__ void __launch_bounds__(256) split_sel_kernel(const float* __restrict__ src,
                                                        int sel, int n4)
{
    const int i = blockIdx.x * blockDim.x + threadIdx.x;
    if (i >= n4) return;
    __nv_bfloat16 *hi, *lo;
    const float* s = src;
    switch (sel) {
        case 0: hi = x_h;  lo = x_l;  break;
        case 1: hi = wq_h; lo = wq_l; break;
        case 2: hi = wk_h; lo = wk_l; break;
        case 3: hi = wv_h; lo = wv_l; break;
        case 4: hi = wo_h; lo = wo_l; break;
        default: hi = v_h; lo = v_l; s = g_v; break;
    }
    const float4 v = ((const float4*)s)[i];
    uint2 h, l; split4(v, h, l);
    ((uint2*)hi)[i] = h;
    ((uint2*)lo)[i] = l;
}

// ============================================================================
// HMMA GEMM: C[M,N] = (Ah+Al)[M,K] @ (Bh+Bl)[N,K]^T + bias
// 128x128 CTA tile, 8 warps (2x4), 3 MMAs per product, fp32 accum.
// K staged by 32; 4-stage cp.async pipeline on preconverted bf16.
// ============================================================================
#define BK        32
#define NSTAGES   (DIM / BK)            /* 64 */
#define LDS_B     40                    /* bf16 elems per smem row (pad 8) */
#define TILE_BYT  (128 * LDS_B * 2)     /* 10240 */
#define OFF_AHI   0
#define OFF_ALO   (1 * TILE_BYT)
#define OFF_BHI   (2 * TILE_BYT)
#define OFF_BLO   (3 * TILE_BYT)
#define STG_BYT   (4 * TILE_BYT)        /* 40960 */
#define GEMM_SMEM (4 * STG_BYT)         /* 163840 */

__device__ __forceinline__ void gemm_issue(uint32_t dstbase,
    const __nv_bfloat16* __restrict__ Ah, const __nv_bfloat16* __restrict__ Al,
    const __nv_bfloat16* __restrict__ Bh, const __nv_bfloat16* __restrict__ Bl,
    int rowBase, int colBase, int kofs, int tid)
{
#pragma unroll
    for (int i = 0; i < 2; ++i) {
        const int f = i * 256 + tid;
        const int r = f >> 2, c = f & 3;
        const uint32_t d = dstbase + (uint32_t)r * (LDS_B * 2) + (uint32_t)c * 16;
        const size_t gA = (size_t)(rowBase + r) * DIM + kofs + c * 8;
        const size_t gB = (size_t)(colBase + r) * DIM + kofs + c * 8;
        cp_async16(d + OFF_AHI, Ah + gA);
        cp_async16(d + OFF_ALO, Al + gA);
        cp_async16(d + OFF_BHI, Bh + gB);
        cp_async16(d + OFF_BLO, Bl + gB);
    }
    CP_COMMIT();
}

__device__ __forceinline__ void gemm_tc_core(
    const __nv_bfloat16* __restrict__ Ah, const __nv_bfloat16* __restrict__ Al,
    const __nv_bfloat16* __restrict__ Bh, const __nv_bfloat16* __restrict__ Bl,
    const float* __restrict__ bias, float* __restrict__ C)
{
    extern __shared__ char smem[];
    const uint32_t smem_u = smem_to_u32(smem);
    const int tid  = threadIdx.x;
    const int lane = tid & 31;
    const int wid  = tid >> 5;
    const int wm   = wid & 1;
    const int wn   = wid >> 1;

    const int rowBase = blockIdx.y * 128;
    const int colBase = blockIdx.x * 128;

    const uint32_t a_off = (uint32_t)(wm * 64 + (lane & 15)) * (LDS_B * 2)
                         + (uint32_t)((lane >> 4) * 8) * 2;
    const uint32_t b_off = (uint32_t)(wn * 32 + ((lane >> 4) & 1) * 8 + (lane & 7)) * (LDS_B * 2)
                         + (uint32_t)(((lane >> 3) & 1) * 8) * 2;

    float acc[4][4][4];
#pragma unroll
    for (int t = 0; t < 4; ++t)
#pragma unroll
        for (int n = 0; n < 4; ++n)
#pragma unroll
            for (int e = 0; e < 4; ++e) acc[t][n][e] = 0.0f;

    // prologue: stages 0..2 in flight
#pragma unroll
    for (int s = 0; s < 3; ++s)
        gemm_issue(smem_u + (uint32_t)(s & 3) * STG_BYT, Ah, Al, Bh, Bl,
                   rowBase, colBase, s * BK, tid);

    for (int s = 0; s < NSTAGES; ++s) {
        CP_WAIT(2);
        __syncthreads();

        const uint32_t cb = smem_u + (uint32_t)(s & 3) * STG_BYT;
#pragma unroll
        for (int ks = 0; ks < 2; ++ks) {
            uint32_t ah[4][4], al[4][4], bh[2][4], bl[2][4];
#pragma unroll
            for (int t = 0; t < 4; ++t) {
                ldsm4(ah[t], cb + OFF_AHI + a_off + (uint32_t)t * (16 * LDS_B * 2) + ks * 32);
                ldsm4(al[t], cb + OFF_ALO + a_off + (uint32_t)t * (16 * LDS_B * 2) + ks * 32);
            }
#pragma unroll
            for (int p = 0; p < 2; ++p) {
                ldsm4(bh[p], cb + OFF_BHI + b_off + (uint32_t)p * (16 * LDS_B * 2) + ks * 32);
                ldsm4(bl[p], cb + OFF_BLO + b_off + (uint32_t)p * (16 * LDS_B * 2) + ks * 32);
            }
#pragma unroll
            for (int t = 0; t < 4; ++t) {
#pragma unroll
                for (int n = 0; n < 4; ++n) {
                    const int p = n >> 1, sub = n & 1;
                    mma_bf16(acc[t][n], ah[t], bh[p][sub * 2], bh[p][sub * 2 + 1]);
                    mma_bf16(acc[t][n], ah[t], bl[p][sub * 2], bl[p][sub * 2 + 1]);
                    mma_bf16(acc[t][n], al[t], bh[p][sub * 2], bh[p][sub * 2 + 1]);
                }
            }
        }

        __syncthreads();   // all warps done reading buffer (s&3) before refill
        if (s + 3 < NSTAGES)
            gemm_issue(smem_u + (uint32_t)((s + 3) & 3) * STG_BYT, Ah, Al, Bh, Bl,
                       rowBase, colBase, (s + 3) * BK, tid);
        else
            CP_COMMIT();   // keep group count uniform for CP_WAIT accounting
    }

#pragma unroll
    for (int t = 0; t < 4; ++t) {
        const int r1 = rowBase + wm * 64 + t * 16 + (lane >> 2);
#pragma unroll
        for (int n = 0; n < 4; ++n) {
            const int col = colBase + wn * 32 + n * 8 + (lane & 3) * 2;
            const float2 b2 = *(const float2*)&bias[col];
            float2 o1, o2;
            o1.x = acc[t][n][0] + b2.x; o1.y = acc[t][n][1] + b2.y;
            o2.x = acc[t][n][2] + b2.x; o2.y = acc[t][n][3] + b2.y;
            *(float2*)&C[(size_t)r1 * DIM + col]       = o1;
            *(float2*)&C[(size_t)(r1 + 8) * DIM + col] = o2;
        }
    }
}

__global__ void __launch_bounds__(256) gemm_qkv_kernel(
    const float* __restrict__ bq, const float* __restrict__ bk, const float* __restrict__ bv)
{
    if (blockIdx.z == 0)      gemm_tc_core(x_h, x_l, wq_h, wq_l, bq, g_q);
    else if (blockIdx.z == 1) gemm_tc_core(x_h, x_l, wk_h, wk_l, bk, g_k);
    else                      gemm_tc_core(x_h, x_l, wv_h, wv_l, bv, g_v);
}

__global__ void __launch_bounds__(256) gemm_out_kernel(
    const float* __restrict__ bo, float* __restrict__ out)
{
    gemm_tc_core(a_h, a_l, wo_h, wo_l, bo, out);
}

// ============================================================================
// Fused RMSNorm(+gain) + RoPE. Reads g_q/g_k fp32, writes bf16 hi/lo pairs.
// ============================================================================
__global__ void __launch_bounds__(256) rmsnorm_rope_kernel(
    const float* __restrict__ freqs, const float* __restrict__ gq, const float* __restrict__ gk)
{
    const int row = blockIdx.x;
    const int s = row & (SEQ - 1);
    const float* xb = (blockIdx.y == 0 ? g_q : g_k) + (size_t)row * DIM;
    __nv_bfloat16* oh = (blockIdx.y == 0 ? q_h : k_h) + (size_t)row * DIM;
    __nv_bfloat16* ol = (blockIdx.y == 0 ? q_l : k_l) + (size_t)row * DIM;
    const float* g = (blockIdx.y == 0) ? gq : gk;
    const int tid = threadIdx.x;
    const int base = tid * 8;

    const float4 u = *(const float4*)(xb + base);
    const float4 w = *(const float4*)(xb + base + 4);
    float ss = u.x*u.x + u.y*u.y + u.z*u.z + u.w*u.w
             + w.x*w.x + w.y*w.y + w.z*w.z + w.w*w.w;
#pragma unroll
    for (int m = 16; m > 0; m >>= 1) ss += __shfl_xor_sync(0xffffffffu, ss, m);
    __shared__ float red[8];
    if ((tid & 31) == 0) red[tid >> 5] = ss;
    __syncthreads();
    const float tot = red[0]+red[1]+red[2]+red[3]+red[4]+red[5]+red[6]+red[7];
    const float rinv = rsqrtf(tot * (1.0f/DIM) + 1e-6f);

    const float4 g0 = *(const float4*)(g + base);
    const float4 g1 = *(const float4*)(g + base + 4);
    float y[8] = {u.x*rinv*g0.x, u.y*rinv*g0.y, u.z*rinv*g0.z, u.w*rinv*g0.w,
                  w.x*rinv*g1.x, w.y*rinv*g1.y, w.z*rinv*g1.z, w.w*rinv*g1.w};

    const float* fr = freqs + (size_t)s * HD;
    float o[8];
#pragma unroll
    for (int p = 0; p < 4; ++p) {
        const int col = base + 2*p;
        const int jj = (col & (HD - 1)) >> 1;
        const float cr = fr[2*jj], ci = fr[2*jj + 1];
        const float xr = y[2*p], xi = y[2*p + 1];
        o[2*p]     = xr*cr - xi*ci;
        o[2*p + 1] = xr*ci + xi*cr;
    }
    float4 r0; r0.x = o[0]; r0.y = o[1]; r0.z = o[2]; r0.w = o[3];
    float4 r1; r1.x = o[4]; r1.y = o[5]; r1.z = o[6]; r1.w = o[7];
    uint2 h, l;
    split4(r0, h, l);
    *(uint2*)(oh + base)     = h;
    *(uint2*)(ol + base)     = l;
    split4(r1, h, l);
    *(uint2*)(oh + base + 4) = h;
    *(uint2*)(ol + base + 4) = l;
}

// ============================================================================
// HMMA flash attention on preconverted bf16 hi/lo. 128 q-rows/CTA, 128-kv tiles.
// cp.async loads; V copy overlapped under the QK matmul.
// Output written as bf16 hi/lo (a_h/a_l) for the out-projection GEMM.
// ============================================================================
#define AST   136                        /* halves per smem row */
#define ATILE_BYT (128 * AST * 2)        /* 34816 */
#define AQH  0
#define AQL  (1 * ATILE_BYT)
#define AKH  (2 * ATILE_BYT)
#define AKL  (3 * ATILE_BYT)
#define AVH  (4 * ATILE_BYT)
#define AVL  (5 * ATILE_BYT)
#define ATTN_SMEM (6 * ATILE_BYT)        /* 208896 */

__global__ void __launch_bounds__(256) attn_kernel()
{
    extern __shared__ char smh[];
    const uint32_t smem_u = smem_to_u32(smh);
    const int tid  = threadIdx.x;
    const int lane = tid & 31;
    const int w    = tid >> 5;
    const int b    = blockIdx.z;
    const int h    = blockIdx.y;
    const int q0   = blockIdx.x * 128;

    const size_t qrow0 = (size_t)(b*SEQ + q0) * DIM + h*HD;
    const size_t krow0 = (size_t)(b*SEQ) * DIM + h*HD;

    // issue Q tile (hi+lo) via cp.async: 8 x 16B per thread per half
#pragma unroll
    for (int i = 0; i < 8; ++i) {
        const int f = i * 256 + tid;
        const int r = f >> 4, c = f & 15;
        const uint32_t d = (uint32_t)r * (AST * 2) + (uint32_t)c * 16;
        const size_t gsrc = qrow0 + (size_t)r * DIM + c * 8;
        cp_async16(smem_u + AQH + d, q_h + gsrc);
        cp_async16(smem_u + AQL + d, q_l + gsrc);
    }
    CP_COMMIT();

    const uint32_t a_off  = ((uint32_t)(w * 16 + (lane & 15)) * AST
                           + (uint32_t)((lane >> 4) * 8)) * 2;
    const uint32_t kb_off = ((uint32_t)(((lane >> 4) & 1) * 8 + (lane & 7)) * AST
                           + (uint32_t)(((lane >> 3) & 1) * 8)) * 2;
    const uint32_t vb_off = ((uint32_t)(((lane >> 3) & 1) * 8 + (lane & 7)) * AST
                           + (uint32_t)(((lane >> 4) & 1) * 8)) * 2;

    float O[16][4];
#pragma unroll
    for (int n = 0; n < 16; ++n)
#pragma unroll
        for (int e = 0; e < 4; ++e) O[n][e] = 0.0f;
    float mq0 = -1e30f, mq1 = -1e30f, l0 = 0.0f, l1 = 0.0f;

    const float Cs = 0.12754276931699657f;   // (1/sqrt(128)) * log2(e)

    for (int kt = 0; kt < SEQ / 128; ++kt) {
        __syncthreads();   // previous tile fully consumed before refill

        const size_t krow = krow0 + (size_t)(kt * 128) * DIM;
        // K first (own commit group), then V (own group)
#pragma unroll
        for (int i = 0; i < 8; ++i) {
            const int f = i * 256 + tid;
            const int r = f >> 4, c = f & 15;
            const uint32_t d = (uint32_t)r * (AST * 2) + (uint32_t)c * 16;
            const size_t gsrc = krow + (size_t)r * DIM + c * 8;
            cp_async16(smem_u + AKH + d, k_h + gsrc);
            cp_async16(smem_u + AKL + d, k_l + gsrc);
        }
        CP_COMMIT();
#pragma unroll
        for (int i = 0; i < 8; ++i) {
            const int f = i * 256 + tid;
            const int r = f >> 4, c = f & 15;
            const uint32_t d = (uint32_t)r * (AST * 2) + (uint32_t)c * 16;
            const size_t gsrc = krow + (size_t)r * DIM + c * 8;
            cp_async16(smem_u + AVH + d, v_h + gsrc);
            cp_async16(smem_u + AVL + d, v_l + gsrc);
        }
        CP_COMMIT();

        CP_WAIT(1);        // K (and Q on first tile) ready; V still in flight
        __syncthreads();

        // ---- scores over 128 kv cols ----
        float acc[16][4];
#pragma unroll
        for (int n = 0; n < 16; ++n)
#pragma unroll
            for (int e = 0; e < 4; ++e) acc[n][e] = 0.0f;

#pragma unroll
        for (int kc = 0; kc < 8; ++kc) {
            uint32_t qa_h[4], qa_l[4];
            ldsm4(qa_h, smem_u + AQH + a_off + kc * 32);
            ldsm4(qa_l, smem_u + AQL + a_off + kc * 32);
#pragma unroll
            for (int np = 0; np < 8; ++np) {
                uint32_t kbh[4], kbl[4];
                ldsm4(kbh, smem_u + AKH + kb_off + (uint32_t)np * (16 * AST * 2) + kc * 32);
                ldsm4(kbl, smem_u + AKL + kb_off + (uint32_t)np * (16 * AST * 2) + kc * 32);
                mma_bf16(acc[2*np],   qa_h, kbh[0], kbh[1]);
                mma_bf16(acc[2*np],   qa_h, kbl[0], kbl[1]);
                mma_bf16(acc[2*np],   qa_l, kbh[0], kbh[1]);
                mma_bf16(acc[2*np+1], qa_h, kbh[2], kbh[3]);
                mma_bf16(acc[2*np+1], qa_h, kbl[2], kbl[3]);
                mma_bf16(acc[2*np+1], qa_l, kbh[2], kbh[3]);
            }
        }

        // ---- online softmax ----
        float pm0 = -1e30f, pm1 = -1e30f;
#pragma unroll
        for (int n = 0; n < 16; ++n) {
            pm0 = fmaxf(pm0, fmaxf(acc[n][0], acc[n][1]));
            pm1 = fmaxf(pm1, fmaxf(acc[n][2], acc[n][3]));
        }
        pm0 = fmaxf(pm0, __shfl_xor_sync(0xffffffffu, pm0, 1));
        pm0 = fmaxf(pm0, __shfl_xor_sync(0xffffffffu, pm0, 2));
        pm1 = fmaxf(pm1, __shfl_xor_sync(0xffffffffu, pm1, 1));
        pm1 = fmaxf(pm1, __shfl_xor_sync(0xffffffffu, pm1, 2));

        const float M0 = fmaxf(mq0, pm0 * Cs);
        const float M1 = fmaxf(mq1, pm1 * Cs);
        const float corr0 = exp2f(mq0 - M0);
        const float corr1 = exp2f(mq1 - M1);
        mq0 = M0; mq1 = M1;

        float rs0 = 0.0f, rs1 = 0.0f;
#pragma unroll
        for (int n = 0; n < 16; ++n) {
            acc[n][0] = exp2f(fmaf(acc[n][0], Cs, -M0));
            acc[n][1] = exp2f(fmaf(acc[n][1], Cs, -M0));
            acc[n][2] = exp2f(fmaf(acc[n][2], Cs, -M1));
            acc[n][3] = exp2f(fmaf(acc[n][3], Cs, -M1));
            rs0 += acc[n][0] + acc[n][1];
            rs1 += acc[n][2] + acc[n][3];
        }
        rs0 += __shfl_xor_sync(0xffffffffu, rs0, 1);
        rs0 += __shfl_xor_sync(0xffffffffu, rs0, 2);
        rs1 += __shfl_xor_sync(0xffffffffu, rs1, 1);
        rs1 += __shfl_xor_sync(0xffffffffu, rs1, 2);
        l0 = l0 * corr0 + rs0;
        l1 = l1 * corr1 + rs1;

#pragma unroll
        for (int n = 0; n < 16; ++n) {
            O[n][0] *= corr0; O[n][1] *= corr0;
            O[n][2] *= corr1; O[n][3] *= corr1;
        }

        CP_WAIT(0);        // V ready
        __syncthreads();

        // ---- O += P @ V ----
#pragma unroll
        for (int kc = 0; kc < 8; ++kc) {
            uint32_t ph[4], pl[4];
            ph[0] = cvt2bf(acc[2*kc][1],   acc[2*kc][0]);
            ph[1] = cvt2bf(acc[2*kc][3],   acc[2*kc][2]);
            ph[2] = cvt2bf(acc[2*kc+1][1], acc[2*kc+1][0]);
            ph[3] = cvt2bf(acc[2*kc+1][3], acc[2*kc+1][2]);
            {
                float e0 = acc[2*kc][0]   - bflo(ph[0]);
                float e1 = acc[2*kc][1]   - bfhi(ph[0]);
                pl[0] = cvt2bf(e1, e0);
                e0 = acc[2*kc][2]   - bflo(ph[1]);
                e1 = acc[2*kc][3]   - bfhi(ph[1]);
                pl[1] = cvt2bf(e1, e0);
                e0 = acc[2*kc+1][0] - bflo(ph[2]);
                e1 = acc[2*kc+1][1] - bfhi(ph[2]);
                pl[2] = cvt2bf(e1, e0);
                e0 = acc[2*kc+1][2] - bflo(ph[3]);
                e1 = acc[2*kc+1][3] - bfhi(ph[3]);
                pl[3] = cvt2bf(e1, e0);
            }
#pragma unroll
            for (int np = 0; np < 8; ++np) {
                uint32_t vbh[4], vbl[4];
                ldsm4t(vbh, smem_u + AVH + vb_off + (uint32_t)kc * (16 * AST * 2) + np * 32);
                ldsm4t(vbl, smem_u + AVL + vb_off + (uint32_t)kc * (16 * AST * 2) + np * 32);
                mma_bf16(O[2*np],   ph, vbh[0], vbh[1]);
                mma_bf16(O[2*np],   ph, vbl[0], vbl[1]);
                mma_bf16(O[2*np],   pl, vbh[0], vbh[1]);
                mma_bf16(O[2*np+1], ph, vbh[2], vbh[3]);
                mma_bf16(O[2*np+1], ph, vbl[2], vbl[3]);
                mma_bf16(O[2*np+1], pl, vbh[2], vbh[3]);
            }
        }
    }

    // ---- finalize: write bf16 hi/lo output ----
    const float inv0 = 1.0f / l0;
    const float inv1 = 1.0f / l1;
    const size_t r0g = (size_t)(b*SEQ + q0 + w*16 + (lane >> 2));
#pragma unroll
    for (int n = 0; n < 16; ++n) {
        const int col = h*HD + 8*n + 2*(lane & 3);
        const float o1x = O[n][0] * inv0, o1y = O[n][1] * inv0;
        const float o2x = O[n][2] * inv1, o2y = O[n][3] * inv1;
        const uint32_t h1 = cvt2bf(o1y, o1x);
        const uint32_t l1p = cvt2bf(o1y - bfhi(h1), o1x - bflo(h1));
        const uint32_t h2 = cvt2bf(o2y, o2x);
        const uint32_t l2p = cvt2bf(o2y - bfhi(h2), o2x - bflo(h2));
        *(uint32_t*)&a_h[r0g * DIM + col]       = h1;
        *(uint32_t*)&a_l[r0g * DIM + col]       = l1p;
        *(uint32_t*)&a_h[(r0g + 8) * DIM + col] = h2;
        *(uint32_t*)&a_l[(r0g + 8) * DIM + col] = l2p;
    }
}

// ============================================================================
// Launcher
// ============================================================================
extern "C" void kernel_launch(void* const* d_in, const int* in_sizes, int n_in,
                              void* d_out, int out_size)
{
    const float* x  = (const float*)d_in[0];
    const float* fr = (const float*)d_in[1];
    const float* wq = (const float*)d_in[2];
    const float* bq = (const float*)d_in[3];
    const float* wk = (const float*)d_in[4];
    const float* bk = (const float*)d_in[5];
    const float* wv = (const float*)d_in[6];
    const float* bv = (const float*)d_in[7];
    const float* wo = (const float*)d_in[8];
    const float* bo = (const float*)d_in[9];
    const float* gq = (const float*)d_in[10];
    const float* gk = (const float*)d_in[11];
    float* out = (float*)d_out;

    (void)in_sizes; (void)n_in; (void)out_size;

    cudaFuncSetAttribute(gemm_qkv_kernel, cudaFuncAttributeMaxDynamicSharedMemorySize, GEMM_SMEM);
    cudaFuncSetAttribute(gemm_out_kernel, cudaFuncAttributeMaxDynamicSharedMemorySize, GEMM_SMEM);
    cudaFuncSetAttribute(attn_kernel, cudaFuncAttributeMaxDynamicSharedMemorySize, ATTN_SMEM);

    const int n4_x = MROWS * DIM / 4;
    const int n4_w = DIM * DIM / 4;

    split_sel_kernel<<<n4_x / 256, 256>>>(x,  0, n4_x);
    split_sel_kernel<<<n4_w / 256, 256>>>(wq, 1, n4_w);
    split_sel_kernel<<<n4_w / 256, 256>>>(wk, 2, n4_w);
    split_sel_kernel<<<n4_w / 256, 256>>>(wv, 3, n4_w);
    split_sel_kernel<<<n4_w / 256, 256>>>(wo, 4, n4_w);

    gemm_qkv_kernel<<<dim3(DIM/128, MROWS/128, 3), 256, GEMM_SMEM>>>(bq, bk, bv);

    rmsnorm_rope_kernel<<<dim3(MROWS, 2), 256>>>(fr, gq, gk);
    split_sel_kernel<<<n4_x / 256, 256>>>(nullptr, 5, n4_x);   // g_v -> v_h/v_l

    attn_kernel<<<dim3(SEQ/128, NH, BSZ), 256, ATTN_SMEM>>>();

    gemm_out_kernel<<<dim3(DIM/128, MROWS/128, 1), 256, GEMM_SMEM>>>(bo, out);
}

// round 8
// speedup vs baseline: 4.6692x; 1.0001x over previous
#include <cuda_runtime.h>
#include <cuda_bf16.h>
#include <cstdint>

#define DIM   2048
#define BSZ   2
#define SEQ   2048
#define NH    16
#define HD    128
#define MROWS (BSZ*SEQ)   /* 4096 */

typedef unsigned long long ull;

// ---- PTX helpers (baseline PTX only; no sm_103a-gated features) ----
__device__ __forceinline__ uint32_t smem_to_u32(const void* p) {
    uint32_t a;
    asm("{ .reg .u64 t; cvta.to.shared.u64 t, %1; cvt.u32.u64 %0, t; }" : "=r"(a) : "l"(p));
    return a;
}
__device__ __forceinline__ void ldsm4(uint32_t (&r)[4], uint32_t addr) {
    asm volatile("ldmatrix.sync.aligned.m8n8.x4.shared.b16 {%0,%1,%2,%3}, [%4];"
                 : "=r"(r[0]), "=r"(r[1]), "=r"(r[2]), "=r"(r[3]) : "r"(addr));
}
__device__ __forceinline__ void ldsm4t(uint32_t (&r)[4], uint32_t addr) {
    asm volatile("ldmatrix.sync.aligned.m8n8.x4.trans.shared.b16 {%0,%1,%2,%3}, [%4];"
                 : "=r"(r[0]), "=r"(r[1]), "=r"(r[2]), "=r"(r[3]) : "r"(addr));
}
__device__ __forceinline__ void mma_bf16(float (&d)[4], const uint32_t (&a)[4],
                                         uint32_t b0, uint32_t b1) {
    asm volatile("mma.sync.aligned.m16n8k16.row.col.f32.bf16.bf16.f32 "
                 "{%0,%1,%2,%3}, {%4,%5,%6,%7}, {%8,%9}, {%0,%1,%2,%3};"
                 : "+f"(d[0]), "+f"(d[1]), "+f"(d[2]), "+f"(d[3])
                 : "r"(a[0]), "r"(a[1]), "r"(a[2]), "r"(a[3]), "r"(b0), "r"(b1));
}
__device__ __forceinline__ uint32_t cvt2bf(float hi, float lo) {
    uint32_t r; asm("cvt.rn.bf16x2.f32 %0, %1, %2;" : "=r"(r) : "f"(hi), "f"(lo)); return r;
}
__device__ __forceinline__ float bflo(uint32_t p) { return __uint_as_float(p << 16); }
__device__ __forceinline__ float bfhi(uint32_t p) { return __uint_as_float(p & 0xffff0000u); }

__device__ __forceinline__ void cp_async16(uint32_t saddr, const void* gptr) {
    asm volatile("cp.async.cg.shared.global [%0], [%1], 16;" :: "r"(saddr), "l"(gptr));
}
#define CP_COMMIT()  asm volatile("cp.async.commit_group;" ::: "memory")
#define CP_WAIT(n)   asm volatile("cp.async.wait_group %0;" :: "n"(n) : "memory")

// ---- scratch (device globals: allocation-free rule) ----
__device__ float g_q[MROWS*DIM];
__device__ float g_k[MROWS*DIM];
__device__ float g_v[MROWS*DIM];
__device__ __nv_bfloat16 x_h[MROWS*DIM],  x_l[MROWS*DIM];
__device__ __nv_bfloat16 wq_h[DIM*DIM], wq_l[DIM*DIM];
__device__ __nv_bfloat16 wk_h[DIM*DIM], wk_l[DIM*DIM];
__device__ __nv_bfloat16 wv_h[DIM*DIM], wv_l[DIM*DIM];
__device__ __nv_bfloat16 wo_h[DIM*DIM], wo_l[DIM*DIM];
__device__ __nv_bfloat16 q_h[MROWS*DIM], q_l[MROWS*DIM];
__device__ __nv_bfloat16 k_h[MROWS*DIM], k_l[MROWS*DIM];
__device__ __nv_bfloat16 v_h[MROWS*DIM], v_l[MROWS*DIM];
__device__ __nv_bfloat16 a_h[MROWS*DIM], a_l[MROWS*DIM];

__device__ __forceinline__ void split4(float4 v, uint2& hi, uint2& lo) {
    __nv_bfloat16 h0 = __float2bfloat16(v.x);
    __nv_bfloat16 h1 = __float2bfloat16(v.y);
    __nv_bfloat16 h2 = __float2bfloat16(v.z);
    __nv_bfloat16 h3 = __float2bfloat16(v.w);
    __nv_bfloat16 l0 = __float2bfloat16(v.x - __bfloat162float(h0));
    __nv_bfloat16 l1 = __float2bfloat16(v.y - __bfloat162float(h1));
    __nv_bfloat16 l2 = __float2bfloat16(v.z - __bfloat162float(h2));
    __nv_bfloat16 l3 = __float2bfloat16(v.w - __bfloat162float(h3));
    hi.x = ((uint32_t)__bfloat16_as_ushort(h1) << 16) | __bfloat16_as_ushort(h0);
    hi.y = ((uint32_t)__bfloat16_as_ushort(h3) << 16) | __bfloat16_as_ushort(h2);
    lo.x = ((uint32_t)__bfloat16_as_ushort(l1) << 16) | __bfloat16_as_ushort(l0);
    lo.y = ((uint32_t)__bfloat16_as_ushort(l3) << 16) | __bfloat16_as_ushort(l2);
}

// ============================================================================
// fp32 -> bf16 hi/lo split kernels (sel picks the destination globals)
// ============================================================================
__global__ void __launch_bounds__(256) split_sel_kernel(const float* __restrict__ src,
                                                        int sel, int n4)
{
    const int i = blockIdx.x * blockDim.x + threadIdx.x;
    if (i >= n4) return;
    __nv_bfloat16 *hi, *lo;
    const float* s = src;
    switch (sel) {
        case 0: hi = x_h;  lo = x_l;  break;
        case 1: hi = wq_h; lo = wq_l; break;
        case 2: hi = wk_h; lo = wk_l; break;
        case 3: hi = wv_h; lo = wv_l; break;
        case 4: hi = wo_h; lo = wo_l; break;
        default: hi = v_h; lo = v_l; s = g_v; break;
    }
    const float4 v = ((const float4*)s)[i];
    uint2 h, l; split4(v, h, l);
    ((uint2*)hi)[i] = h;
    ((uint2*)lo)[i] = l;
}

// ============================================================================
// HMMA GEMM: C[M,N] = (Ah+Al)[M,K] @ (Bh+Bl)[N,K]^T + bias
// 128x128 CTA tile, 8 warps (2x4), 3 MMAs per product, fp32 accum.
// K staged by 32; 4-stage cp.async pipeline on preconverted bf16.
// ============================================================================
#define BK        32
#define NSTAGES   (DIM / BK)            /* 64 */
#define LDS_B     40                    /* bf16 elems per smem row (pad 8) */
#define TILE_BYT  (128 * LDS_B * 2)     /* 10240 */
#define OFF_AHI   0
#define OFF_ALO   (1 * TILE_BYT)
#define OFF_BHI   (2 * TILE_BYT)
#define OFF_BLO   (3 * TILE_BYT)
#define STG_BYT   (4 * TILE_BYT)        /* 40960 */
#define GEMM_SMEM (4 * STG_BYT)         /* 163840 */

__device__ __forceinline__ void gemm_issue(uint32_t dstbase,
    const __nv_bfloat16* __restrict__ Ah, const __nv_bfloat16* __restrict__ Al,
    const __nv_bfloat16* __restrict__ Bh, const __nv_bfloat16* __restrict__ Bl,
    int rowBase, int colBase, int kofs, int tid)
{
#pragma unroll
    for (int i = 0; i < 2; ++i) {
        const int f = i * 256 + tid;
        const int r = f >> 2, c = f & 3;
        const uint32_t d = dstbase + (uint32_t)r * (LDS_B * 2) + (uint32_t)c * 16;
        const size_t gA = (size_t)(rowBase + r) * DIM + kofs + c * 8;
        const size_t gB = (size_t)(colBase + r) * DIM + kofs + c * 8;
        cp_async16(d + OFF_AHI, Ah + gA);
        cp_async16(d + OFF_ALO, Al + gA);
        cp_async16(d + OFF_BHI, Bh + gB);
        cp_async16(d + OFF_BLO, Bl + gB);
    }
    CP_COMMIT();
}

__device__ __forceinline__ void gemm_tc_core(
    const __nv_bfloat16* __restrict__ Ah, const __nv_bfloat16* __restrict__ Al,
    const __nv_bfloat16* __restrict__ Bh, const __nv_bfloat16* __restrict__ Bl,
    const float* __restrict__ bias, float* __restrict__ C)
{
    extern __shared__ char smem[];
    const uint32_t smem_u = smem_to_u32(smem);
    const int tid  = threadIdx.x;
    const int lane = tid & 31;
    const int wid  = tid >> 5;
    const int wm   = wid & 1;
    const int wn   = wid >> 1;

    const int rowBase = blockIdx.y * 128;
    const int colBase = blockIdx.x * 128;

    const uint32_t a_off = (uint32_t)(wm * 64 + (lane & 15)) * (LDS_B * 2)
                         + (uint32_t)((lane >> 4) * 8) * 2;
    const uint32_t b_off = (uint32_t)(wn * 32 + ((lane >> 4) & 1) * 8 + (lane & 7)) * (LDS_B * 2)
                         + (uint32_t)(((lane >> 3) & 1) * 8) * 2;

    float acc[4][4][4];
#pragma unroll
    for (int t = 0; t < 4; ++t)
#pragma unroll
        for (int n = 0; n < 4; ++n)
#pragma unroll
            for (int e = 0; e < 4; ++e) acc[t][n][e] = 0.0f;

    // prologue: stages 0..2 in flight
#pragma unroll
    for (int s = 0; s < 3; ++s)
        gemm_issue(smem_u + (uint32_t)(s & 3) * STG_BYT, Ah, Al, Bh, Bl,
                   rowBase, colBase, s * BK, tid);

    for (int s = 0; s < NSTAGES; ++s) {
        CP_WAIT(2);
        __syncthreads();

        const uint32_t cb = smem_u + (uint32_t)(s & 3) * STG_BYT;
#pragma unroll
        for (int ks = 0; ks < 2; ++ks) {
            uint32_t ah[4][4], al[4][4], bh[2][4], bl[2][4];
#pragma unroll
            for (int t = 0; t < 4; ++t) {
                ldsm4(ah[t], cb + OFF_AHI + a_off + (uint32_t)t * (16 * LDS_B * 2) + ks * 32);
                ldsm4(al[t], cb + OFF_ALO + a_off + (uint32_t)t * (16 * LDS_B * 2) + ks * 32);
            }
#pragma unroll
            for (int p = 0; p < 2; ++p) {
                ldsm4(bh[p], cb + OFF_BHI + b_off + (uint32_t)p * (16 * LDS_B * 2) + ks * 32);
                ldsm4(bl[p], cb + OFF_BLO + b_off + (uint32_t)p * (16 * LDS_B * 2) + ks * 32);
            }
#pragma unroll
            for (int t = 0; t < 4; ++t) {
#pragma unroll
                for (int n = 0; n < 4; ++n) {
                    const int p = n >> 1, sub = n & 1;
                    mma_bf16(acc[t][n], ah[t], bh[p][sub * 2], bh[p][sub * 2 + 1]);
                    mma_bf16(acc[t][n], ah[t], bl[p][sub * 2], bl[p][sub * 2 + 1]);
                    mma_bf16(acc[t][n], al[t], bh[p][sub * 2], bh[p][sub * 2 + 1]);
                }
            }
        }

        __syncthreads();   // all warps done reading buffer (s&3) before refill
        if (s + 3 < NSTAGES)
            gemm_issue(smem_u + (uint32_t)((s + 3) & 3) * STG_BYT, Ah, Al, Bh, Bl,
                       rowBase, colBase, (s + 3) * BK, tid);
        else
            CP_COMMIT();   // keep group count uniform for CP_WAIT accounting
    }

#pragma unroll
    for (int t = 0; t < 4; ++t) {
        const int r1 = rowBase + wm * 64 + t * 16 + (lane >> 2);
#pragma unroll
        for (int n = 0; n < 4; ++n) {
            const int col = colBase + wn * 32 + n * 8 + (lane & 3) * 2;
            const float2 b2 = *(const float2*)&bias[col];
            float2 o1, o2;
            o1.x = acc[t][n][0] + b2.x; o1.y = acc[t][n][1] + b2.y;
            o2.x = acc[t][n][2] + b2.x; o2.y = acc[t][n][3] + b2.y;
            *(float2*)&C[(size_t)r1 * DIM + col]       = o1;
            *(float2*)&C[(size_t)(r1 + 8) * DIM + col] = o2;
        }
    }
}

__global__ void __launch_bounds__(256) gemm_qkv_kernel(
    const float* __restrict__ bq, const float* __restrict__ bk, const float* __restrict__ bv)
{
    if (blockIdx.z == 0)      gemm_tc_core(x_h, x_l, wq_h, wq_l, bq, g_q);
    else if (blockIdx.z == 1) gemm_tc_core(x_h, x_l, wk_h, wk_l, bk, g_k);
    else                      gemm_tc_core(x_h, x_l, wv_h, wv_l, bv, g_v);
}

__global__ void __launch_bounds__(256) gemm_out_kernel(
    const float* __restrict__ bo, float* __restrict__ out)
{
    gemm_tc_core(a_h, a_l, wo_h, wo_l, bo, out);
}

// ============================================================================
// Fused RMSNorm(+gain) + RoPE. Reads g_q/g_k fp32, writes bf16 hi/lo pairs.
// ============================================================================
__global__ void __launch_bounds__(256) rmsnorm_rope_kernel(
    const float* __restrict__ freqs, const float* __restrict__ gq, const float* __restrict__ gk)
{
    const int row = blockIdx.x;
    const int s = row & (SEQ - 1);
    const float* xb = (blockIdx.y == 0 ? g_q : g_k) + (size_t)row * DIM;
    __nv_bfloat16* oh = (blockIdx.y == 0 ? q_h : k_h) + (size_t)row * DIM;
    __nv_bfloat16* ol = (blockIdx.y == 0 ? q_l : k_l) + (size_t)row * DIM;
    const float* g = (blockIdx.y == 0) ? gq : gk;
    const int tid = threadIdx.x;
    const int base = tid * 8;

    const float4 u = *(const float4*)(xb + base);
    const float4 w = *(const float4*)(xb + base + 4);
    float ss = u.x*u.x + u.y*u.y + u.z*u.z + u.w*u.w
             + w.x*w.x + w.y*w.y + w.z*w.z + w.w*w.w;
#pragma unroll
    for (int m = 16; m > 0; m >>= 1) ss += __shfl_xor_sync(0xffffffffu, ss, m);
    __shared__ float red[8];
    if ((tid & 31) == 0) red[tid >> 5] = ss;
    __syncthreads();
    const float tot = red[0]+red[1]+red[2]+red[3]+red[4]+red[5]+red[6]+red[7];
    const float rinv = rsqrtf(tot * (1.0f/DIM) + 1e-6f);

    const float4 g0 = *(const float4*)(g + base);
    const float4 g1 = *(const float4*)(g + base + 4);
    float y[8] = {u.x*rinv*g0.x, u.y*rinv*g0.y, u.z*rinv*g0.z, u.w*rinv*g0.w,
                  w.x*rinv*g1.x, w.y*rinv*g1.y, w.z*rinv*g1.z, w.w*rinv*g1.w};

    const float* fr = freqs + (size_t)s * HD;
    float o[8];
#pragma unroll
    for (int p = 0; p < 4; ++p) {
        const int col = base + 2*p;
        const int jj = (col & (HD - 1)) >> 1;
        const float cr = fr[2*jj], ci = fr[2*jj + 1];
        const float xr = y[2*p], xi = y[2*p + 1];
        o[2*p]     = xr*cr - xi*ci;
        o[2*p + 1] = xr*ci + xi*cr;
    }
    float4 r0; r0.x = o[0]; r0.y = o[1]; r0.z = o[2]; r0.w = o[3];
    float4 r1; r1.x = o[4]; r1.y = o[5]; r1.z = o[6]; r1.w = o[7];
    uint2 h, l;
    split4(r0, h, l);
    *(uint2*)(oh + base)     = h;
    *(uint2*)(ol + base)     = l;
    split4(r1, h, l);
    *(uint2*)(oh + base + 4) = h;
    *(uint2*)(ol + base + 4) = l;
}

// ============================================================================
// HMMA flash attention on preconverted bf16 hi/lo. 128 q-rows/CTA, 128-kv tiles.
// cp.async loads; V copy overlapped under the QK matmul.
// Output written as bf16 hi/lo (a_h/a_l) for the out-projection GEMM.
// ============================================================================
#define AST   136                        /* halves per smem row */
#define ATILE_BYT (128 * AST * 2)        /* 34816 */
#define AQH  0
#define AQL  (1 * ATILE_BYT)
#define AKH  (2 * ATILE_BYT)
#define AKL  (3 * ATILE_BYT)
#define AVH  (4 * ATILE_BYT)
#define AVL  (5 * ATILE_BYT)
#define ATTN_SMEM (6 * ATILE_BYT)        /* 208896 */

__global__ void __launch_bounds__(256) attn_kernel()
{
    extern __shared__ char smh[];
    const uint32_t smem_u = smem_to_u32(smh);
    const int tid  = threadIdx.x;
    const int lane = tid & 31;
    const int w    = tid >> 5;
    const int b    = blockIdx.z;
    const int h    = blockIdx.y;
    const int q0   = blockIdx.x * 128;

    const size_t qrow0 = (size_t)(b*SEQ + q0) * DIM + h*HD;
    const size_t krow0 = (size_t)(b*SEQ) * DIM + h*HD;

    // issue Q tile (hi+lo) via cp.async: 8 x 16B per thread per half
#pragma unroll
    for (int i = 0; i < 8; ++i) {
        const int f = i * 256 + tid;
        const int r = f >> 4, c = f & 15;
        const uint32_t d = (uint32_t)r * (AST * 2) + (uint32_t)c * 16;
        const size_t gsrc = qrow0 + (size_t)r * DIM + c * 8;
        cp_async16(smem_u + AQH + d, q_h + gsrc);
        cp_async16(smem_u + AQL + d, q_l + gsrc);
    }
    CP_COMMIT();

    const uint32_t a_off  = ((uint32_t)(w * 16 + (lane & 15)) * AST
                           + (uint32_t)((lane >> 4) * 8)) * 2;
    const uint32_t kb_off = ((uint32_t)(((lane >> 4) & 1) * 8 + (lane & 7)) * AST
                           + (uint32_t)(((lane >> 3) & 1) * 8)) * 2;
    const uint32_t vb_off = ((uint32_t)(((lane >> 3) & 1) * 8 + (lane & 7)) * AST
                           + (uint32_t)(((lane >> 4) & 1) * 8)) * 2;

    float O[16][4];
#pragma unroll
    for (int n = 0; n < 16; ++n)
#pragma unroll
        for (int e = 0; e < 4; ++e) O[n][e] = 0.0f;
    float mq0 = -1e30f, mq1 = -1e30f, l0 = 0.0f, l1 = 0.0f;

    const float Cs = 0.12754276931699657f;   // (1/sqrt(128)) * log2(e)

    for (int kt = 0; kt < SEQ / 128; ++kt) {
        __syncthreads();   // previous tile fully consumed before refill

        const size_t krow = krow0 + (size_t)(kt * 128) * DIM;
        // K first (own commit group), then V (own group)
#pragma unroll
        for (int i = 0; i < 8; ++i) {
            const int f = i * 256 + tid;
            const int r = f >> 4, c = f & 15;
            const uint32_t d = (uint32_t)r * (AST * 2) + (uint32_t)c * 16;
            const size_t gsrc = krow + (size_t)r * DIM + c * 8;
            cp_async16(smem_u + AKH + d, k_h + gsrc);
            cp_async16(smem_u + AKL + d, k_l + gsrc);
        }
        CP_COMMIT();
#pragma unroll
        for (int i = 0; i < 8; ++i) {
            const int f = i * 256 + tid;
            const int r = f >> 4, c = f & 15;
            const uint32_t d = (uint32_t)r * (AST * 2) + (uint32_t)c * 16;
            const size_t gsrc = krow + (size_t)r * DIM + c * 8;
            cp_async16(smem_u + AVH + d, v_h + gsrc);
            cp_async16(smem_u + AVL + d, v_l + gsrc);
        }
        CP_COMMIT();

        CP_WAIT(1);        // K (and Q on first tile) ready; V still in flight
        __syncthreads();

        // ---- scores over 128 kv cols ----
        float acc[16][4];
#pragma unroll
        for (int n = 0; n < 16; ++n)
#pragma unroll
            for (int e = 0; e < 4; ++e) acc[n][e] = 0.0f;

#pragma unroll
        for (int kc = 0; kc < 8; ++kc) {
            uint32_t qa_h[4], qa_l[4];
            ldsm4(qa_h, smem_u + AQH + a_off + kc * 32);
            ldsm4(qa_l, smem_u + AQL + a_off + kc * 32);
#pragma unroll
            for (int np = 0; np < 8; ++np) {
                uint32_t kbh[4], kbl[4];
                ldsm4(kbh, smem_u + AKH + kb_off + (uint32_t)np * (16 * AST * 2) + kc * 32);
                ldsm4(kbl, smem_u + AKL + kb_off + (uint32_t)np * (16 * AST * 2) + kc * 32);
                mma_bf16(acc[2*np],   qa_h, kbh[0], kbh[1]);
                mma_bf16(acc[2*np],   qa_h, kbl[0], kbl[1]);
                mma_bf16(acc[2*np],   qa_l, kbh[0], kbh[1]);
                mma_bf16(acc[2*np+1], qa_h, kbh[2], kbh[3]);
                mma_bf16(acc[2*np+1], qa_h, kbl[2], kbl[3]);
                mma_bf16(acc[2*np+1], qa_l, kbh[2], kbh[3]);
            }
        }

        // ---- online softmax ----
        float pm0 = -1e30f, pm1 = -1e30f;
#pragma unroll
        for (int n = 0; n < 16; ++n) {
            pm0 = fmaxf(pm0, fmaxf(acc[n][0], acc[n][1]));
            pm1 = fmaxf(pm1, fmaxf(acc[n][2], acc[n][3]));
        }
        pm0 = fmaxf(pm0, __shfl_xor_sync(0xffffffffu, pm0, 1));
        pm0 = fmaxf(pm0, __shfl_xor_sync(0xffffffffu, pm0, 2));
        pm1 = fmaxf(pm1, __shfl_xor_sync(0xffffffffu, pm1, 1));
        pm1 = fmaxf(pm1, __shfl_xor_sync(0xffffffffu, pm1, 2));

        const float M0 = fmaxf(mq0, pm0 * Cs);
        const float M1 = fmaxf(mq1, pm1 * Cs);
        const float corr0 = exp2f(mq0 - M0);
        const float corr1 = exp2f(mq1 - M1);
        mq0 = M0; mq1 = M1;

        float rs0 = 0.0f, rs1 = 0.0f;
#pragma unroll
        for (int n = 0; n < 16; ++n) {
            acc[n][0] = exp2f(fmaf(acc[n][0], Cs, -M0));
            acc[n][1] = exp2f(fmaf(acc[n][1], Cs, -M0));
            acc[n][2] = exp2f(fmaf(acc[n][2], Cs, -M1));
            acc[n][3] = exp2f(fmaf(acc[n][3], Cs, -M1));
            rs0 += acc[n][0] + acc[n][1];
            rs1 += acc[n][2] + acc[n][3];
        }
        rs0 += __shfl_xor_sync(0xffffffffu, rs0, 1);
        rs0 += __shfl_xor_sync(0xffffffffu, rs0, 2);
        rs1 += __shfl_xor_sync(0xffffffffu, rs1, 1);
        rs1 += __shfl_xor_sync(0xffffffffu, rs1, 2);
        l0 = l0 * corr0 + rs0;
        l1 = l1 * corr1 + rs1;

#pragma unroll
        for (int n = 0; n < 16; ++n) {
            O[n][0] *= corr0; O[n][1] *= corr0;
            O[n][2] *= corr1; O[n][3] *= corr1;
        }

        CP_WAIT(0);        // V ready
        __syncthreads();

        // ---- O += P @ V ----
#pragma unroll
        for (int kc = 0; kc < 8; ++kc) {
            uint32_t ph[4], pl[4];
            ph[0] = cvt2bf(acc[2*kc][1],   acc[2*kc][0]);
            ph[1] = cvt2bf(acc[2*kc][3],   acc[2*kc][2]);
            ph[2] = cvt2bf(acc[2*kc+1][1], acc[2*kc+1][0]);
            ph[3] = cvt2bf(acc[2*kc+1][3], acc[2*kc+1][2]);
            {
                float e0 = acc[2*kc][0]   - bflo(ph[0]);
                float e1 = acc[2*kc][1]   - bfhi(ph[0]);
                pl[0] = cvt2bf(e1, e0);
                e0 = acc[2*kc][2]   - bflo(ph[1]);
                e1 = acc[2*kc][3]   - bfhi(ph[1]);
                pl[1] = cvt2bf(e1, e0);
                e0 = acc[2*kc+1][0] - bflo(ph[2]);
                e1 = acc[2*kc+1][1] - bfhi(ph[2]);
                pl[2] = cvt2bf(e1, e0);
                e0 = acc[2*kc+1][2] - bflo(ph[3]);
                e1 = acc[2*kc+1][3] - bfhi(ph[3]);
                pl[3] = cvt2bf(e1, e0);
            }
#pragma unroll
            for (int np = 0; np < 8; ++np) {
                uint32_t vbh[4], vbl[4];
                ldsm4t(vbh, smem_u + AVH + vb_off + (uint32_t)kc * (16 * AST * 2) + np * 32);
                ldsm4t(vbl, smem_u + AVL + vb_off + (uint32_t)kc * (16 * AST * 2) + np * 32);
                mma_bf16(O[2*np],   ph, vbh[0], vbh[1]);
                mma_bf16(O[2*np],   ph, vbl[0], vbl[1]);
                mma_bf16(O[2*np],   pl, vbh[0], vbh[1]);
                mma_bf16(O[2*np+1], ph, vbh[2], vbh[3]);
                mma_bf16(O[2*np+1], ph, vbl[2], vbl[3]);
                mma_bf16(O[2*np+1], pl, vbh[2], vbh[3]);
            }
        }
    }

    // ---- finalize: write bf16 hi/lo output ----
    const float inv0 = 1.0f / l0;
    const float inv1 = 1.0f / l1;
    const size_t r0g = (size_t)(b*SEQ + q0 + w*16 + (lane >> 2));
#pragma unroll
    for (int n = 0; n < 16; ++n) {
        const int col = h*HD + 8*n + 2*(lane & 3);
        const float o1x = O[n][0] * inv0, o1y = O[n][1] * inv0;
        const float o2x = O[n][2] * inv1, o2y = O[n][3] * inv1;
        const uint32_t h1 = cvt2bf(o1y, o1x);
        const uint32_t l1p = cvt2bf(o1y - bfhi(h1), o1x - bflo(h1));
        const uint32_t h2 = cvt2bf(o2y, o2x);
        const uint32_t l2p = cvt2bf(o2y - bfhi(h2), o2x - bflo(h2));
        *(uint32_t*)&a_h[r0g * DIM + col]       = h1;
        *(uint32_t*)&a_l[r0g * DIM + col]       = l1p;
        *(uint32_t*)&a_h[(r0g + 8) * DIM + col] = h2;
        *(uint32_t*)&a_l[(r0g + 8) * DIM + col] = l2p;
    }
}

// ============================================================================
// Launcher
// ============================================================================
extern "C" void kernel_launch(void* const* d_in, const int* in_sizes, int n_in,
                              void* d_out, int out_size)
{
    const float* x  = (const float*)d_in[0];
    const float* fr = (const float*)d_in[1];
    const float* wq = (const float*)d_in[2];
    const float* bq = (const float*)d_in[3];
    const float* wk = (const float*)d_in[4];
    const float* bk = (const float*)d_in[5];
    const float* wv = (const float*)d_in[6];
    const float* bv = (const float*)d_in[7];
    const float* wo = (const float*)d_in[8];
    const float* bo = (const float*)d_in[9];
    const float* gq = (const float*)d_in[10];
    const float* gk = (const float*)d_in[11];
    float* out = (float*)d_out;

    (void)in_sizes; (void)n_in; (void)out_size;

    cudaFuncSetAttribute(gemm_qkv_kernel, cudaFuncAttributeMaxDynamicSharedMemorySize, GEMM_SMEM);
    cudaFuncSetAttribute(gemm_out_kernel, cudaFuncAttributeMaxDynamicSharedMemorySize, GEMM_SMEM);
    cudaFuncSetAttribute(attn_kernel, cudaFuncAttributeMaxDynamicSharedMemorySize, ATTN_SMEM);

    const int n4_x = MROWS * DIM / 4;
    const int n4_w = DIM * DIM / 4;

    split_sel_kernel<<<n4_x / 256, 256>>>(x,  0, n4_x);
    split_sel_kernel<<<n4_w / 256, 256>>>(wq, 1, n4_w);
    split_sel_kernel<<<n4_w / 256, 256>>>(wk, 2, n4_w);
    split_sel_kernel<<<n4_w / 256, 256>>>(wv, 3, n4_w);
    split_sel_kernel<<<n4_w / 256, 256>>>(wo, 4, n4_w);

    gemm_qkv_kernel<<<dim3(DIM/128, MROWS/128, 3), 256, GEMM_SMEM>>>(bq, bk, bv);

    rmsnorm_rope_kernel<<<dim3(MROWS, 2), 256>>>(fr, gq, gk);
    split_sel_kernel<<<n4_x / 256, 256>>>(nullptr, 5, n4_x);   // g_v -> v_h/v_l

    attn_kernel<<<dim3(SEQ/128, NH, BSZ), 256, ATTN_SMEM>>>();

    gemm_out_kernel<<<dim3(DIM/128, MROWS/128, 1), 256, GEMM_SMEM>>>(bo, out);
}

// round 9
// speedup vs baseline: 5.2645x; 1.1275x over previous
#include <cuda_runtime.h>
#include <cuda_bf16.h>
#include <cstdint>

#define DIM   2048
#define BSZ   2
#define SEQ   2048
#define NH    16
#define HD    128
#define MROWS (BSZ*SEQ)   /* 4096 */

typedef unsigned long long ull;

// ---- PTX helpers (baseline PTX only; no sm_103a-gated features) ----
__device__ __forceinline__ uint32_t smem_to_u32(const void* p) {
    uint32_t a;
    asm("{ .reg .u64 t; cvta.to.shared.u64 t, %1; cvt.u32.u64 %0, t; }" : "=r"(a) : "l"(p));
    return a;
}
__device__ __forceinline__ void ldsm4(uint32_t (&r)[4], uint32_t addr) {
    asm volatile("ldmatrix.sync.aligned.m8n8.x4.shared.b16 {%0,%1,%2,%3}, [%4];"
                 : "=r"(r[0]), "=r"(r[1]), "=r"(r[2]), "=r"(r[3]) : "r"(addr));
}
__device__ __forceinline__ void ldsm4t(uint32_t (&r)[4], uint32_t addr) {
    asm volatile("ldmatrix.sync.aligned.m8n8.x4.trans.shared.b16 {%0,%1,%2,%3}, [%4];"
                 : "=r"(r[0]), "=r"(r[1]), "=r"(r[2]), "=r"(r[3]) : "r"(addr));
}
__device__ __forceinline__ void mma_bf16(float (&d)[4], const uint32_t (&a)[4],
                                         uint32_t b0, uint32_t b1) {
    asm volatile("mma.sync.aligned.m16n8k16.row.col.f32.bf16.bf16.f32 "
                 "{%0,%1,%2,%3}, {%4,%5,%6,%7}, {%8,%9}, {%0,%1,%2,%3};"
                 : "+f"(d[0]), "+f"(d[1]), "+f"(d[2]), "+f"(d[3])
                 : "r"(a[0]), "r"(a[1]), "r"(a[2]), "r"(a[3]), "r"(b0), "r"(b1));
}
__device__ __forceinline__ uint32_t cvt2bf(float hi, float lo) {
    uint32_t r; asm("cvt.rn.bf16x2.f32 %0, %1, %2;" : "=r"(r) : "f"(hi), "f"(lo)); return r;
}
__device__ __forceinline__ float bflo(uint32_t p) { return __uint_as_float(p << 16); }
__device__ __forceinline__ float bfhi(uint32_t p) { return __uint_as_float(p & 0xffff0000u); }

__device__ __forceinline__ void cp_async16(uint32_t saddr, const void* gptr) {
    asm volatile("cp.async.cg.shared.global [%0], [%1], 16;" :: "r"(saddr), "l"(gptr));
}
#define CP_COMMIT()  asm volatile("cp.async.commit_group;" ::: "memory")
#define CP_WAIT(n)   asm volatile("cp.async.wait_group %0;" :: "n"(n) : "memory")

// ---- scratch (device globals: allocation-free rule) ----
__device__ float g_q[MROWS*DIM];
__device__ float g_k[MROWS*DIM];
__device__ float g_v[MROWS*DIM];
__device__ __nv_bfloat16 x_h[MROWS*DIM],  x_l[MROWS*DIM];
__device__ __nv_bfloat16 wq_h[DIM*DIM], wq_l[DIM*DIM];
__device__ __nv_bfloat16 wk_h[DIM*DIM], wk_l[DIM*DIM];
__device__ __nv_bfloat16 wv_h[DIM*DIM], wv_l[DIM*DIM];
__device__ __nv_bfloat16 wo_h[DIM*DIM], wo_l[DIM*DIM];
__device__ __nv_bfloat16 q_h[MROWS*DIM], q_l[MROWS*DIM];
__device__ __nv_bfloat16 k_h[MROWS*DIM], k_l[MROWS*DIM];
__device__ __nv_bfloat16 v_h[MROWS*DIM], v_l[MROWS*DIM];
__device__ __nv_bfloat16 a_h[MROWS*DIM], a_l[MROWS*DIM];

__device__ __forceinline__ void split4(float4 v, uint2& hi, uint2& lo) {
    __nv_bfloat16 h0 = __float2bfloat16(v.x);
    __nv_bfloat16 h1 = __float2bfloat16(v.y);
    __nv_bfloat16 h2 = __float2bfloat16(v.z);
    __nv_bfloat16 h3 = __float2bfloat16(v.w);
    __nv_bfloat16 l0 = __float2bfloat16(v.x - __bfloat162float(h0));
    __nv_bfloat16 l1 = __float2bfloat16(v.y - __bfloat162float(h1));
    __nv_bfloat16 l2 = __float2bfloat16(v.z - __bfloat162float(h2));
    __nv_bfloat16 l3 = __float2bfloat16(v.w - __bfloat16_as_ushort(h3) * 0.0f - __bfloat162float(h3));
    hi.x = ((uint32_t)__bfloat16_as_ushort(h1) << 16) | __bfloat16_as_ushort(h0);
    hi.y = ((uint32_t)__bfloat16_as_ushort(h3) << 16) | __bfloat16_as_ushort(h2);
    lo.x = ((uint32_t)__bfloat16_as_ushort(l1) << 16) | __bfloat16_as_ushort(l0);
    lo.y = ((uint32_t)__bfloat16_as_ushort(l3) << 16) | __bfloat16_as_ushort(l2);
}

// ============================================================================
// fp32 -> bf16 hi/lo split kernels (sel picks the destination globals)
// ============================================================================
__global__ void __launch_bounds__(256) split_sel_kernel(const float* __restrict__ src,
                                                        int sel, int n4)
{
    const int i = blockIdx.x * blockDim.x + threadIdx.x;
    if (i >= n4) return;
    __nv_bfloat16 *hi, *lo;
    const float* s = src;
    switch (sel) {
        case 0: hi = x_h;  lo = x_l;  break;
        case 1: hi = wq_h; lo = wq_l; break;
        case 2: hi = wk_h; lo = wk_l; break;
        case 3: hi = wv_h; lo = wv_l; break;
        case 4: hi = wo_h; lo = wo_l; break;
        default: hi = v_h; lo = v_l; s = g_v; break;
    }
    const float4 v = ((const float4*)s)[i];
    uint2 h, l; split4(v, h, l);
    ((uint2*)hi)[i] = h;
    ((uint2*)lo)[i] = l;
}

// weights batched: z = 0..3 -> wq,wk,wv,wo
__global__ void __launch_bounds__(256) split_w_kernel(
    const float* __restrict__ wq, const float* __restrict__ wk,
    const float* __restrict__ wv, const float* __restrict__ wo, int n4)
{
    const int i = blockIdx.x * blockDim.x + threadIdx.x;
    if (i >= n4) return;
    const float* s;
    __nv_bfloat16 *hi, *lo;
    switch (blockIdx.y) {
        case 0: s = wq; hi = wq_h; lo = wq_l; break;
        case 1: s = wk; hi = wk_h; lo = wk_l; break;
        case 2: s = wv; hi = wv_h; lo = wv_l; break;
        default: s = wo; hi = wo_h; lo = wo_l; break;
    }
    const float4 v = ((const float4*)s)[i];
    uint2 h, l; split4(v, h, l);
    ((uint2*)hi)[i] = h;
    ((uint2*)lo)[i] = l;
}

// ============================================================================
// HMMA GEMM: C[M,N] = (Ah+Al)[M,K] @ (Bh+Bl)[N,K]^T + bias
// 128x128 CTA tile, 8 warps (2x4), 3 MMAs per product, fp32 accum.
// K staged by 32; 2-stage cp.async pipeline; 2 CTAs/SM (80KB smem, <=128 regs).
// ============================================================================
#define BK        32
#define NSTAGES   (DIM / BK)            /* 64 */
#define LDS_B     40                    /* bf16 elems per smem row (pad 8) */
#define TILE_BYT  (128 * LDS_B * 2)     /* 10240 */
#define OFF_AHI   0
#define OFF_ALO   (1 * TILE_BYT)
#define OFF_BHI   (2 * TILE_BYT)
#define OFF_BLO   (3 * TILE_BYT)
#define STG_BYT   (4 * TILE_BYT)        /* 40960 */
#define GEMM_SMEM (2 * STG_BYT)         /* 81920 -> 2 CTAs/SM */

__device__ __forceinline__ void gemm_issue(uint32_t dstbase,
    const __nv_bfloat16* __restrict__ Ah, const __nv_bfloat16* __restrict__ Al,
    const __nv_bfloat16* __restrict__ Bh, const __nv_bfloat16* __restrict__ Bl,
    int rowBase, int colBase, int kofs, int tid)
{
#pragma unroll
    for (int i = 0; i < 2; ++i) {
        const int f = i * 256 + tid;
        const int r = f >> 2, c = f & 3;
        const uint32_t d = dstbase + (uint32_t)r * (LDS_B * 2) + (uint32_t)c * 16;
        const size_t gA = (size_t)(rowBase + r) * DIM + kofs + c * 8;
        const size_t gB = (size_t)(colBase + r) * DIM + kofs + c * 8;
        cp_async16(d + OFF_AHI, Ah + gA);
        cp_async16(d + OFF_ALO, Al + gA);
        cp_async16(d + OFF_BHI, Bh + gB);
        cp_async16(d + OFF_BLO, Bl + gB);
    }
    CP_COMMIT();
}

__device__ __forceinline__ void gemm_tc_core(
    const __nv_bfloat16* __restrict__ Ah, const __nv_bfloat16* __restrict__ Al,
    const __nv_bfloat16* __restrict__ Bh, const __nv_bfloat16* __restrict__ Bl,
    const float* __restrict__ bias, float* __restrict__ C)
{
    extern __shared__ char smem[];
    const uint32_t smem_u = smem_to_u32(smem);
    const int tid  = threadIdx.x;
    const int lane = tid & 31;
    const int wid  = tid >> 5;
    const int wm   = wid & 1;
    const int wn   = wid >> 1;

    const int rowBase = blockIdx.y * 128;
    const int colBase = blockIdx.x * 128;

    const uint32_t a_off = (uint32_t)(wm * 64 + (lane & 15)) * (LDS_B * 2)
                         + (uint32_t)((lane >> 4) * 8) * 2;
    const uint32_t b_off = (uint32_t)(wn * 32 + ((lane >> 4) & 1) * 8 + (lane & 7)) * (LDS_B * 2)
                         + (uint32_t)(((lane >> 3) & 1) * 8) * 2;

    float acc[4][4][4];
#pragma unroll
    for (int t = 0; t < 4; ++t)
#pragma unroll
        for (int n = 0; n < 4; ++n)
#pragma unroll
            for (int e = 0; e < 4; ++e) acc[t][n][e] = 0.0f;

    // prologue: stages 0,1 in flight
    gemm_issue(smem_u,           Ah, Al, Bh, Bl, rowBase, colBase, 0,  tid);
    gemm_issue(smem_u + STG_BYT, Ah, Al, Bh, Bl, rowBase, colBase, BK, tid);

    for (int s = 0; s < NSTAGES; ++s) {
        CP_WAIT(1);
        __syncthreads();

        const uint32_t cb = smem_u + (uint32_t)(s & 1) * STG_BYT;
#pragma unroll
        for (int ks = 0; ks < 2; ++ks) {
            uint32_t ah[4][4], al[4][4], bh[2][4], bl[2][4];
#pragma unroll
            for (int t = 0; t < 4; ++t) {
                ldsm4(ah[t], cb + OFF_AHI + a_off + (uint32_t)t * (16 * LDS_B * 2) + ks * 32);
                ldsm4(al[t], cb + OFF_ALO + a_off + (uint32_t)t * (16 * LDS_B * 2) + ks * 32);
            }
#pragma unroll
            for (int p = 0; p < 2; ++p) {
                ldsm4(bh[p], cb + OFF_BHI + b_off + (uint32_t)p * (16 * LDS_B * 2) + ks * 32);
                ldsm4(bl[p], cb + OFF_BLO + b_off + (uint32_t)p * (16 * LDS_B * 2) + ks * 32);
            }
#pragma unroll
            for (int t = 0; t < 4; ++t) {
#pragma unroll
                for (int n = 0; n < 4; ++n) {
                    const int p = n >> 1, sub = n & 1;
                    mma_bf16(acc[t][n], ah[t], bh[p][sub * 2], bh[p][sub * 2 + 1]);
                    mma_bf16(acc[t][n], ah[t], bl[p][sub * 2], bl[p][sub * 2 + 1]);
                    mma_bf16(acc[t][n], al[t], bh[p][sub * 2], bh[p][sub * 2 + 1]);
                }
            }
        }

        __syncthreads();   // all warps done reading buffer (s&1) before refill
        if (s + 2 < NSTAGES)
            gemm_issue(smem_u + (uint32_t)(s & 1) * STG_BYT, Ah, Al, Bh, Bl,
                       rowBase, colBase, (s + 2) * BK, tid);
        else
            CP_COMMIT();   // keep group count uniform for CP_WAIT accounting
    }

#pragma unroll
    for (int t = 0; t < 4; ++t) {
        const int r1 = rowBase + wm * 64 + t * 16 + (lane >> 2);
#pragma unroll
        for (int n = 0; n < 4; ++n) {
            const int col = colBase + wn * 32 + n * 8 + (lane & 3) * 2;
            const float2 b2 = *(const float2*)&bias[col];
            float2 o1, o2;
            o1.x = acc[t][n][0] + b2.x; o1.y = acc[t][n][1] + b2.y;
            o2.x = acc[t][n][2] + b2.x; o2.y = acc[t][n][3] + b2.y;
            *(float2*)&C[(size_t)r1 * DIM + col]       = o1;
            *(float2*)&C[(size_t)(r1 + 8) * DIM + col] = o2;
        }
    }
}

__global__ void __launch_bounds__(256, 2) gemm_qkv_kernel(
    const float* __restrict__ bq, const float* __restrict__ bk, const float* __restrict__ bv)
{
    if (blockIdx.z == 0)      gemm_tc_core(x_h, x_l, wq_h, wq_l, bq, g_q);
    else if (blockIdx.z == 1) gemm_tc_core(x_h, x_l, wk_h, wk_l, bk, g_k);
    else                      gemm_tc_core(x_h, x_l, wv_h, wv_l, bv, g_v);
}

__global__ void __launch_bounds__(256, 2) gemm_out_kernel(
    const float* __restrict__ bo, float* __restrict__ out)
{
    gemm_tc_core(a_h, a_l, wo_h, wo_l, bo, out);
}

// ============================================================================
// Fused RMSNorm(+gain) + RoPE. Reads g_q/g_k fp32, writes bf16 hi/lo pairs.
// ============================================================================
__global__ void __launch_bounds__(256) rmsnorm_rope_kernel(
    const float* __restrict__ freqs, const float* __restrict__ gq, const float* __restrict__ gk)
{
    const int row = blockIdx.x;
    const int s = row & (SEQ - 1);
    const float* xb = (blockIdx.y == 0 ? g_q : g_k) + (size_t)row * DIM;
    __nv_bfloat16* oh = (blockIdx.y == 0 ? q_h : k_h) + (size_t)row * DIM;
    __nv_bfloat16* ol = (blockIdx.y == 0 ? q_l : k_l) + (size_t)row * DIM;
    const float* g = (blockIdx.y == 0) ? gq : gk;
    const int tid = threadIdx.x;
    const int base = tid * 8;

    const float4 u = *(const float4*)(xb + base);
    const float4 w = *(const float4*)(xb + base + 4);
    float ss = u.x*u.x + u.y*u.y + u.z*u.z + u.w*u.w
             + w.x*w.x + w.y*w.y + w.z*w.z + w.w*w.w;
#pragma unroll
    for (int m = 16; m > 0; m >>= 1) ss += __shfl_xor_sync(0xffffffffu, ss, m);
    __shared__ float red[8];
    if ((tid & 31) == 0) red[tid >> 5] = ss;
    __syncthreads();
    const float tot = red[0]+red[1]+red[2]+red[3]+red[4]+red[5]+red[6]+red[7];
    const float rinv = rsqrtf(tot * (1.0f/DIM) + 1e-6f);

    const float4 g0 = *(const float4*)(g + base);
    const float4 g1 = *(const float4*)(g + base + 4);
    float y[8] = {u.x*rinv*g0.x, u.y*rinv*g0.y, u.z*rinv*g0.z, u.w*rinv*g0.w,
                  w.x*rinv*g1.x, w.y*rinv*g1.y, w.z*rinv*g1.z, w.w*rinv*g1.w};

    const float* fr = freqs + (size_t)s * HD;
    float o[8];
#pragma unroll
    for (int p = 0; p < 4; ++p) {
        const int col = base + 2*p;
        const int jj = (col & (HD - 1)) >> 1;
        const float cr = fr[2*jj], ci = fr[2*jj + 1];
        const float xr = y[2*p], xi = y[2*p + 1];
        o[2*p]     = xr*cr - xi*ci;
        o[2*p + 1] = xr*ci + xi*cr;
    }
    float4 r0; r0.x = o[0]; r0.y = o[1]; r0.z = o[2]; r0.w = o[3];
    float4 r1; r1.x = o[4]; r1.y = o[5]; r1.z = o[6]; r1.w = o[7];
    uint2 h, l;
    split4(r0, h, l);
    *(uint2*)(oh + base)     = h;
    *(uint2*)(ol + base)     = l;
    split4(r1, h, l);
    *(uint2*)(oh + base + 4) = h;
    *(uint2*)(ol + base + 4) = l;
}

// ============================================================================
// HMMA flash attention on preconverted bf16 hi/lo. 128 q-rows/CTA, 128-kv tiles.
// cp.async loads; V copy overlapped under the QK matmul.
// ============================================================================
#define AST   136                        /* halves per smem row */
#define ATILE_BYT (128 * AST * 2)        /* 34816 */
#define AQH  0
#define AQL  (1 * ATILE_BYT)
#define AKH  (2 * ATILE_BYT)
#define AKL  (3 * ATILE_BYT)
#define AVH  (4 * ATILE_BYT)
#define AVL  (5 * ATILE_BYT)
#define ATTN_SMEM (6 * ATILE_BYT)        /* 208896 */

__global__ void __launch_bounds__(256) attn_kernel()
{
    extern __shared__ char smh[];
    const uint32_t smem_u = smem_to_u32(smh);
    const int tid  = threadIdx.x;
    const int lane = tid & 31;
    const int w    = tid >> 5;
    const int b    = blockIdx.z;
    const int h    = blockIdx.y;
    const int q0   = blockIdx.x * 128;

    const size_t qrow0 = (size_t)(b*SEQ + q0) * DIM + h*HD;
    const size_t krow0 = (size_t)(b*SEQ) * DIM + h*HD;

#pragma unroll
    for (int i = 0; i < 8; ++i) {
        const int f = i * 256 + tid;
        const int r = f >> 4, c = f & 15;
        const uint32_t d = (uint32_t)r * (AST * 2) + (uint32_t)c * 16;
        const size_t gsrc = qrow0 + (size_t)r * DIM + c * 8;
        cp_async16(smem_u + AQH + d, q_h + gsrc);
        cp_async16(smem_u + AQL + d, q_l + gsrc);
    }
    CP_COMMIT();

    const uint32_t a_off  = ((uint32_t)(w * 16 + (lane & 15)) * AST
                           + (uint32_t)((lane >> 4) * 8)) * 2;
    const uint32_t kb_off = ((uint32_t)(((lane >> 4) & 1) * 8 + (lane & 7)) * AST
                           + (uint32_t)(((lane >> 3) & 1) * 8)) * 2;
    const uint32_t vb_off = ((uint32_t)(((lane >> 3) & 1) * 8 + (lane & 7)) * AST
                           + (uint32_t)(((lane >> 4) & 1) * 8)) * 2;

    float O[16][4];
#pragma unroll
    for (int n = 0; n < 16; ++n)
#pragma unroll
        for (int e = 0; e < 4; ++e) O[n][e] = 0.0f;
    float mq0 = -1e30f, mq1 = -1e30f, l0 = 0.0f, l1 = 0.0f;

    const float Cs = 0.12754276931699657f;   // (1/sqrt(128)) * log2(e)

    for (int kt = 0; kt < SEQ / 128; ++kt) {
        __syncthreads();

        const size_t krow = krow0 + (size_t)(kt * 128) * DIM;
#pragma unroll
        for (int i = 0; i < 8; ++i) {
            const int f = i * 256 + tid;
            const int r = f >> 4, c = f & 15;
            const uint32_t d = (uint32_t)r * (AST * 2) + (uint32_t)c * 16;
            const size_t gsrc = krow + (size_t)r * DIM + c * 8;
            cp_async16(smem_u + AKH + d, k_h + gsrc);
            cp_async16(smem_u + AKL + d, k_l + gsrc);
        }
        CP_COMMIT();
#pragma unroll
        for (int i = 0; i < 8; ++i) {
            const int f = i * 256 + tid;
            const int r = f >> 4, c = f & 15;
            const uint32_t d = (uint32_t)r * (AST * 2) + (uint32_t)c * 16;
            const size_t gsrc = krow + (size_t)r * DIM + c * 8;
            cp_async16(smem_u + AVH + d, v_h + gsrc);
            cp_async16(smem_u + AVL + d, v_l + gsrc);
        }
        CP_COMMIT();

        CP_WAIT(1);
        __syncthreads();

        float acc[16][4];
#pragma unroll
        for (int n = 0; n < 16; ++n)
#pragma unroll
            for (int e = 0; e < 4; ++e) acc[n][e] = 0.0f;

#pragma unroll
        for (int kc = 0; kc < 8; ++kc) {
            uint32_t qa_h[4], qa_l[4];
            ldsm4(qa_h, smem_u + AQH + a_off + kc * 32);
            ldsm4(qa_l, smem_u + AQL + a_off + kc * 32);
#pragma unroll
            for (int np = 0; np < 8; ++np) {
                uint32_t kbh[4], kbl[4];
                ldsm4(kbh, smem_u + AKH + kb_off + (uint32_t)np * (16 * AST * 2) + kc * 32);
                ldsm4(kbl, smem_u + AKL + kb_off + (uint32_t)np * (16 * AST * 2) + kc * 32);
                mma_bf16(acc[2*np],   qa_h, kbh[0], kbh[1]);
                mma_bf16(acc[2*np],   qa_h, kbl[0], kbl[1]);
                mma_bf16(acc[2*np],   qa_l, kbh[0], kbh[1]);
                mma_bf16(acc[2*np+1], qa_h, kbh[2], kbh[3]);
                mma_bf16(acc[2*np+1], qa_h, kbl[2], kbl[3]);
                mma_bf16(acc[2*np+1], qa_l, kbh[2], kbh[3]);
            }
        }

        float pm0 = -1e30f, pm1 = -1e30f;
#pragma unroll
        for (int n = 0; n < 16; ++n) {
            pm0 = fmaxf(pm0, fmaxf(acc[n][0], acc[n][1]));
            pm1 = fmaxf(pm1, fmaxf(acc[n][2], acc[n][3]));
        }
        pm0 = fmaxf(pm0, __shfl_xor_sync(0xffffffffu, pm0, 1));
        pm0 = fmaxf(pm0, __shfl_xor_sync(0xffffffffu, pm0, 2));
        pm1 = fmaxf(pm1, __shfl_xor_sync(0xffffffffu, pm1, 1));
        pm1 = fmaxf(pm1, __shfl_xor_sync(0xffffffffu, pm1, 2));

        const float M0 = fmaxf(mq0, pm0 * Cs);
        const float M1 = fmaxf(mq1, pm1 * Cs);
        const float corr0 = exp2f(mq0 - M0);
        const float corr1 = exp2f(mq1 - M1);
        mq0 = M0; mq1 = M1;

        float rs0 = 0.0f, rs1 = 0.0f;
#pragma unroll
        for (int n = 0; n < 16; ++n) {
            acc[n][0] = exp2f(fmaf(acc[n][0], Cs, -M0));
            acc[n][1] = exp2f(fmaf(acc[n][1], Cs, -M0));
            acc[n][2] = exp2f(fmaf(acc[n][2], Cs, -M1));
            acc[n][3] = exp2f(fmaf(acc[n][3], Cs, -M1));
            rs0 += acc[n][0] + acc[n][1];
            rs1 += acc[n][2] + acc[n][3];
        }
        rs0 += __shfl_xor_sync(0xffffffffu, rs0, 1);
        rs0 += __shfl_xor_sync(0xffffffffu, rs0, 2);
        rs1 += __shfl_xor_sync(0xffffffffu, rs1, 1);
        rs1 += __shfl_xor_sync(0xffffffffu, rs1, 2);
        l0 = l0 * corr0 + rs0;
        l1 = l1 * corr1 + rs1;

#pragma unroll
        for (int n = 0; n < 16; ++n) {
            O[n][0] *= corr0; O[n][1] *= corr0;
            O[n][2] *= corr1; O[n][3] *= corr1;
        }

        CP_WAIT(0);
        __syncthreads();

#pragma unroll
        for (int kc = 0; kc < 8; ++kc) {
            uint32_t ph[4], pl[4];
            ph[0] = cvt2bf(acc[2*kc][1],   acc[2*kc][0]);
            ph[1] = cvt2bf(acc[2*kc][3],   acc[2*kc][2]);
            ph[2] = cvt2bf(acc[2*kc+1][1], acc[2*kc+1][0]);
            ph[3] = cvt2bf(acc[2*kc+1][3], acc[2*kc+1][2]);
            {
                float e0 = acc[2*kc][0]   - bflo(ph[0]);
                float e1 = acc[2*kc][1]   - bfhi(ph[0]);
                pl[0] = cvt2bf(e1, e0);
                e0 = acc[2*kc][2]   - bflo(ph[1]);
                e1 = acc[2*kc][3]   - bfhi(ph[1]);
                pl[1] = cvt2bf(e1, e0);
                e0 = acc[2*kc+1][0] - bflo(ph[2]);
                e1 = acc[2*kc+1][1] - bfhi(ph[2]);
                pl[2] = cvt2bf(e1, e0);
                e0 = acc[2*kc+1][2] - bflo(ph[3]);
                e1 = acc[2*kc+1][3] - bfhi(ph[3]);
                pl[3] = cvt2bf(e1, e0);
            }
#pragma unroll
            for (int np = 0; np < 8; ++np) {
                uint32_t vbh[4], vbl[4];
                ldsm4t(vbh, smem_u + AVH + vb_off + (uint32_t)kc * (16 * AST * 2) + np * 32);
                ldsm4t(vbl, smem_u + AVL + vb_off + (uint32_t)kc * (16 * AST * 2) + np * 32);
                mma_bf16(O[2*np],   ph, vbh[0], vbh[1]);
                mma_bf16(O[2*np],   ph, vbl[0], vbl[1]);
                mma_bf16(O[2*np],   pl, vbh[0], vbh[1]);
                mma_bf16(O[2*np+1], ph, vbh[2], vbh[3]);
                mma_bf16(O[2*np+1], ph, vbl[2], vbl[3]);
                mma_bf16(O[2*np+1], pl, vbh[2], vbh[3]);
            }
        }
    }

    const float inv0 = 1.0f / l0;
    const float inv1 = 1.0f / l1;
    const size_t r0g = (size_t)(b*SEQ + q0 + w*16 + (lane >> 2));
#pragma unroll
    for (int n = 0; n < 16; ++n) {
        const int col = h*HD + 8*n + 2*(lane & 3);
        const float o1x = O[n][0] * inv0, o1y = O[n][1] * inv0;
        const float o2x = O[n][2] * inv1, o2y = O[n][3] * inv1;
        const uint32_t h1 = cvt2bf(o1y, o1x);
        const uint32_t l1p = cvt2bf(o1y - bfhi(h1), o1x - bflo(h1));
        const uint32_t h2 = cvt2bf(o2y, o2x);
        const uint32_t l2p = cvt2bf(o2y - bfhi(h2), o2x - bflo(h2));
        *(uint32_t*)&a_h[r0g * DIM + col]       = h1;
        *(uint32_t*)&a_l[r0g * DIM + col]       = l1p;
        *(uint32_t*)&a_h[(r0g + 8) * DIM + col] = h2;
        *(uint32_t*)&a_l[(r0g + 8) * DIM + col] = l2p;
    }
}

// ============================================================================
// Launcher
// ============================================================================
extern "C" void kernel_launch(void* const* d_in, const int* in_sizes, int n_in,
                              void* d_out, int out_size)
{
    const float* x  = (const float*)d_in[0];
    const float* fr = (const float*)d_in[1];
    const float* wq = (const float*)d_in[2];
    const float* bq = (const float*)d_in[3];
    const float* wk = (const float*)d_in[4];
    const float* bk = (const float*)d_in[5];
    const float* wv = (const float*)d_in[6];
    const float* bv = (const float*)d_in[7];
    const float* wo = (const float*)d_in[8];
    const float* bo = (const float*)d_in[9];
    const float* gq = (const float*)d_in[10];
    const float* gk = (const float*)d_in[11];
    float* out = (float*)d_out;

    (void)in_sizes; (void)n_in; (void)out_size;

    cudaFuncSetAttribute(gemm_qkv_kernel, cudaFuncAttributeMaxDynamicSharedMemorySize, GEMM_SMEM);
    cudaFuncSetAttribute(gemm_out_kernel, cudaFuncAttributeMaxDynamicSharedMemorySize, GEMM_SMEM);
    cudaFuncSetAttribute(attn_kernel, cudaFuncAttributeMaxDynamicSharedMemorySize, ATTN_SMEM);

    const int n4_x = MROWS * DIM / 4;
    const int n4_w = DIM * DIM / 4;

    split_sel_kernel<<<n4_x / 256, 256>>>(x, 0, n4_x);
    split_w_kernel<<<dim3(n4_w / 256, 4), 256>>>(wq, wk, wv, wo, n4_w);

    gemm_qkv_kernel<<<dim3(DIM/128, MROWS/128, 3), 256, GEMM_SMEM>>>(bq, bk, bv);

    rmsnorm_rope_kernel<<<dim3(MROWS, 2), 256>>>(fr, gq, gk);
    split_sel_kernel<<<n4_x / 256, 256>>>(nullptr, 5, n4_x);   // g_v -> v_h/v_l

    attn_kernel<<<dim3(SEQ/128, NH, BSZ), 256, ATTN_SMEM>>>();

    gemm_out_kernel<<<dim3(DIM/128, MROWS/128, 1), 256, GEMM_SMEM>>>(bo, out);
}

// round 10
// speedup vs baseline: 5.3510x; 1.0164x over previous
#include <cuda_runtime.h>
#include <cuda_bf16.h>
#include <cstdint>

#define DIM   2048
#define BSZ   2
#define SEQ   2048
#define NH    16
#define HD    128
#define MROWS (BSZ*SEQ)   /* 4096 */

typedef unsigned long long ull;

// ---- PTX helpers (baseline PTX only; no sm_103a-gated features) ----
__device__ __forceinline__ uint32_t smem_to_u32(const void* p) {
    uint32_t a;
    asm("{ .reg .u64 t; cvta.to.shared.u64 t, %1; cvt.u32.u64 %0, t; }" : "=r"(a) : "l"(p));
    return a;
}
__device__ __forceinline__ void ldsm4(uint32_t (&r)[4], uint32_t addr) {
    asm volatile("ldmatrix.sync.aligned.m8n8.x4.shared.b16 {%0,%1,%2,%3}, [%4];"
                 : "=r"(r[0]), "=r"(r[1]), "=r"(r[2]), "=r"(r[3]) : "r"(addr));
}
__device__ __forceinline__ void ldsm4t(uint32_t (&r)[4], uint32_t addr) {
    asm volatile("ldmatrix.sync.aligned.m8n8.x4.trans.shared.b16 {%0,%1,%2,%3}, [%4];"
                 : "=r"(r[0]), "=r"(r[1]), "=r"(r[2]), "=r"(r[3]) : "r"(addr));
}
__device__ __forceinline__ void mma_bf16(float (&d)[4], const uint32_t (&a)[4],
                                         uint32_t b0, uint32_t b1) {
    asm volatile("mma.sync.aligned.m16n8k16.row.col.f32.bf16.bf16.f32 "
                 "{%0,%1,%2,%3}, {%4,%5,%6,%7}, {%8,%9}, {%0,%1,%2,%3};"
                 : "+f"(d[0]), "+f"(d[1]), "+f"(d[2]), "+f"(d[3])
                 : "r"(a[0]), "r"(a[1]), "r"(a[2]), "r"(a[3]), "r"(b0), "r"(b1));
}
__device__ __forceinline__ uint32_t cvt2bf(float hi, float lo) {
    uint32_t r; asm("cvt.rn.bf16x2.f32 %0, %1, %2;" : "=r"(r) : "f"(hi), "f"(lo)); return r;
}
__device__ __forceinline__ float bflo(uint32_t p) { return __uint_as_float(p << 16); }
__device__ __forceinline__ float bfhi(uint32_t p) { return __uint_as_float(p & 0xffff0000u); }

__device__ __forceinline__ void cp_async16(uint32_t saddr, const void* gptr) {
    asm volatile("cp.async.cg.shared.global [%0], [%1], 16;" :: "r"(saddr), "l"(gptr));
}
#define CP_COMMIT()  asm volatile("cp.async.commit_group;" ::: "memory")
#define CP_WAIT(n)   asm volatile("cp.async.wait_group %0;" :: "n"(n) : "memory")

// ---- scratch (device globals: allocation-free rule) ----
__device__ float g_q[MROWS*DIM];
__device__ float g_k[MROWS*DIM];
__device__ __nv_bfloat16 x_h[MROWS*DIM],  x_l[MROWS*DIM];
__device__ __nv_bfloat16 wq_h[DIM*DIM], wq_l[DIM*DIM];
__device__ __nv_bfloat16 wk_h[DIM*DIM], wk_l[DIM*DIM];
__device__ __nv_bfloat16 wv_h[DIM*DIM], wv_l[DIM*DIM];
__device__ __nv_bfloat16 wo_h[DIM*DIM], wo_l[DIM*DIM];
__device__ __nv_bfloat16 q_h[MROWS*DIM], q_l[MROWS*DIM];
__device__ __nv_bfloat16 k_h[MROWS*DIM], k_l[MROWS*DIM];
__device__ __nv_bfloat16 v_h[MROWS*DIM], v_l[MROWS*DIM];
__device__ __nv_bfloat16 a_h[MROWS*DIM], a_l[MROWS*DIM];

__device__ __forceinline__ void split4(float4 v, uint2& hi, uint2& lo) {
    __nv_bfloat16 h0 = __float2bfloat16(v.x);
    __nv_bfloat16 h1 = __float2bfloat16(v.y);
    __nv_bfloat16 h2 = __float2bfloat16(v.z);
    __nv_bfloat16 h3 = __float2bfloat16(v.w);
    __nv_bfloat16 l0 = __float2bfloat16(v.x - __bfloat162float(h0));
    __nv_bfloat16 l1 = __float2bfloat16(v.y - __bfloat162float(h1));
    __nv_bfloat16 l2 = __float2bfloat16(v.z - __bfloat162float(h2));
    __nv_bfloat16 l3 = __float2bfloat16(v.w - __bfloat162float(h3));
    hi.x = ((uint32_t)__bfloat16_as_ushort(h1) << 16) | __bfloat16_as_ushort(h0);
    hi.y = ((uint32_t)__bfloat16_as_ushort(h3) << 16) | __bfloat16_as_ushort(h2);
    lo.x = ((uint32_t)__bfloat16_as_ushort(l1) << 16) | __bfloat16_as_ushort(l0);
    lo.y = ((uint32_t)__bfloat16_as_ushort(l3) << 16) | __bfloat16_as_ushort(l2);
}

// ============================================================================
// fp32 -> bf16 hi/lo split kernels
// ============================================================================
__global__ void __launch_bounds__(256) split_x_kernel(const float* __restrict__ src, int n4)
{
    const int i = blockIdx.x * blockDim.x + threadIdx.x;
    if (i >= n4) return;
    const float4 v = ((const float4*)src)[i];
    uint2 h, l; split4(v, h, l);
    ((uint2*)x_h)[i] = h;
    ((uint2*)x_l)[i] = l;
}

__global__ void __launch_bounds__(256) split_w_kernel(
    const float* __restrict__ wq, const float* __restrict__ wk,
    const float* __restrict__ wv, const float* __restrict__ wo, int n4)
{
    const int i = blockIdx.x * blockDim.x + threadIdx.x;
    if (i >= n4) return;
    const float* s;
    __nv_bfloat16 *hi, *lo;
    switch (blockIdx.y) {
        case 0: s = wq; hi = wq_h; lo = wq_l; break;
        case 1: s = wk; hi = wk_h; lo = wk_l; break;
        case 2: s = wv; hi = wv_h; lo = wv_l; break;
        default: s = wo; hi = wo_h; lo = wo_l; break;
    }
    const float4 v = ((const float4*)s)[i];
    uint2 h, l; split4(v, h, l);
    ((uint2*)hi)[i] = h;
    ((uint2*)lo)[i] = l;
}

// ============================================================================
// HMMA GEMM: C[M,N] = (Ah+Al)[M,K] @ (Bh+Bl)[N,K]^T + bias
// 128x128 CTA tile, 8 warps (2x4), 3 MMAs per product, fp32 accum.
// 2-stage cp.async pipeline; 2 CTAs/SM. BF16OUT writes hi/lo split directly.
// ============================================================================
#define BK        32
#define NSTAGES   (DIM / BK)            /* 64 */
#define LDS_B     40
#define TILE_BYT  (128 * LDS_B * 2)     /* 10240 */
#define OFF_AHI   0
#define OFF_ALO   (1 * TILE_BYT)
#define OFF_BHI   (2 * TILE_BYT)
#define OFF_BLO   (3 * TILE_BYT)
#define STG_BYT   (4 * TILE_BYT)        /* 40960 */
#define GEMM_SMEM (2 * STG_BYT)         /* 81920 -> 2 CTAs/SM */

__device__ __forceinline__ void gemm_issue(uint32_t dstbase,
    const __nv_bfloat16* __restrict__ Ah, const __nv_bfloat16* __restrict__ Al,
    const __nv_bfloat16* __restrict__ Bh, const __nv_bfloat16* __restrict__ Bl,
    int rowBase, int colBase, int kofs, int tid)
{
#pragma unroll
    for (int i = 0; i < 2; ++i) {
        const int f = i * 256 + tid;
        const int r = f >> 2, c = f & 3;
        const uint32_t d = dstbase + (uint32_t)r * (LDS_B * 2) + (uint32_t)c * 16;
        const size_t gA = (size_t)(rowBase + r) * DIM + kofs + c * 8;
        const size_t gB = (size_t)(colBase + r) * DIM + kofs + c * 8;
        cp_async16(d + OFF_AHI, Ah + gA);
        cp_async16(d + OFF_ALO, Al + gA);
        cp_async16(d + OFF_BHI, Bh + gB);
        cp_async16(d + OFF_BLO, Bl + gB);
    }
    CP_COMMIT();
}

template<bool BF16OUT>
__device__ __forceinline__ void gemm_tc_core(
    const __nv_bfloat16* __restrict__ Ah, const __nv_bfloat16* __restrict__ Al,
    const __nv_bfloat16* __restrict__ Bh, const __nv_bfloat16* __restrict__ Bl,
    const float* __restrict__ bias, float* __restrict__ C,
    __nv_bfloat16* __restrict__ Ch, __nv_bfloat16* __restrict__ Cl)
{
    extern __shared__ char smem[];
    const uint32_t smem_u = smem_to_u32(smem);
    const int tid  = threadIdx.x;
    const int lane = tid & 31;
    const int wid  = tid >> 5;
    const int wm   = wid & 1;
    const int wn   = wid >> 1;

    const int rowBase = blockIdx.y * 128;
    const int colBase = blockIdx.x * 128;

    const uint32_t a_off = (uint32_t)(wm * 64 + (lane & 15)) * (LDS_B * 2)
                         + (uint32_t)((lane >> 4) * 8) * 2;
    const uint32_t b_off = (uint32_t)(wn * 32 + ((lane >> 4) & 1) * 8 + (lane & 7)) * (LDS_B * 2)
                         + (uint32_t)(((lane >> 3) & 1) * 8) * 2;

    float acc[4][4][4];
#pragma unroll
    for (int t = 0; t < 4; ++t)
#pragma unroll
        for (int n = 0; n < 4; ++n)
#pragma unroll
            for (int e = 0; e < 4; ++e) acc[t][n][e] = 0.0f;

    gemm_issue(smem_u,           Ah, Al, Bh, Bl, rowBase, colBase, 0,  tid);
    gemm_issue(smem_u + STG_BYT, Ah, Al, Bh, Bl, rowBase, colBase, BK, tid);

    for (int s = 0; s < NSTAGES; ++s) {
        CP_WAIT(1);
        __syncthreads();

        const uint32_t cb = smem_u + (uint32_t)(s & 1) * STG_BYT;
#pragma unroll
        for (int ks = 0; ks < 2; ++ks) {
            uint32_t ah[4][4], al[4][4], bh[2][4], bl[2][4];
#pragma unroll
            for (int t = 0; t < 4; ++t) {
                ldsm4(ah[t], cb + OFF_AHI + a_off + (uint32_t)t * (16 * LDS_B * 2) + ks * 32);
                ldsm4(al[t], cb + OFF_ALO + a_off + (uint32_t)t * (16 * LDS_B * 2) + ks * 32);
            }
#pragma unroll
            for (int p = 0; p < 2; ++p) {
                ldsm4(bh[p], cb + OFF_BHI + b_off + (uint32_t)p * (16 * LDS_B * 2) + ks * 32);
                ldsm4(bl[p], cb + OFF_BLO + b_off + (uint32_t)p * (16 * LDS_B * 2) + ks * 32);
            }
#pragma unroll
            for (int t = 0; t < 4; ++t) {
#pragma unroll
                for (int n = 0; n < 4; ++n) {
                    const int p = n >> 1, sub = n & 1;
                    mma_bf16(acc[t][n], ah[t], bh[p][sub * 2], bh[p][sub * 2 + 1]);
                    mma_bf16(acc[t][n], ah[t], bl[p][sub * 2], bl[p][sub * 2 + 1]);
                    mma_bf16(acc[t][n], al[t], bh[p][sub * 2], bh[p][sub * 2 + 1]);
                }
            }
        }

        __syncthreads();
        if (s + 2 < NSTAGES)
            gemm_issue(smem_u + (uint32_t)(s & 1) * STG_BYT, Ah, Al, Bh, Bl,
                       rowBase, colBase, (s + 2) * BK, tid);
        else
            CP_COMMIT();
    }

#pragma unroll
    for (int t = 0; t < 4; ++t) {
        const int r1 = rowBase + wm * 64 + t * 16 + (lane >> 2);
#pragma unroll
        for (int n = 0; n < 4; ++n) {
            const int col = colBase + wn * 32 + n * 8 + (lane & 3) * 2;
            const float2 b2 = *(const float2*)&bias[col];
            const float o1x = acc[t][n][0] + b2.x, o1y = acc[t][n][1] + b2.y;
            const float o2x = acc[t][n][2] + b2.x, o2y = acc[t][n][3] + b2.y;
            if (!BF16OUT) {
                float2 o1, o2;
                o1.x = o1x; o1.y = o1y; o2.x = o2x; o2.y = o2y;
                *(float2*)&C[(size_t)r1 * DIM + col]       = o1;
                *(float2*)&C[(size_t)(r1 + 8) * DIM + col] = o2;
            } else {
                const uint32_t h1 = cvt2bf(o1y, o1x);
                const uint32_t l1 = cvt2bf(o1y - bfhi(h1), o1x - bflo(h1));
                const uint32_t h2 = cvt2bf(o2y, o2x);
                const uint32_t l2 = cvt2bf(o2y - bfhi(h2), o2x - bflo(h2));
                *(uint32_t*)&Ch[(size_t)r1 * DIM + col]       = h1;
                *(uint32_t*)&Cl[(size_t)r1 * DIM + col]       = l1;
                *(uint32_t*)&Ch[(size_t)(r1 + 8) * DIM + col] = h2;
                *(uint32_t*)&Cl[(size_t)(r1 + 8) * DIM + col] = l2;
            }
        }
    }
}

__global__ void __launch_bounds__(256, 2) gemm_qkv_kernel(
    const float* __restrict__ bq, const float* __restrict__ bk, const float* __restrict__ bv)
{
    if (blockIdx.z == 0)
        gemm_tc_core<false>(x_h, x_l, wq_h, wq_l, bq, g_q, nullptr, nullptr);
    else if (blockIdx.z == 1)
        gemm_tc_core<false>(x_h, x_l, wk_h, wk_l, bk, g_k, nullptr, nullptr);
    else
        gemm_tc_core<true>(x_h, x_l, wv_h, wv_l, bv, nullptr, v_h, v_l);
}

__global__ void __launch_bounds__(256, 2) gemm_out_kernel(
    const float* __restrict__ bo, float* __restrict__ out)
{
    gemm_tc_core<false>(a_h, a_l, wo_h, wo_l, bo, out, nullptr, nullptr);
}

// ============================================================================
// Fused RMSNorm(+gain) + RoPE. Reads g_q/g_k fp32, writes bf16 hi/lo pairs.
// ============================================================================
__global__ void __launch_bounds__(256) rmsnorm_rope_kernel(
    const float* __restrict__ freqs, const float* __restrict__ gq, const float* __restrict__ gk)
{
    const int row = blockIdx.x;
    const int s = row & (SEQ - 1);
    const float* xb = (blockIdx.y == 0 ? g_q : g_k) + (size_t)row * DIM;
    __nv_bfloat16* oh = (blockIdx.y == 0 ? q_h : k_h) + (size_t)row * DIM;
    __nv_bfloat16* ol = (blockIdx.y == 0 ? q_l : k_l) + (size_t)row * DIM;
    const float* g = (blockIdx.y == 0) ? gq : gk;
    const int tid = threadIdx.x;
    const int base = tid * 8;

    const float4 u = *(const float4*)(xb + base);
    const float4 w = *(const float4*)(xb + base + 4);
    float ss = u.x*u.x + u.y*u.y + u.z*u.z + u.w*u.w
             + w.x*w.x + w.y*w.y + w.z*w.z + w.w*w.w;
#pragma unroll
    for (int m = 16; m > 0; m >>= 1) ss += __shfl_xor_sync(0xffffffffu, ss, m);
    __shared__ float red[8];
    if ((tid & 31) == 0) red[tid >> 5] = ss;
    __syncthreads();
    const float tot = red[0]+red[1]+red[2]+red[3]+red[4]+red[5]+red[6]+red[7];
    const float rinv = rsqrtf(tot * (1.0f/DIM) + 1e-6f);

    const float4 g0 = *(const float4*)(g + base);
    const float4 g1 = *(const float4*)(g + base + 4);
    float y[8] = {u.x*rinv*g0.x, u.y*rinv*g0.y, u.z*rinv*g0.z, u.w*rinv*g0.w,
                  w.x*rinv*g1.x, w.y*rinv*g1.y, w.z*rinv*g1.z, w.w*rinv*g1.w};

    const float* fr = freqs + (size_t)s * HD;
    float o[8];
#pragma unroll
    for (int p = 0; p < 4; ++p) {
        const int col = base + 2*p;
        const int jj = (col & (HD - 1)) >> 1;
        const float cr = fr[2*jj], ci = fr[2*jj + 1];
        const float xr = y[2*p], xi = y[2*p + 1];
        o[2*p]     = xr*cr - xi*ci;
        o[2*p + 1] = xr*ci + xi*cr;
    }
    float4 r0; r0.x = o[0]; r0.y = o[1]; r0.z = o[2]; r0.w = o[3];
    float4 r1; r1.x = o[4]; r1.y = o[5]; r1.z = o[6]; r1.w = o[7];
    uint2 h, l;
    split4(r0, h, l);
    *(uint2*)(oh + base)     = h;
    *(uint2*)(ol + base)     = l;
    split4(r1, h, l);
    *(uint2*)(oh + base + 4) = h;
    *(uint2*)(ol + base + 4) = l;
}

// ============================================================================
// HMMA flash attention. 128 q-rows/CTA, 128-kv tiles.
// Q fragments live in registers (loaded straight from gmem, A-frag layout).
// Smem: K double-buffered (hi/lo) + V single (hi/lo) = 6 tiles.
// K_{i+1} load overlaps softmax+PV_i; V_i load overlaps QK_i.
// ============================================================================
#define AST   136                        /* halves per smem row */
#define ATILE_BYT (128 * AST * 2)        /* 34816 */
/* K buf0: [0,2T), K buf1: [2T,4T), V: [4T,6T)  (each pair = hi then lo) */
#define AVH  (4 * ATILE_BYT)
#define AVL  (5 * ATILE_BYT)
#define ATTN_SMEM (6 * ATILE_BYT)        /* 208896 */

__device__ __forceinline__ void attn_issue(uint32_t dstH, uint32_t dstL,
    const __nv_bfloat16* __restrict__ srcH, const __nv_bfloat16* __restrict__ srcL,
    size_t gbase, int tid)
{
#pragma unroll
    for (int i = 0; i < 8; ++i) {
        const int f = i * 256 + tid;
        const int r = f >> 4, c = f & 15;
        const uint32_t d = (uint32_t)r * (AST * 2) + (uint32_t)c * 16;
        const size_t gsrc = gbase + (size_t)r * DIM + c * 8;
        cp_async16(dstH + d, srcH + gsrc);
        cp_async16(dstL + d, srcL + gsrc);
    }
    CP_COMMIT();
}

__global__ void __launch_bounds__(256) attn_kernel()
{
    extern __shared__ char smh[];
    const uint32_t smem_u = smem_to_u32(smh);
    const int tid  = threadIdx.x;
    const int lane = tid & 31;
    const int w    = tid >> 5;
    const int b    = blockIdx.z;
    const int h    = blockIdx.y;
    const int q0   = blockIdx.x * 128;

    const size_t krow0 = (size_t)(b*SEQ) * DIM + h*HD;

    // ---- prologue: issue K tile 0 into K buf0 ----
    attn_issue(smem_u, smem_u + ATILE_BYT, k_h, k_l, krow0, tid);

    // ---- Q fragments -> registers (m16n8k16 A layout) ----
    // lane: row r = lane>>2 (and +8), k-pair col c0 = (lane&3)*2 (and +8)
    uint32_t qh[8][4], ql[8][4];
    {
        const size_t qbase = (size_t)(b*SEQ + q0 + w*16) * DIM + h*HD;
        const int r0 = lane >> 2;
        const int c0 = (lane & 3) * 2;
#pragma unroll
        for (int kc = 0; kc < 8; ++kc) {
            const size_t k0 = qbase + kc * 16 + c0;
            qh[kc][0] = *(const uint32_t*)&q_h[k0 + (size_t)r0 * DIM];
            qh[kc][1] = *(const uint32_t*)&q_h[k0 + (size_t)(r0 + 8) * DIM];
            qh[kc][2] = *(const uint32_t*)&q_h[k0 + 8 + (size_t)r0 * DIM];
            qh[kc][3] = *(const uint32_t*)&q_h[k0 + 8 + (size_t)(r0 + 8) * DIM];
            ql[kc][0] = *(const uint32_t*)&q_l[k0 + (size_t)r0 * DIM];
            ql[kc][1] = *(const uint32_t*)&q_l[k0 + (size_t)(r0 + 8) * DIM];
            ql[kc][2] = *(const uint32_t*)&q_l[k0 + 8 + (size_t)r0 * DIM];
            ql[kc][3] = *(const uint32_t*)&q_l[k0 + 8 + (size_t)(r0 + 8) * DIM];
        }
    }

    const uint32_t kb_off = ((uint32_t)(((lane >> 4) & 1) * 8 + (lane & 7)) * AST
                           + (uint32_t)(((lane >> 3) & 1) * 8)) * 2;
    const uint32_t vb_off = ((uint32_t)(((lane >> 3) & 1) * 8 + (lane & 7)) * AST
                           + (uint32_t)(((lane >> 4) & 1) * 8)) * 2;

    float O[16][4];
#pragma unroll
    for (int n = 0; n < 16; ++n)
#pragma unroll
        for (int e = 0; e < 4; ++e) O[n][e] = 0.0f;
    float mq0 = -1e30f, mq1 = -1e30f, l0 = 0.0f, l1 = 0.0f;

    const float Cs = 0.12754276931699657f;   // (1/sqrt(128)) * log2(e)

    for (int kt = 0; kt < SEQ / 128; ++kt) {
        const size_t krow = krow0 + (size_t)(kt * 128) * DIM;

        CP_WAIT(0);        // K_kt resident (V_{kt-1} completed earlier)
        __syncthreads();   // K visible to all; all warps past PV_{kt-1}

        // V_kt load overlaps QK
        attn_issue(smem_u + AVH, smem_u + AVL, v_h, v_l, krow, tid);

        // ---- scores over 128 kv cols (K from buffer kt&1) ----
        const uint32_t kbase = smem_u + (uint32_t)(kt & 1) * (2 * ATILE_BYT);
        float acc[16][4];
#pragma unroll
        for (int n = 0; n < 16; ++n)
#pragma unroll
            for (int e = 0; e < 4; ++e) acc[n][e] = 0.0f;

#pragma unroll
        for (int kc = 0; kc < 8; ++kc) {
#pragma unroll
            for (int np = 0; np < 8; ++np) {
                uint32_t kbh[4], kbl[4];
                ldsm4(kbh, kbase + kb_off + (uint32_t)np * (16 * AST * 2) + kc * 32);
                ldsm4(kbl, kbase + ATILE_BYT + kb_off + (uint32_t)np * (16 * AST * 2) + kc * 32);
                mma_bf16(acc[2*np],   qh[kc], kbh[0], kbh[1]);
                mma_bf16(acc[2*np],   qh[kc], kbl[0], kbl[1]);
                mma_bf16(acc[2*np],   ql[kc], kbh[0], kbh[1]);
                mma_bf16(acc[2*np+1], qh[kc], kbh[2], kbh[3]);
                mma_bf16(acc[2*np+1], qh[kc], kbl[2], kbl[3]);
                mma_bf16(acc[2*np+1], ql[kc], kbh[2], kbh[3]);
            }
        }

        // K_{kt+1} load overlaps softmax + PV (other K buffer; safe: all warps
        // past QK_{kt-1} via this iteration's top sync)
        if (kt + 1 < SEQ / 128) {
            attn_issue(smem_u + (uint32_t)((kt + 1) & 1) * (2 * ATILE_BYT),
                       smem_u + (uint32_t)((kt + 1) & 1) * (2 * ATILE_BYT) + ATILE_BYT,
                       k_h, k_l, krow + 128 * DIM, tid);
        } else {
            CP_COMMIT();
        }

        // ---- online softmax ----
        float pm0 = -1e30f, pm1 = -1e30f;
#pragma unroll
        for (int n = 0; n < 16; ++n) {
            pm0 = fmaxf(pm0, fmaxf(acc[n][0], acc[n][1]));
            pm1 = fmaxf(pm1, fmaxf(acc[n][2], acc[n][3]));
        }
        pm0 = fmaxf(pm0, __shfl_xor_sync(0xffffffffu, pm0, 1));
        pm0 = fmaxf(pm0, __shfl_xor_sync(0xffffffffu, pm0, 2));
        pm1 = fmaxf(pm1, __shfl_xor_sync(0xffffffffu, pm1, 1));
        pm1 = fmaxf(pm1, __shfl_xor_sync(0xffffffffu, pm1, 2));

        const float M0 = fmaxf(mq0, pm0 * Cs);
        const float M1 = fmaxf(mq1, pm1 * Cs);
        const float corr0 = exp2f(mq0 - M0);
        const float corr1 = exp2f(mq1 - M1);
        mq0 = M0; mq1 = M1;

        float rs0 = 0.0f, rs1 = 0.0f;
#pragma unroll
        for (int n = 0; n < 16; ++n) {
            acc[n][0] = exp2f(fmaf(acc[n][0], Cs, -M0));
            acc[n][1] = exp2f(fmaf(acc[n][1], Cs, -M0));
            acc[n][2] = exp2f(fmaf(acc[n][2], Cs, -M1));
            acc[n][3] = exp2f(fmaf(acc[n][3], Cs, -M1));
            rs0 += acc[n][0] + acc[n][1];
            rs1 += acc[n][2] + acc[n][3];
        }
        rs0 += __shfl_xor_sync(0xffffffffu, rs0, 1);
        rs0 += __shfl_xor_sync(0xffffffffu, rs0, 2);
        rs1 += __shfl_xor_sync(0xffffffffu, rs1, 1);
        rs1 += __shfl_xor_sync(0xffffffffu, rs1, 2);
        l0 = l0 * corr0 + rs0;
        l1 = l1 * corr1 + rs1;

#pragma unroll
        for (int n = 0; n < 16; ++n) {
            O[n][0] *= corr0; O[n][1] *= corr0;
            O[n][2] *= corr1; O[n][3] *= corr1;
        }

        CP_WAIT(1);        // V_kt resident (K_{kt+1} may still be in flight)
        __syncthreads();

        // ---- O += P @ V ----
#pragma unroll
        for (int kc = 0; kc < 8; ++kc) {
            uint32_t ph[4], pl[4];
            ph[0] = cvt2bf(acc[2*kc][1],   acc[2*kc][0]);
            ph[1] = cvt2bf(acc[2*kc][3],   acc[2*kc][2]);
            ph[2] = cvt2bf(acc[2*kc+1][1], acc[2*kc+1][0]);
            ph[3] = cvt2bf(acc[2*kc+1][3], acc[2*kc+1][2]);
            {
                float e0 = acc[2*kc][0]   - bflo(ph[0]);
                float e1 = acc[2*kc][1]   - bfhi(ph[0]);
                pl[0] = cvt2bf(e1, e0);
                e0 = acc[2*kc][2]   - bflo(ph[1]);
                e1 = acc[2*kc][3]   - bfhi(ph[1]);
                pl[1] = cvt2bf(e1, e0);
                e0 = acc[2*kc+1][0] - bflo(ph[2]);
                e1 = acc[2*kc+1][1] - bfhi(ph[2]);
                pl[2] = cvt2bf(e1, e0);
                e0 = acc[2*kc+1][2] - bflo(ph[3]);
                e1 = acc[2*kc+1][3] - bfhi(ph[3]);
                pl[3] = cvt2bf(e1, e0);
            }
#pragma unroll
            for (int np = 0; np < 8; ++np) {
                uint32_t vbh[4], vbl[4];
                ldsm4t(vbh, smem_u + AVH + vb_off + (uint32_t)kc * (16 * AST * 2) + np * 32);
                ldsm4t(vbl, smem_u + AVL + vb_off + (uint32_t)kc * (16 * AST * 2) + np * 32);
                mma_bf16(O[2*np],   ph, vbh[0], vbh[1]);
                mma_bf16(O[2*np],   ph, vbl[0], vbl[1]);
                mma_bf16(O[2*np],   pl, vbh[0], vbh[1]);
                mma_bf16(O[2*np+1], ph, vbh[2], vbh[3]);
                mma_bf16(O[2*np+1], ph, vbl[2], vbl[3]);
                mma_bf16(O[2*np+1], pl, vbh[2], vbh[3]);
            }
        }
    }

    // ---- finalize: write bf16 hi/lo output ----
    const float inv0 = 1.0f / l0;
    const float inv1 = 1.0f / l1;
    const size_t r0g = (size_t)(b*SEQ + q0 + w*16 + (lane >> 2));
#pragma unroll
    for (int n = 0; n < 16; ++n) {
        const int col = h*HD + 8*n + 2*(lane & 3);
        const float o1x = O[n][0] * inv0, o1y = O[n][1] * inv0;
        const float o2x = O[n][2] * inv1, o2y = O[n][3] * inv1;
        const uint32_t h1 = cvt2bf(o1y, o1x);
        const uint32_t l1p = cvt2bf(o1y - bfhi(h1), o1x - bflo(h1));
        const uint32_t h2 = cvt2bf(o2y, o2x);
        const uint32_t l2p = cvt2bf(o2y - bfhi(h2), o2x - bflo(h2));
        *(uint32_t*)&a_h[r0g * DIM + col]       = h1;
        *(uint32_t*)&a_l[r0g * DIM + col]       = l1p;
        *(uint32_t*)&a_h[(r0g + 8) * DIM + col] = h2;
        *(uint32_t*)&a_l[(r0g + 8) * DIM + col] = l2p;
    }
}

// ============================================================================
// Launcher
// ============================================================================
extern "C" void kernel_launch(void* const* d_in, const int* in_sizes, int n_in,
                              void* d_out, int out_size)
{
    const float* x  = (const float*)d_in[0];
    const float* fr = (const float*)d_in[1];
    const float* wq = (const float*)d_in[2];
    const float* bq = (const float*)d_in[3];
    const float* wk = (const float*)d_in[4];
    const float* bk = (const float*)d_in[5];
    const float* wv = (const float*)d_in[6];
    const float* bv = (const float*)d_in[7];
    const float* wo = (const float*)d_in[8];
    const float* bo = (const float*)d_in[9];
    const float* gq = (const float*)d_in[10];
    const float* gk = (const float*)d_in[11];
    float* out = (float*)d_out;

    (void)in_sizes; (void)n_in; (void)out_size;

    cudaFuncSetAttribute(gemm_qkv_kernel, cudaFuncAttributeMaxDynamicSharedMemorySize, GEMM_SMEM);
    cudaFuncSetAttribute(gemm_out_kernel, cudaFuncAttributeMaxDynamicSharedMemorySize, GEMM_SMEM);
    cudaFuncSetAttribute(attn_kernel, cudaFuncAttributeMaxDynamicSharedMemorySize, ATTN_SMEM);

    const int n4_x = MROWS * DIM / 4;
    const int n4_w = DIM * DIM / 4;

    split_x_kernel<<<n4_x / 256, 256>>>(x, n4_x);
    split_w_kernel<<<dim3(n4_w / 256, 4), 256>>>(wq, wk, wv, wo, n4_w);

    gemm_qkv_kernel<<<dim3(DIM/128, MROWS/128, 3), 256, GEMM_SMEM>>>(bq, bk, bv);

    rmsnorm_rope_kernel<<<dim3(MROWS, 2), 256>>>(fr, gq, gk);

    attn_kernel<<<dim3(SEQ/128, NH, BSZ), 256, ATTN_SMEM>>>();

    gemm_out_kernel<<<dim3(DIM/128, MROWS/128, 1), 256, GEMM_SMEM>>>(bo, out);
}

// round 11
// speedup vs baseline: 5.3512x; 1.0000x over previous
#include <cuda_runtime.h>
#include <cuda_bf16.h>
#include <cstdint>

#define DIM   2048
#define BSZ   2
#define SEQ   2048
#define NH    16
#define HD    128
#define MROWS (BSZ*SEQ)   /* 4096 */

typedef unsigned long long ull;

// ---- PTX helpers (baseline PTX only; no sm_103a-gated features) ----
__device__ __forceinline__ uint32_t smem_to_u32(const void* p) {
    uint32_t a;
    asm("{ .reg .u64 t; cvta.to.shared.u64 t, %1; cvt.u32.u64 %0, t; }" : "=r"(a) : "l"(p));
    return a;
}
__device__ __forceinline__ void ldsm4(uint32_t (&r)[4], uint32_t addr) {
    asm volatile("ldmatrix.sync.aligned.m8n8.x4.shared.b16 {%0,%1,%2,%3}, [%4];"
                 : "=r"(r[0]), "=r"(r[1]), "=r"(r[2]), "=r"(r[3]) : "r"(addr));
}
__device__ __forceinline__ void ldsm4t(uint32_t (&r)[4], uint32_t addr) {
    asm volatile("ldmatrix.sync.aligned.m8n8.x4.trans.shared.b16 {%0,%1,%2,%3}, [%4];"
                 : "=r"(r[0]), "=r"(r[1]), "=r"(r[2]), "=r"(r[3]) : "r"(addr));
}
__device__ __forceinline__ void mma_bf16(float (&d)[4], const uint32_t (&a)[4],
                                         uint32_t b0, uint32_t b1) {
    asm volatile("mma.sync.aligned.m16n8k16.row.col.f32.bf16.bf16.f32 "
                 "{%0,%1,%2,%3}, {%4,%5,%6,%7}, {%8,%9}, {%0,%1,%2,%3};"
                 : "+f"(d[0]), "+f"(d[1]), "+f"(d[2]), "+f"(d[3])
                 : "r"(a[0]), "r"(a[1]), "r"(a[2]), "r"(a[3]), "r"(b0), "r"(b1));
}
__device__ __forceinline__ uint32_t cvt2bf(float hi, float lo) {
    uint32_t r; asm("cvt.rn.bf16x2.f32 %0, %1, %2;" : "=r"(r) : "f"(hi), "f"(lo)); return r;
}
__device__ __forceinline__ float bflo(uint32_t p) { return __uint_as_float(p << 16); }
__device__ __forceinline__ float bfhi(uint32_t p) { return __uint_as_float(p & 0xffff0000u); }

__device__ __forceinline__ void cp_async16(uint32_t saddr, const void* gptr) {
    asm volatile("cp.async.cg.shared.global [%0], [%1], 16;" :: "r"(saddr), "l"(gptr));
}
#define CP_COMMIT()  asm volatile("cp.async.commit_group;" ::: "memory")
#define CP_WAIT(n)   asm volatile("cp.async.wait_group %0;" :: "n"(n) : "memory")

// ---- scratch (device globals: allocation-free rule) ----
__device__ float g_q[MROWS*DIM];
__device__ float g_k[MROWS*DIM];
__device__ __nv_bfloat16 x_h[MROWS*DIM],  x_l[MROWS*DIM];
__device__ __nv_bfloat16 wq_h[DIM*DIM], wq_l[DIM*DIM];
__device__ __nv_bfloat16 wk_h[DIM*DIM], wk_l[DIM*DIM];
__device__ __nv_bfloat16 wv_h[DIM*DIM], wv_l[DIM*DIM];
__device__ __nv_bfloat16 wo_h[DIM*DIM], wo_l[DIM*DIM];
__device__ __nv_bfloat16 q_h[MROWS*DIM], q_l[MROWS*DIM];
__device__ __nv_bfloat16 k_h[MROWS*DIM], k_l[MROWS*DIM];
__device__ __nv_bfloat16 v_h[MROWS*DIM], v_l[MROWS*DIM];
__device__ __nv_bfloat16 a_h[MROWS*DIM], a_l[MROWS*DIM];

__device__ __forceinline__ void split4(float4 v, uint2& hi, uint2& lo) {
    __nv_bfloat16 h0 = __float2bfloat16(v.x);
    __nv_bfloat16 h1 = __float2bfloat16(v.y);
    __nv_bfloat16 h2 = __float2bfloat16(v.z);
    __nv_bfloat16 h3 = __float2bfloat16(v.w);
    __nv_bfloat16 l0 = __float2bfloat16(v.x - __bfloat162float(h0));
    __nv_bfloat16 l1 = __float2bfloat16(v.y - __bfloat162float(h1));
    __nv_bfloat16 l2 = __float2bfloat16(v.z - __bfloat162float(h2));
    __nv_bfloat16 l3 = __float2bfloat16(v.w - __bfloat162float(h3));
    hi.x = ((uint32_t)__bfloat16_as_ushort(h1) << 16) | __bfloat16_as_ushort(h0);
    hi.y = ((uint32_t)__bfloat16_as_ushort(h3) << 16) | __bfloat16_as_ushort(h2);
    lo.x = ((uint32_t)__bfloat16_as_ushort(l1) << 16) | __bfloat16_as_ushort(l0);
    lo.y = ((uint32_t)__bfloat16_as_ushort(l3) << 16) | __bfloat16_as_ushort(l2);
}

// ============================================================================
// fp32 -> bf16 hi/lo split kernels
// ============================================================================
__global__ void __launch_bounds__(256) split_x_kernel(const float* __restrict__ src, int n4)
{
    const int i = blockIdx.x * blockDim.x + threadIdx.x;
    if (i >= n4) return;
    const float4 v = ((const float4*)src)[i];
    uint2 h, l; split4(v, h, l);
    ((uint2*)x_h)[i] = h;
    ((uint2*)x_l)[i] = l;
}

__global__ void __launch_bounds__(256) split_w_kernel(
    const float* __restrict__ wq, const float* __restrict__ wk,
    const float* __restrict__ wv, const float* __restrict__ wo, int n4)
{
    const int i = blockIdx.x * blockDim.x + threadIdx.x;
    if (i >= n4) return;
    const float* s;
    __nv_bfloat16 *hi, *lo;
    switch (blockIdx.y) {
        case 0: s = wq; hi = wq_h; lo = wq_l; break;
        case 1: s = wk; hi = wk_h; lo = wk_l; break;
        case 2: s = wv; hi = wv_h; lo = wv_l; break;
        default: s = wo; hi = wo_h; lo = wo_l; break;
    }
    const float4 v = ((const float4*)s)[i];
    uint2 h, l; split4(v, h, l);
    ((uint2*)hi)[i] = h;
    ((uint2*)lo)[i] = l;
}

// ============================================================================
// HMMA GEMM: C[M,N] = (Ah+Al)[M,K] @ (Bh+Bl)[N,K]^T + bias
// 128x128 CTA tile, 8 warps (2x4), 3 MMAs per product, fp32 accum.
// 2-stage cp.async pipeline; 2 CTAs/SM. BF16OUT writes hi/lo split directly.
// ============================================================================
#define BK        32
#define NSTAGES   (DIM / BK)            /* 64 */
#define LDS_B     40
#define TILE_BYT  (128 * LDS_B * 2)     /* 10240 */
#define OFF_AHI   0
#define OFF_ALO   (1 * TILE_BYT)
#define OFF_BHI   (2 * TILE_BYT)
#define OFF_BLO   (3 * TILE_BYT)
#define STG_BYT   (4 * TILE_BYT)        /* 40960 */
#define GEMM_SMEM (2 * STG_BYT)         /* 81920 -> 2 CTAs/SM */

__device__ __forceinline__ void gemm_issue(uint32_t dstbase,
    const __nv_bfloat16* __restrict__ Ah, const __nv_bfloat16* __restrict__ Al,
    const __nv_bfloat16* __restrict__ Bh, const __nv_bfloat16* __restrict__ Bl,
    int rowBase, int colBase, int kofs, int tid)
{
#pragma unroll
    for (int i = 0; i < 2; ++i) {
        const int f = i * 256 + tid;
        const int r = f >> 2, c = f & 3;
        const uint32_t d = dstbase + (uint32_t)r * (LDS_B * 2) + (uint32_t)c * 16;
        const size_t gA = (size_t)(rowBase + r) * DIM + kofs + c * 8;
        const size_t gB = (size_t)(colBase + r) * DIM + kofs + c * 8;
        cp_async16(d + OFF_AHI, Ah + gA);
        cp_async16(d + OFF_ALO, Al + gA);
        cp_async16(d + OFF_BHI, Bh + gB);
        cp_async16(d + OFF_BLO, Bl + gB);
    }
    CP_COMMIT();
}

template<bool BF16OUT>
__device__ __forceinline__ void gemm_tc_core(
    const __nv_bfloat16* __restrict__ Ah, const __nv_bfloat16* __restrict__ Al,
    const __nv_bfloat16* __restrict__ Bh, const __nv_bfloat16* __restrict__ Bl,
    const float* __restrict__ bias, float* __restrict__ C,
    __nv_bfloat16* __restrict__ Ch, __nv_bfloat16* __restrict__ Cl)
{
    extern __shared__ char smem[];
    const uint32_t smem_u = smem_to_u32(smem);
    const int tid  = threadIdx.x;
    const int lane = tid & 31;
    const int wid  = tid >> 5;
    const int wm   = wid & 1;
    const int wn   = wid >> 1;

    const int rowBase = blockIdx.y * 128;
    const int colBase = blockIdx.x * 128;

    const uint32_t a_off = (uint32_t)(wm * 64 + (lane & 15)) * (LDS_B * 2)
                         + (uint32_t)((lane >> 4) * 8) * 2;
    const uint32_t b_off = (uint32_t)(wn * 32 + ((lane >> 4) & 1) * 8 + (lane & 7)) * (LDS_B * 2)
                         + (uint32_t)(((lane >> 3) & 1) * 8) * 2;

    float acc[4][4][4];
#pragma unroll
    for (int t = 0; t < 4; ++t)
#pragma unroll
        for (int n = 0; n < 4; ++n)
#pragma unroll
            for (int e = 0; e < 4; ++e) acc[t][n][e] = 0.0f;

    gemm_issue(smem_u,           Ah, Al, Bh, Bl, rowBase, colBase, 0,  tid);
    gemm_issue(smem_u + STG_BYT, Ah, Al, Bh, Bl, rowBase, colBase, BK, tid);

    for (int s = 0; s < NSTAGES; ++s) {
        CP_WAIT(1);
        __syncthreads();

        const uint32_t cb = smem_u + (uint32_t)(s & 1) * STG_BYT;
#pragma unroll
        for (int ks = 0; ks < 2; ++ks) {
            uint32_t ah[4][4], al[4][4], bh[2][4], bl[2][4];
#pragma unroll
            for (int t = 0; t < 4; ++t) {
                ldsm4(ah[t], cb + OFF_AHI + a_off + (uint32_t)t * (16 * LDS_B * 2) + ks * 32);
                ldsm4(al[t], cb + OFF_ALO + a_off + (uint32_t)t * (16 * LDS_B * 2) + ks * 32);
            }
#pragma unroll
            for (int p = 0; p < 2; ++p) {
                ldsm4(bh[p], cb + OFF_BHI + b_off + (uint32_t)p * (16 * LDS_B * 2) + ks * 32);
                ldsm4(bl[p], cb + OFF_BLO + b_off + (uint32_t)p * (16 * LDS_B * 2) + ks * 32);
            }
#pragma unroll
            for (int t = 0; t < 4; ++t) {
#pragma unroll
                for (int n = 0; n < 4; ++n) {
                    const int p = n >> 1, sub = n & 1;
                    mma_bf16(acc[t][n], ah[t], bh[p][sub * 2], bh[p][sub * 2 + 1]);
                    mma_bf16(acc[t][n], ah[t], bl[p][sub * 2], bl[p][sub * 2 + 1]);
                    mma_bf16(acc[t][n], al[t], bh[p][sub * 2], bh[p][sub * 2 + 1]);
                }
            }
        }

        __syncthreads();
        if (s + 2 < NSTAGES)
            gemm_issue(smem_u + (uint32_t)(s & 1) * STG_BYT, Ah, Al, Bh, Bl,
                       rowBase, colBase, (s + 2) * BK, tid);
        else
            CP_COMMIT();
    }

#pragma unroll
    for (int t = 0; t < 4; ++t) {
        const int r1 = rowBase + wm * 64 + t * 16 + (lane >> 2);
#pragma unroll
        for (int n = 0; n < 4; ++n) {
            const int col = colBase + wn * 32 + n * 8 + (lane & 3) * 2;
            const float2 b2 = *(const float2*)&bias[col];
            const float o1x = acc[t][n][0] + b2.x, o1y = acc[t][n][1] + b2.y;
            const float o2x = acc[t][n][2] + b2.x, o2y = acc[t][n][3] + b2.y;
            if (!BF16OUT) {
                float2 o1, o2;
                o1.x = o1x; o1.y = o1y; o2.x = o2x; o2.y = o2y;
                *(float2*)&C[(size_t)r1 * DIM + col]       = o1;
                *(float2*)&C[(size_t)(r1 + 8) * DIM + col] = o2;
            } else {
                const uint32_t h1 = cvt2bf(o1y, o1x);
                const uint32_t l1 = cvt2bf(o1y - bfhi(h1), o1x - bflo(h1));
                const uint32_t h2 = cvt2bf(o2y, o2x);
                const uint32_t l2 = cvt2bf(o2y - bfhi(h2), o2x - bflo(h2));
                *(uint32_t*)&Ch[(size_t)r1 * DIM + col]       = h1;
                *(uint32_t*)&Cl[(size_t)r1 * DIM + col]       = l1;
                *(uint32_t*)&Ch[(size_t)(r1 + 8) * DIM + col] = h2;
                *(uint32_t*)&Cl[(size_t)(r1 + 8) * DIM + col] = l2;
            }
        }
    }
}

__global__ void __launch_bounds__(256, 2) gemm_qkv_kernel(
    const float* __restrict__ bq, const float* __restrict__ bk, const float* __restrict__ bv)
{
    if (blockIdx.z == 0)
        gemm_tc_core<false>(x_h, x_l, wq_h, wq_l, bq, g_q, nullptr, nullptr);
    else if (blockIdx.z == 1)
        gemm_tc_core<false>(x_h, x_l, wk_h, wk_l, bk, g_k, nullptr, nullptr);
    else
        gemm_tc_core<true>(x_h, x_l, wv_h, wv_l, bv, nullptr, v_h, v_l);
}

__global__ void __launch_bounds__(256, 2) gemm_out_kernel(
    const float* __restrict__ bo, float* __restrict__ out)
{
    gemm_tc_core<false>(a_h, a_l, wo_h, wo_l, bo, out, nullptr, nullptr);
}

// ============================================================================
// Fused RMSNorm(+gain) + RoPE. Reads g_q/g_k fp32, writes bf16 hi/lo pairs.
// ============================================================================
__global__ void __launch_bounds__(256) rmsnorm_rope_kernel(
    const float* __restrict__ freqs, const float* __restrict__ gq, const float* __restrict__ gk)
{
    const int row = blockIdx.x;
    const int s = row & (SEQ - 1);
    const float* xb = (blockIdx.y == 0 ? g_q : g_k) + (size_t)row * DIM;
    __nv_bfloat16* oh = (blockIdx.y == 0 ? q_h : k_h) + (size_t)row * DIM;
    __nv_bfloat16* ol = (blockIdx.y == 0 ? q_l : k_l) + (size_t)row * DIM;
    const float* g = (blockIdx.y == 0) ? gq : gk;
    const int tid = threadIdx.x;
    const int base = tid * 8;

    const float4 u = *(const float4*)(xb + base);
    const float4 w = *(const float4*)(xb + base + 4);
    float ss = u.x*u.x + u.y*u.y + u.z*u.z + u.w*u.w
             + w.x*w.x + w.y*w.y + w.z*w.z + w.w*w.w;
#pragma unroll
    for (int m = 16; m > 0; m >>= 1) ss += __shfl_xor_sync(0xffffffffu, ss, m);
    __shared__ float red[8];
    if ((tid & 31) == 0) red[tid >> 5] = ss;
    __syncthreads();
    const float tot = red[0]+red[1]+red[2]+red[3]+red[4]+red[5]+red[6]+red[7];
    const float rinv = rsqrtf(tot * (1.0f/DIM) + 1e-6f);

    const float4 g0 = *(const float4*)(g + base);
    const float4 g1 = *(const float4*)(g + base + 4);
    float y[8] = {u.x*rinv*g0.x, u.y*rinv*g0.y, u.z*rinv*g0.z, u.w*rinv*g0.w,
                  w.x*rinv*g1.x, w.y*rinv*g1.y, w.z*rinv*g1.z, w.w*rinv*g1.w};

    const float* fr = freqs + (size_t)s * HD;
    float o[8];
#pragma unroll
    for (int p = 0; p < 4; ++p) {
        const int col = base + 2*p;
        const int jj = (col & (HD - 1)) >> 1;
        const float cr = fr[2*jj], ci = fr[2*jj + 1];
        const float xr = y[2*p], xi = y[2*p + 1];
        o[2*p]     = xr*cr - xi*ci;
        o[2*p + 1] = xr*ci + xi*cr;
    }
    float4 r0; r0.x = o[0]; r0.y = o[1]; r0.z = o[2]; r0.w = o[3];
    float4 r1; r1.x = o[4]; r1.y = o[5]; r1.z = o[6]; r1.w = o[7];
    uint2 h, l;
    split4(r0, h, l);
    *(uint2*)(oh + base)     = h;
    *(uint2*)(ol + base)     = l;
    split4(r1, h, l);
    *(uint2*)(oh + base + 4) = h;
    *(uint2*)(ol + base + 4) = l;
}

// ============================================================================
// HMMA flash attention. 128 q-rows/CTA, 128-kv tiles.
// Q fragments live in registers (loaded straight from gmem, A-frag layout).
// Smem: K double-buffered (hi/lo) + V single (hi/lo) = 6 tiles.
// K_{i+1} load overlaps softmax+PV_i; V_i load overlaps QK_i.
// ============================================================================
#define AST   136                        /* halves per smem row */
#define ATILE_BYT (128 * AST * 2)        /* 34816 */
/* K buf0: [0,2T), K buf1: [2T,4T), V: [4T,6T)  (each pair = hi then lo) */
#define AVH  (4 * ATILE_BYT)
#define AVL  (5 * ATILE_BYT)
#define ATTN_SMEM (6 * ATILE_BYT)        /* 208896 */

__device__ __forceinline__ void attn_issue(uint32_t dstH, uint32_t dstL,
    const __nv_bfloat16* __restrict__ srcH, const __nv_bfloat16* __restrict__ srcL,
    size_t gbase, int tid)
{
#pragma unroll
    for (int i = 0; i < 8; ++i) {
        const int f = i * 256 + tid;
        const int r = f >> 4, c = f & 15;
        const uint32_t d = (uint32_t)r * (AST * 2) + (uint32_t)c * 16;
        const size_t gsrc = gbase + (size_t)r * DIM + c * 8;
        cp_async16(dstH + d, srcH + gsrc);
        cp_async16(dstL + d, srcL + gsrc);
    }
    CP_COMMIT();
}

__global__ void __launch_bounds__(256) attn_kernel()
{
    extern __shared__ char smh[];
    const uint32_t smem_u = smem_to_u32(smh);
    const int tid  = threadIdx.x;
    const int lane = tid & 31;
    const int w    = tid >> 5;
    const int b    = blockIdx.z;
    const int h    = blockIdx.y;
    const int q0   = blockIdx.x * 128;

    const size_t krow0 = (size_t)(b*SEQ) * DIM + h*HD;

    // ---- prologue: issue K tile 0 into K buf0 ----
    attn_issue(smem_u, smem_u + ATILE_BYT, k_h, k_l, krow0, tid);

    // ---- Q fragments -> registers (m16n8k16 A layout) ----
    // lane: row r = lane>>2 (and +8), k-pair col c0 = (lane&3)*2 (and +8)
    uint32_t qh[8][4], ql[8][4];
    {
        const size_t qbase = (size_t)(b*SEQ + q0 + w*16) * DIM + h*HD;
        const int r0 = lane >> 2;
        const int c0 = (lane & 3) * 2;
#pragma unroll
        for (int kc = 0; kc < 8; ++kc) {
            const size_t k0 = qbase + kc * 16 + c0;
            qh[kc][0] = *(const uint32_t*)&q_h[k0 + (size_t)r0 * DIM];
            qh[kc][1] = *(const uint32_t*)&q_h[k0 + (size_t)(r0 + 8) * DIM];
            qh[kc][2] = *(const uint32_t*)&q_h[k0 + 8 + (size_t)r0 * DIM];
            qh[kc][3] = *(const uint32_t*)&q_h[k0 + 8 + (size_t)(r0 + 8) * DIM];
            ql[kc][0] = *(const uint32_t*)&q_l[k0 + (size_t)r0 * DIM];
            ql[kc][1] = *(const uint32_t*)&q_l[k0 + (size_t)(r0 + 8) * DIM];
            ql[kc][2] = *(const uint32_t*)&q_l[k0 + 8 + (size_t)r0 * DIM];
            ql[kc][3] = *(const uint32_t*)&q_l[k0 + 8 + (size_t)(r0 + 8) * DIM];
        }
    }

    const uint32_t kb_off = ((uint32_t)(((lane >> 4) & 1) * 8 + (lane & 7)) * AST
                           + (uint32_t)(((lane >> 3) & 1) * 8)) * 2;
    const uint32_t vb_off = ((uint32_t)(((lane >> 3) & 1) * 8 + (lane & 7)) * AST
                           + (uint32_t)(((lane >> 4) & 1) * 8)) * 2;

    float O[16][4];
#pragma unroll
    for (int n = 0; n < 16; ++n)
#pragma unroll
        for (int e = 0; e < 4; ++e) O[n][e] = 0.0f;
    float mq0 = -1e30f, mq1 = -1e30f, l0 = 0.0f, l1 = 0.0f;

    const float Cs = 0.12754276931699657f;   // (1/sqrt(128)) * log2(e)

    for (int kt = 0; kt < SEQ / 128; ++kt) {
        const size_t krow = krow0 + (size_t)(kt * 128) * DIM;

        CP_WAIT(0);        // K_kt resident (V_{kt-1} completed earlier)
        __syncthreads();   // K visible to all; all warps past PV_{kt-1}

        // V_kt load overlaps QK
        attn_issue(smem_u + AVH, smem_u + AVL, v_h, v_l, krow, tid);

        // ---- scores over 128 kv cols (K from buffer kt&1) ----
        const uint32_t kbase = smem_u + (uint32_t)(kt & 1) * (2 * ATILE_BYT);
        float acc[16][4];
#pragma unroll
        for (int n = 0; n < 16; ++n)
#pragma unroll
            for (int e = 0; e < 4; ++e) acc[n][e] = 0.0f;

#pragma unroll
        for (int kc = 0; kc < 8; ++kc) {
#pragma unroll
            for (int np = 0; np < 8; ++np) {
                uint32_t kbh[4], kbl[4];
                ldsm4(kbh, kbase + kb_off + (uint32_t)np * (16 * AST * 2) + kc * 32);
                ldsm4(kbl, kbase + ATILE_BYT + kb_off + (uint32_t)np * (16 * AST * 2) + kc * 32);
                mma_bf16(acc[2*np],   qh[kc], kbh[0], kbh[1]);
                mma_bf16(acc[2*np],   qh[kc], kbl[0], kbl[1]);
                mma_bf16(acc[2*np],   ql[kc], kbh[0], kbh[1]);
                mma_bf16(acc[2*np+1], qh[kc], kbh[2], kbh[3]);
                mma_bf16(acc[2*np+1], qh[kc], kbl[2], kbl[3]);
                mma_bf16(acc[2*np+1], ql[kc], kbh[2], kbh[3]);
            }
        }

        // K_{kt+1} load overlaps softmax + PV (other K buffer; safe: all warps
        // past QK_{kt-1} via this iteration's top sync)
        if (kt + 1 < SEQ / 128) {
            attn_issue(smem_u + (uint32_t)((kt + 1) & 1) * (2 * ATILE_BYT),
                       smem_u + (uint32_t)((kt + 1) & 1) * (2 * ATILE_BYT) + ATILE_BYT,
                       k_h, k_l, krow + 128 * DIM, tid);
        } else {
            CP_COMMIT();
        }

        // ---- online softmax ----
        float pm0 = -1e30f, pm1 = -1e30f;
#pragma unroll
        for (int n = 0; n < 16; ++n) {
            pm0 = fmaxf(pm0, fmaxf(acc[n][0], acc[n][1]));
            pm1 = fmaxf(pm1, fmaxf(acc[n][2], acc[n][3]));
        }
        pm0 = fmaxf(pm0, __shfl_xor_sync(0xffffffffu, pm0, 1));
        pm0 = fmaxf(pm0, __shfl_xor_sync(0xffffffffu, pm0, 2));
        pm1 = fmaxf(pm1, __shfl_xor_sync(0xffffffffu, pm1, 1));
        pm1 = fmaxf(pm1, __shfl_xor_sync(0xffffffffu, pm1, 2));

        const float M0 = fmaxf(mq0, pm0 * Cs);
        const float M1 = fmaxf(mq1, pm1 * Cs);
        const float corr0 = exp2f(mq0 - M0);
        const float corr1 = exp2f(mq1 - M1);
        mq0 = M0; mq1 = M1;

        float rs0 = 0.0f, rs1 = 0.0f;
#pragma unroll
        for (int n = 0; n < 16; ++n) {
            acc[n][0] = exp2f(fmaf(acc[n][0], Cs, -M0));
            acc[n][1] = exp2f(fmaf(acc[n][1], Cs, -M0));
            acc[n][2] = exp2f(fmaf(acc[n][2], Cs, -M1));
            acc[n][3] = exp2f(fmaf(acc[n][3], Cs, -M1));
            rs0 += acc[n][0] + acc[n][1];
            rs1 += acc[n][2] + acc[n][3];
        }
        rs0 += __shfl_xor_sync(0xffffffffu, rs0, 1);
        rs0 += __shfl_xor_sync(0xffffffffu, rs0, 2);
        rs1 += __shfl_xor_sync(0xffffffffu, rs1, 1);
        rs1 += __shfl_xor_sync(0xffffffffu, rs1, 2);
        l0 = l0 * corr0 + rs0;
        l1 = l1 * corr1 + rs1;

#pragma unroll
        for (int n = 0; n < 16; ++n) {
            O[n][0] *= corr0; O[n][1] *= corr0;
            O[n][2] *= corr1; O[n][3] *= corr1;
        }

        CP_WAIT(1);        // V_kt resident (K_{kt+1} may still be in flight)
        __syncthreads();

        // ---- O += P @ V ----
#pragma unroll
        for (int kc = 0; kc < 8; ++kc) {
            uint32_t ph[4], pl[4];
            ph[0] = cvt2bf(acc[2*kc][1],   acc[2*kc][0]);
            ph[1] = cvt2bf(acc[2*kc][3],   acc[2*kc][2]);
            ph[2] = cvt2bf(acc[2*kc+1][1], acc[2*kc+1][0]);
            ph[3] = cvt2bf(acc[2*kc+1][3], acc[2*kc+1][2]);
            {
                float e0 = acc[2*kc][0]   - bflo(ph[0]);
                float e1 = acc[2*kc][1]   - bfhi(ph[0]);
                pl[0] = cvt2bf(e1, e0);
                e0 = acc[2*kc][2]   - bflo(ph[1]);
                e1 = acc[2*kc][3]   - bfhi(ph[1]);
                pl[1] = cvt2bf(e1, e0);
                e0 = acc[2*kc+1][0] - bflo(ph[2]);
                e1 = acc[2*kc+1][1] - bfhi(ph[2]);
                pl[2] = cvt2bf(e1, e0);
                e0 = acc[2*kc+1][2] - bflo(ph[3]);
                e1 = acc[2*kc+1][3] - bfhi(ph[3]);
                pl[3] = cvt2bf(e1, e0);
            }
#pragma unroll
            for (int np = 0; np < 8; ++np) {
                uint32_t vbh[4], vbl[4];
                ldsm4t(vbh, smem_u + AVH + vb_off + (uint32_t)kc * (16 * AST * 2) + np * 32);
                ldsm4t(vbl, smem_u + AVL + vb_off + (uint32_t)kc * (16 * AST * 2) + np * 32);
                mma_bf16(O[2*np],   ph, vbh[0], vbh[1]);
                mma_bf16(O[2*np],   ph, vbl[0], vbl[1]);
                mma_bf16(O[2*np],   pl, vbh[0], vbh[1]);
                mma_bf16(O[2*np+1], ph, vbh[2], vbh[3]);
                mma_bf16(O[2*np+1], ph, vbl[2], vbl[3]);
                mma_bf16(O[2*np+1], pl, vbh[2], vbh[3]);
            }
        }
    }

    // ---- finalize: write bf16 hi/lo output ----
    const float inv0 = 1.0f / l0;
    const float inv1 = 1.0f / l1;
    const size_t r0g = (size_t)(b*SEQ + q0 + w*16 + (lane >> 2));
#pragma unroll
    for (int n = 0; n < 16; ++n) {
        const int col = h*HD + 8*n + 2*(lane & 3);
        const float o1x = O[n][0] * inv0, o1y = O[n][1] * inv0;
        const float o2x = O[n][2] * inv1, o2y = O[n][3] * inv1;
        const uint32_t h1 = cvt2bf(o1y, o1x);
        const uint32_t l1p = cvt2bf(o1y - bfhi(h1), o1x - bflo(h1));
        const uint32_t h2 = cvt2bf(o2y, o2x);
        const uint32_t l2p = cvt2bf(o2y - bfhi(h2), o2x - bflo(h2));
        *(uint32_t*)&a_h[r0g * DIM + col]       = h1;
        *(uint32_t*)&a_l[r0g * DIM + col]       = l1p;
        *(uint32_t*)&a_h[(r0g + 8) * DIM + col] = h2;
        *(uint32_t*)&a_l[(r0g + 8) * DIM + col] = l2p;
    }
}

// ============================================================================
// Launcher
// ============================================================================
extern "C" void kernel_launch(void* const* d_in, const int* in_sizes, int n_in,
                              void* d_out, int out_size)
{
    const float* x  = (const float*)d_in[0];
    const float* fr = (const float*)d_in[1];
    const float* wq = (const float*)d_in[2];
    const float* bq = (const float*)d_in[3];
    const float* wk = (const float*)d_in[4];
    const float* bk = (const float*)d_in[5];
    const float* wv = (const float*)d_in[6];
    const float* bv = (const float*)d_in[7];
    const float* wo = (const float*)d_in[8];
    const float* bo = (const float*)d_in[9];
    const float* gq = (const float*)d_in[10];
    const float* gk = (const float*)d_in[11];
    float* out = (float*)d_out;

    (void)in_sizes; (void)n_in; (void)out_size;

    cudaFuncSetAttribute(gemm_qkv_kernel, cudaFuncAttributeMaxDynamicSharedMemorySize, GEMM_SMEM);
    cudaFuncSetAttribute(gemm_out_kernel, cudaFuncAttributeMaxDynamicSharedMemorySize, GEMM_SMEM);
    cudaFuncSetAttribute(attn_kernel, cudaFuncAttributeMaxDynamicSharedMemorySize, ATTN_SMEM);

    const int n4_x = MROWS * DIM / 4;
    const int n4_w = DIM * DIM / 4;

    split_x_kernel<<<n4_x / 256, 256>>>(x, n4_x);
    split_w_kernel<<<dim3(n4_w / 256, 4), 256>>>(wq, wk, wv, wo, n4_w);

    gemm_qkv_kernel<<<dim3(DIM/128, MROWS/128, 3), 256, GEMM_SMEM>>>(bq, bk, bv);

    rmsnorm_rope_kernel<<<dim3(MROWS, 2), 256>>>(fr, gq, gk);

    attn_kernel<<<dim3(SEQ/128, NH, BSZ), 256, ATTN_SMEM>>>();

    gemm_out_kernel<<<dim3(DIM/128, MROWS/128, 1), 256, GEMM_SMEM>>>(bo, out);
}